// round 2
// baseline (speedup 1.0000x reference)
#include <cuda_runtime.h>
#include <math.h>
#include <float.h>

#define BATCH  8
#define LSEQ   4096
#define DMODEL 512
#define TOPK   8
#define NGRP   64   // channel groups per batch for FFT partial accumulation (512/8)

// ---------------- scratch (static device globals; no allocations) ----------------
__device__ float  g_q  [BATCH * DMODEL * LSEQ];
__device__ float  g_k  [BATCH * DMODEL * LSEQ];
__device__ float  g_v  [BATCH * DMODEL * LSEQ];
__device__ float  g_agg[BATCH * DMODEL * LSEQ];
__device__ float2 g_spart[BATCH * NGRP * LSEQ];
__device__ float  g_mcorr[BATCH * LSEQ];
__device__ float  g_weights[BATCH * TOPK];
__device__ int    g_delays [BATCH * TOPK];

// =====================================================================
// GEMM: C[b,m,n] = sum_k A[m,k] * B[b,k,n] + bias[m]
//   A: W row-major [M=512, K=512]
//   B operand, two layouts:
//     B_KMAJ=false : X[b, n, k]  (k contiguous)  -- hidden_states / projections
//     B_KMAJ=true  : X[b, k, n]  (n contiguous)  -- agg for output projection
//   Output:
//     TRANS_OUT=false: out[b, m, n]   ([B, D, L] channel-major for FFT/gather)
//     TRANS_OUT=true : out[b, n, m]   ([B, L, D] final output layout)
// 128x128 tile, Kt=16, 256 threads, 8x8 per thread.
// =====================================================================
template<bool TRANS_OUT, bool B_KMAJ>
__global__ __launch_bounds__(256, 2)
void gemm_kernel(const float* __restrict__ A,
                 const float* __restrict__ X,
                 const float* __restrict__ bias,
                 float* __restrict__ out)
{
    const int M = DMODEL, N = LSEQ, K = DMODEL;
    __shared__ float As[16][132];
    __shared__ float Bs[16][132];

    const int b  = blockIdx.z;
    const int m0 = blockIdx.y * 128;
    const int n0 = blockIdx.x * 128;
    const float* Xb = X + (size_t)b * N * K;

    const int tid = threadIdx.x;
    const int tx = tid & 15;     // n micro-tile
    const int ty = tid >> 4;     // m micro-tile

    float c[8][8];
#pragma unroll
    for (int i = 0; i < 8; ++i)
#pragma unroll
        for (int j = 0; j < 8; ++j) c[i][j] = 0.f;

    for (int k0 = 0; k0 < K; k0 += 16) {
        // ---- load A tile (128m x 16k), transpose into As[k][m] ----
#pragma unroll
        for (int it = 0; it < 2; ++it) {
            int idx = tid + it * 256;              // 0..511
            int m  = idx >> 2;
            int kq = (idx & 3) << 2;
            float4 va = *(const float4*)&A[(size_t)(m0 + m) * K + k0 + kq];
            As[kq + 0][m] = va.x; As[kq + 1][m] = va.y;
            As[kq + 2][m] = va.z; As[kq + 3][m] = va.w;
        }
        // ---- load B tile (16k x 128n) ----
        if (B_KMAJ) {
            // X[b, k, n]: n contiguous, direct vector copy
#pragma unroll
            for (int it = 0; it < 2; ++it) {
                int idx = tid + it * 256;          // 0..511
                int kk = idx >> 5;                 // 0..15
                int nq = (idx & 31) << 2;          // 0..124
                float4 vb = *(const float4*)&Xb[(size_t)(k0 + kk) * N + n0 + nq];
                *(float4*)&Bs[kk][nq] = vb;
            }
        } else {
            // X[b, n, k]: k contiguous, transpose on store
#pragma unroll
            for (int it = 0; it < 2; ++it) {
                int idx = tid + it * 256;
                int n  = idx >> 2;
                int kq = (idx & 3) << 2;
                float4 vb = *(const float4*)&Xb[(size_t)(n0 + n) * K + k0 + kq];
                Bs[kq + 0][n] = vb.x; Bs[kq + 1][n] = vb.y;
                Bs[kq + 2][n] = vb.z; Bs[kq + 3][n] = vb.w;
            }
        }
        __syncthreads();

#pragma unroll
        for (int kk = 0; kk < 16; ++kk) {
            float4 a0 = *(const float4*)&As[kk][ty * 8];
            float4 a1 = *(const float4*)&As[kk][ty * 8 + 4];
            float4 b0 = *(const float4*)&Bs[kk][tx * 8];
            float4 b1 = *(const float4*)&Bs[kk][tx * 8 + 4];
            float av[8] = {a0.x, a0.y, a0.z, a0.w, a1.x, a1.y, a1.z, a1.w};
            float bv[8] = {b0.x, b0.y, b0.z, b0.w, b1.x, b1.y, b1.z, b1.w};
#pragma unroll
            for (int i = 0; i < 8; ++i)
#pragma unroll
                for (int j = 0; j < 8; ++j) c[i][j] += av[i] * bv[j];
        }
        __syncthreads();
    }

    if (!TRANS_OUT) {
        // out[b, m, n]
#pragma unroll
        for (int i = 0; i < 8; ++i) {
            int m = m0 + ty * 8 + i;
            float bi = bias[m];
            size_t base = ((size_t)b * M + m) * N + n0 + tx * 8;
            float4 v0 = make_float4(c[i][0] + bi, c[i][1] + bi, c[i][2] + bi, c[i][3] + bi);
            float4 v1 = make_float4(c[i][4] + bi, c[i][5] + bi, c[i][6] + bi, c[i][7] + bi);
            *(float4*)&out[base]     = v0;
            *(float4*)&out[base + 4] = v1;
        }
    } else {
        // out[b, n, m] — store float4 along m (contiguous D axis)
        float bias8[8];
#pragma unroll
        for (int i = 0; i < 8; ++i) bias8[i] = bias[m0 + ty * 8 + i];
#pragma unroll
        for (int j = 0; j < 8; ++j) {
            int n = n0 + tx * 8 + j;
            size_t base = ((size_t)b * N + n) * M + m0 + ty * 8;
            float4 v0 = make_float4(c[0][j] + bias8[0], c[1][j] + bias8[1],
                                    c[2][j] + bias8[2], c[3][j] + bias8[3]);
            float4 v1 = make_float4(c[4][j] + bias8[4], c[5][j] + bias8[5],
                                    c[6][j] + bias8[6], c[7][j] + bias8[7]);
            *(float4*)&out[base]     = v0;
            *(float4*)&out[base + 4] = v1;
        }
    }
}

// =====================================================================
// Complex helpers + FFT kernels
// =====================================================================
// Forward FFT of z = q + i*k (one complex FFT does two real FFTs).
// Accumulates Qf * conj(Kf) over 8 channels per block into g_spart.
// 1024 threads, dyn smem = 4096 float2 (buf) + 2048 float2 (twiddles) = 48KB.
__global__ void fftcorr_kernel()
{
    extern __shared__ float2 sm[];
    float2* buf = sm;          // 4096
    float2* tw  = sm + 4096;   // 2048: tw[j] = exp(-2*pi*i*j/4096)

    const int tid = threadIdx.x;
    const int g = blockIdx.x, b = blockIdx.y;

    for (int j = tid; j < 2048; j += 1024) {
        float s, c;
        sincosf(6.283185307179586f * (float)j / 4096.0f, &s, &c);
        tw[j] = make_float2(c, -s);
    }

    float2 acc[4] = {{0,0},{0,0},{0,0},{0,0}};

    for (int cc = 0; cc < 8; ++cc) {
        int ch = g * 8 + cc;
        const float* qp = g_q + (((size_t)b * DMODEL + ch) << 12);
        const float* kp = g_k + (((size_t)b * DMODEL + ch) << 12);

        __syncthreads();  // buf free from previous iteration; tw ready (iter 0)
#pragma unroll
        for (int it = 0; it < 4; ++it) {
            int i = tid + it * 1024;
            int r = __brev((unsigned)i) >> 20;
            buf[r] = make_float2(qp[i], kp[i]);
        }
        __syncthreads();

        for (int s = 0; s < 12; ++s) {
            int half = 1 << s;
#pragma unroll
            for (int it = 0; it < 2; ++it) {
                int bfi = tid + it * 1024;                 // 0..2047
                int pos = bfi & (half - 1);
                int i = ((bfi >> s) << (s + 1)) + pos;
                int j = i + half;
                float2 w = tw[pos << (11 - s)];
                float2 u = buf[i];
                float2 v = buf[j];
                float2 t = make_float2(w.x * v.x - w.y * v.y,
                                       w.x * v.y + w.y * v.x);
                buf[i] = make_float2(u.x + t.x, u.y + t.y);
                buf[j] = make_float2(u.x - t.x, u.y - t.y);
            }
            __syncthreads();
        }

        // Hermitian split + product:  P[f] = Q[f] * conj(K[f])
#pragma unroll
        for (int it = 0; it < 4; ++it) {
            int f = tid + it * 1024;
            float2 Zf = buf[f];
            float2 Zm = buf[(4096 - f) & 4095];
            float2 Q  = make_float2(0.5f * (Zf.x + Zm.x), 0.5f * (Zf.y - Zm.y));
            float dx = Zf.x - Zm.x, dy = Zf.y + Zm.y;
            float2 Kc = make_float2(0.5f * dy, -0.5f * dx);
            acc[it].x += Q.x * Kc.x + Q.y * Kc.y;
            acc[it].y += Q.y * Kc.x - Q.x * Kc.y;
        }
    }
    __syncthreads();
#pragma unroll
    for (int it = 0; it < 4; ++it) {
        int f = tid + it * 1024;
        g_spart[(((size_t)b * NGRP + g) << 12) + f] = acc[it];
    }
}

// Reduce channel-group partials, inverse FFT, write mean_corr (scaled).
__global__ void ifft_kernel()
{
    extern __shared__ float2 sm[];
    float2* buf = sm;
    float2* tw  = sm + 4096;

    const int tid = threadIdx.x;
    const int b = blockIdx.x;

    for (int j = tid; j < 2048; j += 1024) {
        float s, c;
        sincosf(6.283185307179586f * (float)j / 4096.0f, &s, &c);
        tw[j] = make_float2(c, s);   // conj: inverse transform
    }

#pragma unroll
    for (int it = 0; it < 4; ++it) {
        int f = tid + it * 1024;
        const float2* sp = g_spart + (((size_t)b * NGRP) << 12) + f;
        float2 s = make_float2(0.f, 0.f);
        for (int gp = 0; gp < NGRP; ++gp) {
            float2 v = sp[(size_t)gp << 12];
            s.x += v.x; s.y += v.y;
        }
        buf[__brev((unsigned)f) >> 20] = s;
    }
    __syncthreads();

    for (int s = 0; s < 12; ++s) {
        int half = 1 << s;
#pragma unroll
        for (int it = 0; it < 2; ++it) {
            int bfi = tid + it * 1024;
            int pos = bfi & (half - 1);
            int i = ((bfi >> s) << (s + 1)) + pos;
            int j = i + half;
            float2 w = tw[pos << (11 - s)];
            float2 u = buf[i];
            float2 v = buf[j];
            float2 t = make_float2(w.x * v.x - w.y * v.y,
                                   w.x * v.y + w.y * v.x);
            buf[i] = make_float2(u.x + t.x, u.y + t.y);
            buf[j] = make_float2(u.x - t.x, u.y - t.y);
        }
        __syncthreads();
    }

    const float scale = 1.0f / (4096.0f * 512.0f);  // 1/L (ifft) * 1/D (channel mean)
#pragma unroll
    for (int it = 0; it < 4; ++it) {
        int tau = tid + it * 1024;
        g_mcorr[b * LSEQ + tau] = buf[tau].x * scale;
    }
}

// =====================================================================
// Top-8 delays per batch + softmax weights. One block per batch.
// =====================================================================
__global__ void topk_kernel()
{
    __shared__ float sval[LSEQ];
    __shared__ float rv[256];
    __shared__ int   ri[256];
    __shared__ float wv[TOPK];
    __shared__ int   wi[TOPK];

    const int tid = threadIdx.x;
    const int b = blockIdx.x;

    for (int i = tid; i < LSEQ; i += 256) sval[i] = g_mcorr[b * LSEQ + i];
    __syncthreads();

    for (int r = 0; r < TOPK; ++r) {
        float best = -FLT_MAX;
        int bi = 0x7fffffff;
        for (int i = tid; i < LSEQ; i += 256) {
            float v = sval[i];
            if (v > best) { best = v; bi = i; }
        }
        rv[tid] = best; ri[tid] = bi;
        __syncthreads();
        for (int s = 128; s > 0; s >>= 1) {
            if (tid < s) {
                if (rv[tid + s] > rv[tid] ||
                    (rv[tid + s] == rv[tid] && ri[tid + s] < ri[tid])) {
                    rv[tid] = rv[tid + s]; ri[tid] = ri[tid + s];
                }
            }
            __syncthreads();
        }
        if (tid == 0) { wv[r] = rv[0]; wi[r] = ri[0]; sval[ri[0]] = -FLT_MAX; }
        __syncthreads();
    }

    if (tid == 0) {
        float mx = wv[0];           // first extracted is the max
        float e[TOPK], sum = 0.f;
#pragma unroll
        for (int i = 0; i < TOPK; ++i) { e[i] = expf(wv[i] - mx); sum += e[i]; }
        float inv = 1.0f / sum;
#pragma unroll
        for (int i = 0; i < TOPK; ++i) {
            g_weights[b * TOPK + i] = e[i] * inv;
            g_delays [b * TOPK + i] = wi[i];
        }
    }
}

// =====================================================================
// Circular gather + weighted aggregation:
//   agg[b,c,l] = sum_i w[b,i] * v[b,c,(l+delay[b,i]) % L]
// =====================================================================
__global__ void gather_kernel()
{
    __shared__ float ws[TOPK];
    __shared__ int   ds[TOPK];
    const int tid = threadIdx.x;
    const int l = blockIdx.x * 256 + tid;
    const int c = blockIdx.y;
    const int b = blockIdx.z;

    if (tid < TOPK) {
        ws[tid] = g_weights[b * TOPK + tid];
        ds[tid] = g_delays [b * TOPK + tid];
    }
    __syncthreads();

    const float* vp = g_v + (((size_t)b * DMODEL + c) << 12);
    float acc = 0.f;
#pragma unroll
    for (int i = 0; i < TOPK; ++i)
        acc += ws[i] * vp[(l + ds[i]) & (LSEQ - 1)];

    g_agg[(((size_t)b * DMODEL + c) << 12) + l] = acc;
}

// =====================================================================
extern "C" void kernel_launch(void* const* d_in, const int* in_sizes, int n_in,
                              void* d_out, int out_size)
{
    const float* hs = (const float*)d_in[0];
    const float* Wq = (const float*)d_in[1];
    const float* bq = (const float*)d_in[2];
    const float* Wk = (const float*)d_in[3];
    const float* bk = (const float*)d_in[4];
    const float* Wv = (const float*)d_in[5];
    const float* bv = (const float*)d_in[6];
    const float* Wo = (const float*)d_in[7];
    const float* bo = (const float*)d_in[8];
    float* out = (float*)d_out;

    void *pq, *pk, *pv, *pa;
    cudaGetSymbolAddress(&pq, g_q);
    cudaGetSymbolAddress(&pk, g_k);
    cudaGetSymbolAddress(&pv, g_v);
    cudaGetSymbolAddress(&pa, g_agg);

    dim3 gemm_grid(LSEQ / 128, DMODEL / 128, BATCH);   // (32, 4, 8)

    // Projections -> [B, D, L]
    gemm_kernel<false, false><<<gemm_grid, 256>>>(Wq, hs, bq, (float*)pq);
    gemm_kernel<false, false><<<gemm_grid, 256>>>(Wk, hs, bk, (float*)pk);
    gemm_kernel<false, false><<<gemm_grid, 256>>>(Wv, hs, bv, (float*)pv);

    // Packed real FFTs + spectral product accumulation
    fftcorr_kernel<<<dim3(NGRP, BATCH), 1024, 49152>>>();

    // Reduce + inverse FFT -> mean_corr
    ifft_kernel<<<BATCH, 1024, 49152>>>();

    // Top-k delays + softmax weights
    topk_kernel<<<BATCH, 256>>>();

    // Time-delay aggregation -> agg [B, D, L]
    gather_kernel<<<dim3(LSEQ / 256, DMODEL, BATCH), 256>>>();

    // Output projection (transposed store into [B, L, D])
    gemm_kernel<true, true><<<gemm_grid, 256>>>(Wo, (const float*)pa, bo, out);
}

// round 5
// speedup vs baseline: 1.9153x; 1.9153x over previous
#include <cuda_runtime.h>
#include <cuda_bf16.h>
#include <math.h>
#include <float.h>
#include <stdint.h>

#define BATCH  8
#define LSEQ   4096
#define DMODEL 512
#define TOPK   8
#define NGRP   64
#define WSZ    (DMODEL * DMODEL)

// ---------------- scratch (static device globals; no allocations) ----------------
__device__ float  g_q  [BATCH * DMODEL * LSEQ];
__device__ float  g_k  [BATCH * DMODEL * LSEQ];
__device__ float  g_v  [BATCH * DMODEL * LSEQ];
__device__ float2 g_spart[BATCH * NGRP * LSEQ];
__device__ float  g_mcorr[BATCH * LSEQ];
__device__ float  g_weights[BATCH * TOPK];
__device__ int    g_delays [BATCH * TOPK];
// bf16 hi/lo operands
__device__ __nv_bfloat16 g_xhi [BATCH * LSEQ * DMODEL];
__device__ __nv_bfloat16 g_xlo [BATCH * LSEQ * DMODEL];
__device__ __nv_bfloat16 g_whi [4 * WSZ];
__device__ __nv_bfloat16 g_wlo [4 * WSZ];
__device__ __nv_bfloat16 g_athi[BATCH * LSEQ * DMODEL];   // aggT [B, L, D]
__device__ __nv_bfloat16 g_atlo[BATCH * LSEQ * DMODEL];

// ====================== helpers ======================
__device__ __forceinline__ uint32_t smem_u32(const void* p) {
    uint32_t a;
    asm("{ .reg .u64 t; cvta.to.shared.u64 t, %1; cvt.u32.u64 %0, t; }" : "=r"(a) : "l"(p));
    return a;
}
#define SWZ(off) ((off) ^ (((off) >> 3) & 0x70))

__device__ __forceinline__ void cpa16(uint32_t dst, const void* src) {
    asm volatile("cp.async.ca.shared.global [%0], [%1], 16;" :: "r"(dst), "l"(src));
}
#define CPA_COMMIT() asm volatile("cp.async.commit_group;" ::: "memory")
#define CPA_WAIT(N)  asm volatile("cp.async.wait_group %0;" :: "n"(N) : "memory")

__device__ __forceinline__ void ldmA(uint32_t* a, uint32_t addr) {
    asm volatile("ldmatrix.sync.aligned.m8n8.x4.shared.b16 {%0,%1,%2,%3}, [%4];"
        : "=r"(a[0]), "=r"(a[1]), "=r"(a[2]), "=r"(a[3]) : "r"(addr));
}
__device__ __forceinline__ void ldmB(uint32_t* b, uint32_t addr) {
    asm volatile("ldmatrix.sync.aligned.m8n8.x2.shared.b16 {%0,%1}, [%2];"
        : "=r"(b[0]), "=r"(b[1]) : "r"(addr));
}
__device__ __forceinline__ void mma16816(float* c, const uint32_t* a, const uint32_t* b) {
    asm volatile("mma.sync.aligned.m16n8k16.row.col.f32.bf16.bf16.f32 "
        "{%0,%1,%2,%3}, {%4,%5,%6,%7}, {%8,%9}, {%0,%1,%2,%3};"
        : "+f"(c[0]), "+f"(c[1]), "+f"(c[2]), "+f"(c[3])
        : "r"(a[0]), "r"(a[1]), "r"(a[2]), "r"(a[3]), "r"(b[0]), "r"(b[1]));
}

// ====================== bf16x3 mma.sync GEMM ======================
// C[b,m,n](+bias[m]) = sum_k W[m,k]*X[b,n,k];  M=512, N=4096, K=512
// W hi/lo [512,512] k-contig; X hi/lo [B,4096,512] k-contig
// TRANS_OUT=false: out[b,m,n];  true: out[b,n,m]
#define BM 128
#define BN 128
#define BK 64
#define NCHUNK (DMODEL / BK)       // 8
#define TSZ     16384              // one 128row x 128B tile
#define OFF_AHI 0
#define OFF_ALO (TSZ)
#define OFF_BHI (2 * TSZ)
#define OFF_BLO (3 * TSZ)
#define STAGE_BYTES (4 * TSZ)      // 65536
#define GEMM_DSMEM  (2 * STAGE_BYTES + 1024)

template<bool TRANS_OUT>
__global__ __launch_bounds__(256, 1)
void gemm_bf16x3_kernel(const __nv_bfloat16* __restrict__ Ahi,
                        const __nv_bfloat16* __restrict__ Alo,
                        const __nv_bfloat16* __restrict__ Bhi,
                        const __nv_bfloat16* __restrict__ Blo,
                        const float* __restrict__ bias,
                        float* __restrict__ out)
{
    extern __shared__ char dsm[];
    const int tid  = threadIdx.x;
    const int wid  = tid >> 5;
    const int lane = tid & 31;
    const int wm   = wid >> 2;          // 0..1  (64 m rows)
    const int wn   = wid & 3;           // 0..3  (32 n cols)
    const int b  = blockIdx.z;
    const int m0 = blockIdx.y * BM;
    const int n0 = blockIdx.x * BN;

    uint32_t sbase = (smem_u32(dsm) + 1023u) & ~1023u;

    const __nv_bfloat16* aHi = Ahi + (size_t)m0 * DMODEL;
    const __nv_bfloat16* aLo = Alo + (size_t)m0 * DMODEL;
    const __nv_bfloat16* bHi = Bhi + ((size_t)b * LSEQ + n0) * DMODEL;
    const __nv_bfloat16* bLo = Blo + ((size_t)b * LSEQ + n0) * DMODEL;

    auto load_chunk = [&](int s, int k0) {
        uint32_t sb = sbase + s * STAGE_BYTES;
#pragma unroll
        for (int it = 0; it < 4; ++it) {
            int idx = tid + it * 256;              // 0..1023
            int row = idx >> 3, q = idx & 7;
            uint32_t sw = SWZ((uint32_t)(row * 128 + q * 16));
            size_t go = (size_t)row * DMODEL + k0 + q * 8;
            cpa16(sb + OFF_AHI + sw, aHi + go);
            cpa16(sb + OFF_ALO + sw, aLo + go);
            cpa16(sb + OFF_BHI + sw, bHi + go);
            cpa16(sb + OFF_BLO + sw, bLo + go);
        }
        CPA_COMMIT();
    };

    float c[4][4][4];
#pragma unroll
    for (int i = 0; i < 4; ++i)
#pragma unroll
        for (int j = 0; j < 4; ++j)
#pragma unroll
            for (int r = 0; r < 4; ++r) c[i][j][r] = 0.f;

    load_chunk(0, 0);

    for (int ch = 0; ch < NCHUNK; ++ch) {
        int s = ch & 1;
        if (ch < NCHUNK - 1) { load_chunk(s ^ 1, (ch + 1) * BK); CPA_WAIT(1); }
        else                 { CPA_WAIT(0); }
        __syncthreads();

        uint32_t sb = sbase + s * STAGE_BYTES;
        uint32_t aHiB = sb + OFF_AHI, aLoB = sb + OFF_ALO;
        uint32_t bHiB = sb + OFF_BHI, bLoB = sb + OFF_BLO;

#pragma unroll
        for (int ks = 0; ks < 4; ++ks) {
            // B fragments (4 n-tiles, hi+lo)
            uint32_t bh[4][2], bl[4][2];
#pragma unroll
            for (int ni = 0; ni < 4; ++ni) {
                uint32_t rowb = wn * 32 + ni * 8 + (lane & 7);
                uint32_t cb   = ks * 32 + (((lane >> 3) & 1) << 4);
                uint32_t off  = SWZ(rowb * 128 + cb);
                ldmB(bh[ni], bHiB + off);
                ldmB(bl[ni], bLoB + off);
            }
            // A fragments per m-tile, 3-pass mma
#pragma unroll
            for (int mi = 0; mi < 4; ++mi) {
                uint32_t rowa = wm * 64 + mi * 16 + (lane & 15);
                uint32_t ca   = ks * 32 + ((lane >> 4) << 4);
                uint32_t off  = SWZ(rowa * 128 + ca);
                uint32_t ah[4], al[4];
                ldmA(ah, aHiB + off);
                ldmA(al, aLoB + off);
#pragma unroll
                for (int ni = 0; ni < 4; ++ni) {
                    mma16816(c[mi][ni], ah, bh[ni]);
                    mma16816(c[mi][ni], ah, bl[ni]);
                    mma16816(c[mi][ni], al, bh[ni]);
                }
            }
        }
        __syncthreads();
    }

    // ---------------- epilogue ----------------
    const int r  = lane >> 2;
    const int q2 = (lane & 3) << 1;
#pragma unroll
    for (int mi = 0; mi < 4; ++mi) {
        int m = m0 + wm * 64 + mi * 16 + r;
        float b0v = bias[m];
        float b1v = bias[m + 8];
#pragma unroll
        for (int ni = 0; ni < 4; ++ni) {
            int n = n0 + wn * 32 + ni * 8 + q2;
            if (!TRANS_OUT) {
                float* p = out + ((size_t)(b * DMODEL + m) << 12) + n;
                *(float2*)p = make_float2(c[mi][ni][0] + b0v, c[mi][ni][1] + b0v);
                float* p2 = p + (8 << 12);
                *(float2*)p2 = make_float2(c[mi][ni][2] + b1v, c[mi][ni][3] + b1v);
            } else {
                float* p = out + (((size_t)b * LSEQ + n) << 9) + m;
                p[0]       = c[mi][ni][0] + b0v;
                p[8]       = c[mi][ni][2] + b1v;
                p[512]     = c[mi][ni][1] + b0v;
                p[512 + 8] = c[mi][ni][3] + b1v;
            }
        }
    }
}

// ====================== fp32 -> bf16 hi/lo converts ======================
__global__ void convert_x_kernel(const float* __restrict__ x)
{
    int i = blockIdx.x * blockDim.x + threadIdx.x;   // over float4s
    float4 v = ((const float4*)x)[i];
    float f[4] = {v.x, v.y, v.z, v.w};
    __nv_bfloat16 h[4], l[4];
#pragma unroll
    for (int j = 0; j < 4; ++j) {
        h[j] = __float2bfloat16(f[j]);
        l[j] = __float2bfloat16(f[j] - __bfloat162float(h[j]));
    }
    __nv_bfloat162 h01, h23, l01, l23;
    h01.x = h[0]; h01.y = h[1]; h23.x = h[2]; h23.y = h[3];
    l01.x = l[0]; l01.y = l[1]; l23.x = l[2]; l23.y = l[3];
    ((__nv_bfloat162*)g_xhi)[2 * i]     = h01;
    ((__nv_bfloat162*)g_xhi)[2 * i + 1] = h23;
    ((__nv_bfloat162*)g_xlo)[2 * i]     = l01;
    ((__nv_bfloat162*)g_xlo)[2 * i + 1] = l23;
}

__global__ void convert_w_kernel(const float* __restrict__ w0, const float* __restrict__ w1,
                                 const float* __restrict__ w2, const float* __restrict__ w3)
{
    int wi = blockIdx.y;
    const float* w = (wi == 0) ? w0 : (wi == 1) ? w1 : (wi == 2) ? w2 : w3;
    int i = blockIdx.x * blockDim.x + threadIdx.x;   // over float4s (65536)
    float4 v = ((const float4*)w)[i];
    float f[4] = {v.x, v.y, v.z, v.w};
#pragma unroll
    for (int j = 0; j < 4; ++j) {
        __nv_bfloat16 h = __float2bfloat16(f[j]);
        __nv_bfloat16 l = __float2bfloat16(f[j] - __bfloat162float(h));
        g_whi[(size_t)wi * WSZ + i * 4 + j] = h;
        g_wlo[(size_t)wi * WSZ + i * 4 + j] = l;
    }
}

// ====================== FFT correlation ======================
__global__ void fftcorr_kernel()
{
    extern __shared__ float2 sm[];
    float2* buf = sm;
    float2* tw  = sm + 4096;

    const int tid = threadIdx.x;
    const int g = blockIdx.x, b = blockIdx.y;

    for (int j = tid; j < 2048; j += 1024) {
        float s, c;
        sincosf(6.283185307179586f * (float)j / 4096.0f, &s, &c);
        tw[j] = make_float2(c, -s);
    }

    float2 acc[4] = {{0,0},{0,0},{0,0},{0,0}};

    for (int cc = 0; cc < 8; ++cc) {
        int ch = g * 8 + cc;
        const float* qp = g_q + (((size_t)b * DMODEL + ch) << 12);
        const float* kp = g_k + (((size_t)b * DMODEL + ch) << 12);

        __syncthreads();
#pragma unroll
        for (int it = 0; it < 4; ++it) {
            int i = tid + it * 1024;
            int r = __brev((unsigned)i) >> 20;
            buf[r] = make_float2(qp[i], kp[i]);
        }
        __syncthreads();

        for (int s = 0; s < 12; ++s) {
            int half = 1 << s;
#pragma unroll
            for (int it = 0; it < 2; ++it) {
                int bfi = tid + it * 1024;
                int pos = bfi & (half - 1);
                int i = ((bfi >> s) << (s + 1)) + pos;
                int j = i + half;
                float2 w = tw[pos << (11 - s)];
                float2 u = buf[i];
                float2 v = buf[j];
                float2 t = make_float2(w.x * v.x - w.y * v.y,
                                       w.x * v.y + w.y * v.x);
                buf[i] = make_float2(u.x + t.x, u.y + t.y);
                buf[j] = make_float2(u.x - t.x, u.y - t.y);
            }
            __syncthreads();
        }

#pragma unroll
        for (int it = 0; it < 4; ++it) {
            int f = tid + it * 1024;
            float2 Zf = buf[f];
            float2 Zm = buf[(4096 - f) & 4095];
            float2 Q  = make_float2(0.5f * (Zf.x + Zm.x), 0.5f * (Zf.y - Zm.y));
            float dx = Zf.x - Zm.x, dy = Zf.y + Zm.y;
            float2 Kc = make_float2(0.5f * dy, -0.5f * dx);
            acc[it].x += Q.x * Kc.x + Q.y * Kc.y;
            acc[it].y += Q.y * Kc.x - Q.x * Kc.y;
        }
    }
    __syncthreads();
#pragma unroll
    for (int it = 0; it < 4; ++it) {
        int f = tid + it * 1024;
        g_spart[(((size_t)b * NGRP + g) << 12) + f] = acc[it];
    }
}

__global__ void ifft_kernel()
{
    extern __shared__ float2 sm[];
    float2* buf = sm;
    float2* tw  = sm + 4096;

    const int tid = threadIdx.x;
    const int b = blockIdx.x;

    for (int j = tid; j < 2048; j += 1024) {
        float s, c;
        sincosf(6.283185307179586f * (float)j / 4096.0f, &s, &c);
        tw[j] = make_float2(c, s);
    }

#pragma unroll
    for (int it = 0; it < 4; ++it) {
        int f = tid + it * 1024;
        const float2* sp = g_spart + (((size_t)b * NGRP) << 12) + f;
        float2 s = make_float2(0.f, 0.f);
        for (int gp = 0; gp < NGRP; ++gp) {
            float2 v = sp[(size_t)gp << 12];
            s.x += v.x; s.y += v.y;
        }
        buf[__brev((unsigned)f) >> 20] = s;
    }
    __syncthreads();

    for (int s = 0; s < 12; ++s) {
        int half = 1 << s;
#pragma unroll
        for (int it = 0; it < 2; ++it) {
            int bfi = tid + it * 1024;
            int pos = bfi & (half - 1);
            int i = ((bfi >> s) << (s + 1)) + pos;
            int j = i + half;
            float2 w = tw[pos << (11 - s)];
            float2 u = buf[i];
            float2 v = buf[j];
            float2 t = make_float2(w.x * v.x - w.y * v.y,
                                   w.x * v.y + w.y * v.x);
            buf[i] = make_float2(u.x + t.x, u.y + t.y);
            buf[j] = make_float2(u.x - t.x, u.y - t.y);
        }
        __syncthreads();
    }

    const float scale = 1.0f / (4096.0f * 512.0f);
#pragma unroll
    for (int it = 0; it < 4; ++it) {
        int tau = tid + it * 1024;
        g_mcorr[b * LSEQ + tau] = buf[tau].x * scale;
    }
}

// ====================== top-k + softmax ======================
__global__ void topk_kernel()
{
    __shared__ float sval[LSEQ];
    __shared__ float rv[256];
    __shared__ int   ri[256];
    __shared__ float wv[TOPK];
    __shared__ int   wi[TOPK];

    const int tid = threadIdx.x;
    const int b = blockIdx.x;

    for (int i = tid; i < LSEQ; i += 256) sval[i] = g_mcorr[b * LSEQ + i];
    __syncthreads();

    for (int r = 0; r < TOPK; ++r) {
        float best = -FLT_MAX;
        int bi = 0x7fffffff;
        for (int i = tid; i < LSEQ; i += 256) {
            float v = sval[i];
            if (v > best) { best = v; bi = i; }
        }
        rv[tid] = best; ri[tid] = bi;
        __syncthreads();
        for (int s = 128; s > 0; s >>= 1) {
            if (tid < s) {
                if (rv[tid + s] > rv[tid] ||
                    (rv[tid + s] == rv[tid] && ri[tid + s] < ri[tid])) {
                    rv[tid] = rv[tid + s]; ri[tid] = ri[tid + s];
                }
            }
            __syncthreads();
        }
        if (tid == 0) { wv[r] = rv[0]; wi[r] = ri[0]; sval[ri[0]] = -FLT_MAX; }
        __syncthreads();
    }

    if (tid == 0) {
        float mx = wv[0];
        float e[TOPK], sum = 0.f;
#pragma unroll
        for (int i = 0; i < TOPK; ++i) { e[i] = expf(wv[i] - mx); sum += e[i]; }
        float inv = 1.0f / sum;
#pragma unroll
        for (int i = 0; i < TOPK; ++i) {
            g_weights[b * TOPK + i] = e[i] * inv;
            g_delays [b * TOPK + i] = wi[i];
        }
    }
}

// ====================== gather + transpose + bf16 split ======================
__global__ void gather_kernel()
{
    __shared__ float ws[TOPK];
    __shared__ int   ds[TOPK];
    __shared__ float tile[32][33];

    const int tx = threadIdx.x;
    const int ty = threadIdx.y;
    const int tid = ty * 32 + tx;
    const int b  = blockIdx.z;
    const int c0 = blockIdx.y * 32;
    const int l0 = blockIdx.x * 32;

    if (tid < TOPK) {
        ws[tid] = g_weights[b * TOPK + tid];
        ds[tid] = g_delays [b * TOPK + tid];
    }
    __syncthreads();

    const int l = l0 + tx;
#pragma unroll
    for (int i = 0; i < 4; ++i) {
        int c = c0 + ty + i * 8;
        const float* vp = g_v + (((size_t)b * DMODEL + c) << 12);
        float acc = 0.f;
#pragma unroll
        for (int j = 0; j < TOPK; ++j)
            acc += ws[j] * vp[(l + ds[j]) & (LSEQ - 1)];
        tile[ty + i * 8][tx] = acc;
    }
    __syncthreads();

#pragma unroll
    for (int i = 0; i < 4; ++i) {
        int lr = ty + i * 8;
        float v = tile[tx][lr];
        __nv_bfloat16 h = __float2bfloat16(v);
        __nv_bfloat16 lo = __float2bfloat16(v - __bfloat162float(h));
        size_t addr = (((size_t)b * LSEQ + l0 + lr) << 9) + c0 + tx;
        g_athi[addr] = h;
        g_atlo[addr] = lo;
    }
}

// =====================================================================
extern "C" void kernel_launch(void* const* d_in, const int* in_sizes, int n_in,
                              void* d_out, int out_size)
{
    const float* hs = (const float*)d_in[0];
    const float* Wq = (const float*)d_in[1];
    const float* bq = (const float*)d_in[2];
    const float* Wk = (const float*)d_in[3];
    const float* bk = (const float*)d_in[4];
    const float* Wv = (const float*)d_in[5];
    const float* bv = (const float*)d_in[6];
    const float* Wo = (const float*)d_in[7];
    const float* bo = (const float*)d_in[8];
    float* out = (float*)d_out;

    void *pq, *pk, *pv, *pxhi, *pxlo, *pwhi, *pwlo, *pathi, *patlo;
    cudaGetSymbolAddress(&pq,   g_q);
    cudaGetSymbolAddress(&pk,   g_k);
    cudaGetSymbolAddress(&pv,   g_v);
    cudaGetSymbolAddress(&pxhi, g_xhi);
    cudaGetSymbolAddress(&pxlo, g_xlo);
    cudaGetSymbolAddress(&pwhi, g_whi);
    cudaGetSymbolAddress(&pwlo, g_wlo);
    cudaGetSymbolAddress(&pathi, g_athi);
    cudaGetSymbolAddress(&patlo, g_atlo);

    cudaFuncSetAttribute(gemm_bf16x3_kernel<false>,
                         cudaFuncAttributeMaxDynamicSharedMemorySize, GEMM_DSMEM);
    cudaFuncSetAttribute(gemm_bf16x3_kernel<true>,
                         cudaFuncAttributeMaxDynamicSharedMemorySize, GEMM_DSMEM);

    const __nv_bfloat16* whi = (const __nv_bfloat16*)pwhi;
    const __nv_bfloat16* wlo = (const __nv_bfloat16*)pwlo;

    // 1. fp32 -> bf16 hi/lo
    convert_x_kernel<<<(BATCH * LSEQ * DMODEL / 4) / 256, 256>>>(hs);
    convert_w_kernel<<<dim3(WSZ / 4 / 256, 4), 256>>>(Wq, Wk, Wv, Wo);

    // 2. Q/K/V projections -> [B, D, L] fp32
    dim3 gg(LSEQ / BN, DMODEL / BM, BATCH);   // (32, 4, 8)
    gemm_bf16x3_kernel<false><<<gg, 256, GEMM_DSMEM>>>(whi + 0 * WSZ, wlo + 0 * WSZ,
        (const __nv_bfloat16*)pxhi, (const __nv_bfloat16*)pxlo, bq, (float*)pq);
    gemm_bf16x3_kernel<false><<<gg, 256, GEMM_DSMEM>>>(whi + 1 * WSZ, wlo + 1 * WSZ,
        (const __nv_bfloat16*)pxhi, (const __nv_bfloat16*)pxlo, bk, (float*)pk);
    gemm_bf16x3_kernel<false><<<gg, 256, GEMM_DSMEM>>>(whi + 2 * WSZ, wlo + 2 * WSZ,
        (const __nv_bfloat16*)pxhi, (const __nv_bfloat16*)pxlo, bv, (float*)pv);

    // 3. correlation spectrum + mean + topk
    fftcorr_kernel<<<dim3(NGRP, BATCH), 1024, 49152>>>();
    ifft_kernel<<<BATCH, 1024, 49152>>>();
    topk_kernel<<<BATCH, 256>>>();

    // 4. gather -> aggT hi/lo [B, L, D]
    gather_kernel<<<dim3(LSEQ / 32, DMODEL / 32, BATCH), dim3(32, 8)>>>();

    // 5. output projection, transposed store -> out [B, L, D]
    gemm_bf16x3_kernel<true><<<gg, 256, GEMM_DSMEM>>>(whi + 3 * WSZ, wlo + 3 * WSZ,
        (const __nv_bfloat16*)pathi, (const __nv_bfloat16*)patlo, bo, out);
}

// round 6
// speedup vs baseline: 2.2355x; 1.1672x over previous
#include <cuda_runtime.h>
#include <cuda_bf16.h>
#include <math.h>
#include <float.h>
#include <stdint.h>

#define BATCH  8
#define LSEQ   4096
#define DMODEL 512
#define TOPK   8
#define NGRP   64
#define WSZ    (DMODEL * DMODEL)

// ---------------- scratch (static device globals; no allocations) ----------------
__device__ float  g_q  [BATCH * DMODEL * LSEQ];
__device__ float  g_k  [BATCH * DMODEL * LSEQ];
__device__ float  g_v  [BATCH * DMODEL * LSEQ];
__device__ float2 g_spart[BATCH * NGRP * LSEQ];
__device__ float2 g_sred [BATCH * LSEQ];
__device__ float  g_mcorr[BATCH * LSEQ];
__device__ float  g_weights[BATCH * TOPK];
__device__ int    g_delays [BATCH * TOPK];
// bf16 hi/lo operands
__device__ __nv_bfloat16 g_xhi [BATCH * LSEQ * DMODEL];
__device__ __nv_bfloat16 g_xlo [BATCH * LSEQ * DMODEL];
__device__ __nv_bfloat16 g_whi [4 * WSZ];
__device__ __nv_bfloat16 g_wlo [4 * WSZ];
__device__ __nv_bfloat16 g_athi[BATCH * LSEQ * DMODEL];   // aggT [B, L, D]
__device__ __nv_bfloat16 g_atlo[BATCH * LSEQ * DMODEL];

// ====================== helpers ======================
__device__ __forceinline__ uint32_t smem_u32(const void* p) {
    uint32_t a;
    asm("{ .reg .u64 t; cvta.to.shared.u64 t, %1; cvt.u32.u64 %0, t; }" : "=r"(a) : "l"(p));
    return a;
}
#define SWZ(off) ((off) ^ (((off) >> 3) & 0x70))

__device__ __forceinline__ void cpa16(uint32_t dst, const void* src) {
    asm volatile("cp.async.ca.shared.global [%0], [%1], 16;" :: "r"(dst), "l"(src));
}
#define CPA_COMMIT() asm volatile("cp.async.commit_group;" ::: "memory")
#define CPA_WAIT(N)  asm volatile("cp.async.wait_group %0;" :: "n"(N) : "memory")

__device__ __forceinline__ void ldmA(uint32_t* a, uint32_t addr) {
    asm volatile("ldmatrix.sync.aligned.m8n8.x4.shared.b16 {%0,%1,%2,%3}, [%4];"
        : "=r"(a[0]), "=r"(a[1]), "=r"(a[2]), "=r"(a[3]) : "r"(addr));
}
__device__ __forceinline__ void ldmB(uint32_t* b, uint32_t addr) {
    asm volatile("ldmatrix.sync.aligned.m8n8.x2.shared.b16 {%0,%1}, [%2];"
        : "=r"(b[0]), "=r"(b[1]) : "r"(addr));
}
__device__ __forceinline__ void mma16816(float* c, const uint32_t* a, const uint32_t* b) {
    asm volatile("mma.sync.aligned.m16n8k16.row.col.f32.bf16.bf16.f32 "
        "{%0,%1,%2,%3}, {%4,%5,%6,%7}, {%8,%9}, {%0,%1,%2,%3};"
        : "+f"(c[0]), "+f"(c[1]), "+f"(c[2]), "+f"(c[3])
        : "r"(a[0]), "r"(a[1]), "r"(a[2]), "r"(a[3]), "r"(b[0]), "r"(b[1]));
}

// ====================== bf16x3 mma.sync GEMM core ======================
#define BM 128
#define BN 128
#define BK 64
#define NCHUNK (DMODEL / BK)       // 8
#define TSZ     16384
#define OFF_AHI 0
#define OFF_ALO (TSZ)
#define OFF_BHI (2 * TSZ)
#define OFF_BLO (3 * TSZ)
#define STAGE_BYTES (4 * TSZ)              // 65536
#define NSTAGE 3
#define GEMM_DSMEM  (NSTAGE * STAGE_BYTES + 1024)

template<bool TRANS_OUT>
__device__ __forceinline__
void gemm_body(const __nv_bfloat16* __restrict__ Ahi,
               const __nv_bfloat16* __restrict__ Alo,
               const __nv_bfloat16* __restrict__ Bhi,
               const __nv_bfloat16* __restrict__ Blo,
               const float* __restrict__ bias,
               float* __restrict__ out,
               char* dsm, int b, int m0, int n0)
{
    const int tid  = threadIdx.x;
    const int wid  = tid >> 5;
    const int lane = tid & 31;
    const int wm   = wid >> 2;
    const int wn   = wid & 3;

    uint32_t sbase = (smem_u32(dsm) + 1023u) & ~1023u;

    const __nv_bfloat16* aHi = Ahi + (size_t)m0 * DMODEL;
    const __nv_bfloat16* aLo = Alo + (size_t)m0 * DMODEL;
    const __nv_bfloat16* bHi = Bhi + ((size_t)b * LSEQ + n0) * DMODEL;
    const __nv_bfloat16* bLo = Blo + ((size_t)b * LSEQ + n0) * DMODEL;

    auto load_chunk = [&](int st, int k0) {
        uint32_t sb = sbase + st * STAGE_BYTES;
#pragma unroll
        for (int it = 0; it < 4; ++it) {
            int idx = tid + it * 256;
            int row = idx >> 3, q = idx & 7;
            uint32_t sw = SWZ((uint32_t)(row * 128 + q * 16));
            size_t go = (size_t)row * DMODEL + k0 + q * 8;
            cpa16(sb + OFF_AHI + sw, aHi + go);
            cpa16(sb + OFF_ALO + sw, aLo + go);
            cpa16(sb + OFF_BHI + sw, bHi + go);
            cpa16(sb + OFF_BLO + sw, bLo + go);
        }
        CPA_COMMIT();
    };

    float c[4][4][4];
#pragma unroll
    for (int i = 0; i < 4; ++i)
#pragma unroll
        for (int j = 0; j < 4; ++j)
#pragma unroll
            for (int r = 0; r < 4; ++r) c[i][j][r] = 0.f;

    load_chunk(0, 0);
    load_chunk(1, BK);

    for (int ch = 0; ch < NCHUNK; ++ch) {
        int st = ch % NSTAGE;
        if (ch + 2 < NCHUNK) { load_chunk((ch + 2) % NSTAGE, (ch + 2) * BK); CPA_WAIT(2); }
        else if (ch + 1 < NCHUNK) { CPA_WAIT(1); }
        else { CPA_WAIT(0); }
        __syncthreads();

        uint32_t sb = sbase + st * STAGE_BYTES;
        uint32_t aHiB = sb + OFF_AHI, aLoB = sb + OFF_ALO;
        uint32_t bHiB = sb + OFF_BHI, bLoB = sb + OFF_BLO;

#pragma unroll
        for (int ks = 0; ks < 4; ++ks) {
            uint32_t bh[4][2], bl[4][2];
#pragma unroll
            for (int ni = 0; ni < 4; ++ni) {
                uint32_t rowb = wn * 32 + ni * 8 + (lane & 7);
                uint32_t cb   = ks * 32 + (((lane >> 3) & 1) << 4);
                uint32_t off  = SWZ(rowb * 128 + cb);
                ldmB(bh[ni], bHiB + off);
                ldmB(bl[ni], bLoB + off);
            }
#pragma unroll
            for (int mi = 0; mi < 4; ++mi) {
                uint32_t rowa = wm * 64 + mi * 16 + (lane & 15);
                uint32_t ca   = ks * 32 + ((lane >> 4) << 4);
                uint32_t off  = SWZ(rowa * 128 + ca);
                uint32_t ah[4], al[4];
                ldmA(ah, aHiB + off);
                ldmA(al, aLoB + off);
#pragma unroll
                for (int ni = 0; ni < 4; ++ni) {
                    mma16816(c[mi][ni], ah, bh[ni]);
                    mma16816(c[mi][ni], ah, bl[ni]);
                    mma16816(c[mi][ni], al, bh[ni]);
                }
            }
        }
        __syncthreads();
    }

    const int r  = lane >> 2;
    const int q2 = (lane & 3) << 1;
#pragma unroll
    for (int mi = 0; mi < 4; ++mi) {
        int m = m0 + wm * 64 + mi * 16 + r;
        float b0v = bias[m];
        float b1v = bias[m + 8];
#pragma unroll
        for (int ni = 0; ni < 4; ++ni) {
            int n = n0 + wn * 32 + ni * 8 + q2;
            if (!TRANS_OUT) {
                float* p = out + ((size_t)(b * DMODEL + m) << 12) + n;
                *(float2*)p = make_float2(c[mi][ni][0] + b0v, c[mi][ni][1] + b0v);
                float* p2 = p + (8 << 12);
                *(float2*)p2 = make_float2(c[mi][ni][2] + b1v, c[mi][ni][3] + b1v);
            } else {
                float* p = out + (((size_t)b * LSEQ + n) << 9) + m;
                p[0]       = c[mi][ni][0] + b0v;
                p[8]       = c[mi][ni][2] + b1v;
                p[512]     = c[mi][ni][1] + b0v;
                p[512 + 8] = c[mi][ni][3] + b1v;
            }
        }
    }
}

struct QKVPtrs {
    const __nv_bfloat16* whi[3];
    const __nv_bfloat16* wlo[3];
    const float* bias[3];
    float* out[3];
};

__global__ __launch_bounds__(256, 1)
void gemm_qkv_kernel(QKVPtrs p, const __nv_bfloat16* __restrict__ Bhi,
                     const __nv_bfloat16* __restrict__ Blo)
{
    extern __shared__ char dsm[];
    int z = blockIdx.z;
    int w = z >> 3;           // which projection
    int b = z & 7;
    gemm_body<false>(p.whi[w], p.wlo[w], Bhi, Blo, p.bias[w], p.out[w],
                     dsm, b, blockIdx.y * BM, blockIdx.x * BN);
}

__global__ __launch_bounds__(256, 1)
void gemm_o_kernel(const __nv_bfloat16* __restrict__ Ahi, const __nv_bfloat16* __restrict__ Alo,
                   const __nv_bfloat16* __restrict__ Bhi, const __nv_bfloat16* __restrict__ Blo,
                   const float* __restrict__ bias, float* __restrict__ out)
{
    extern __shared__ char dsm[];
    gemm_body<true>(Ahi, Alo, Bhi, Blo, bias, out,
                    dsm, blockIdx.z, blockIdx.y * BM, blockIdx.x * BN);
}

// ====================== fp32 -> bf16 hi/lo converts ======================
__global__ void convert_x_kernel(const float* __restrict__ x)
{
    int i = blockIdx.x * blockDim.x + threadIdx.x;
    float4 v = ((const float4*)x)[i];
    float f[4] = {v.x, v.y, v.z, v.w};
    __nv_bfloat16 h[4], l[4];
#pragma unroll
    for (int j = 0; j < 4; ++j) {
        h[j] = __float2bfloat16(f[j]);
        l[j] = __float2bfloat16(f[j] - __bfloat162float(h[j]));
    }
    __nv_bfloat162 h01, h23, l01, l23;
    h01.x = h[0]; h01.y = h[1]; h23.x = h[2]; h23.y = h[3];
    l01.x = l[0]; l01.y = l[1]; l23.x = l[2]; l23.y = l[3];
    ((__nv_bfloat162*)g_xhi)[2 * i]     = h01;
    ((__nv_bfloat162*)g_xhi)[2 * i + 1] = h23;
    ((__nv_bfloat162*)g_xlo)[2 * i]     = l01;
    ((__nv_bfloat162*)g_xlo)[2 * i + 1] = l23;
}

__global__ void convert_w_kernel(const float* __restrict__ w0, const float* __restrict__ w1,
                                 const float* __restrict__ w2, const float* __restrict__ w3)
{
    int wi = blockIdx.y;
    const float* w = (wi == 0) ? w0 : (wi == 1) ? w1 : (wi == 2) ? w2 : w3;
    int i = blockIdx.x * blockDim.x + threadIdx.x;
    float4 v = ((const float4*)w)[i];
    float f[4] = {v.x, v.y, v.z, v.w};
#pragma unroll
    for (int j = 0; j < 4; ++j) {
        __nv_bfloat16 h = __float2bfloat16(f[j]);
        __nv_bfloat16 l = __float2bfloat16(f[j] - __bfloat162float(h));
        g_whi[(size_t)wi * WSZ + i * 4 + j] = h;
        g_wlo[(size_t)wi * WSZ + i * 4 + j] = l;
    }
}

// ====================== radix-4 FFT machinery ======================
__device__ __forceinline__ int rev4_12(unsigned i) {
    unsigned r = __brev(i) >> 20;                  // 12-bit bit-reversal
    return (int)(((r & 0x555u) << 1) | ((r >> 1) & 0x555u));  // swap bit pairs -> base-4 digit reversal
}
__device__ __forceinline__ float2 cmul(float2 a, float2 b) {
    return make_float2(a.x * b.x - a.y * b.y, a.x * b.y + a.y * b.x);
}

// In-place 4096-pt FFT, input in base-4 digit-reversed order, natural output.
// tw[j] = exp(-+2*pi*i*j/4096), j < 1024 (sign per direction). 1024 threads.
template<bool INV>
__device__ __forceinline__ void fft4096_r4(float2* buf, const float2* tw, int tid)
{
#pragma unroll
    for (int s = 0; s < 6; ++s) {
        const int Q = 1 << (2 * s);
        int pos = tid & (Q - 1);
        int i0  = ((tid >> (2 * s)) << (2 * s + 2)) + pos;
        float2 w1 = tw[pos << (10 - 2 * s)];
        float2 w2 = cmul(w1, w1);
        float2 w3 = cmul(w2, w1);
        float2 a  = buf[i0];
        float2 bb = cmul(buf[i0 + Q], w1);
        float2 cc = cmul(buf[i0 + 2 * Q], w2);
        float2 dd = cmul(buf[i0 + 3 * Q], w3);
        float2 s0 = make_float2(a.x + cc.x, a.y + cc.y);
        float2 s1 = make_float2(a.x - cc.x, a.y - cc.y);
        float2 s2 = make_float2(bb.x + dd.x, bb.y + dd.y);
        float2 s3 = make_float2(bb.x - dd.x, bb.y - dd.y);
        float2 j3 = INV ? make_float2(-s3.y, s3.x) : make_float2(s3.y, -s3.x);
        buf[i0]         = make_float2(s0.x + s2.x, s0.y + s2.y);
        buf[i0 + Q]     = make_float2(s1.x + j3.x, s1.y + j3.y);
        buf[i0 + 2 * Q] = make_float2(s0.x - s2.x, s0.y - s2.y);
        buf[i0 + 3 * Q] = make_float2(s1.x - j3.x, s1.y - j3.y);
        __syncthreads();
    }
}

#define FFT_DSMEM ((4096 + 1024) * 8)   // 40960 bytes

// Forward FFT of z = q + i*k per channel, accumulate Qf*conj(Kf) over 8 channels.
__global__ void fftcorr_kernel()
{
    extern __shared__ float2 sm[];
    float2* buf = sm;
    float2* tw  = sm + 4096;

    const int tid = threadIdx.x;
    const int g = blockIdx.x, b = blockIdx.y;

    {
        float s, c;
        sincosf(6.283185307179586f * (float)tid / 4096.0f, &s, &c);
        tw[tid] = make_float2(c, -s);
    }

    float2 acc[4] = {{0,0},{0,0},{0,0},{0,0}};

    for (int cc = 0; cc < 8; ++cc) {
        int ch = g * 8 + cc;
        const float* qp = g_q + (((size_t)b * DMODEL + ch) << 12);
        const float* kp = g_k + (((size_t)b * DMODEL + ch) << 12);

        __syncthreads();
#pragma unroll
        for (int it = 0; it < 4; ++it) {
            int i = tid + it * 1024;
            buf[rev4_12((unsigned)i)] = make_float2(qp[i], kp[i]);
        }
        __syncthreads();

        fft4096_r4<false>(buf, tw, tid);

#pragma unroll
        for (int it = 0; it < 4; ++it) {
            int f = tid + it * 1024;
            float2 Zf = buf[f];
            float2 Zm = buf[(4096 - f) & 4095];
            float2 Q  = make_float2(0.5f * (Zf.x + Zm.x), 0.5f * (Zf.y - Zm.y));
            float dx = Zf.x - Zm.x, dy = Zf.y + Zm.y;
            float2 Kc = make_float2(0.5f * dy, -0.5f * dx);
            acc[it].x += Q.x * Kc.x + Q.y * Kc.y;
            acc[it].y += Q.y * Kc.x - Q.x * Kc.y;
        }
    }
#pragma unroll
    for (int it = 0; it < 4; ++it) {
        int f = tid + it * 1024;
        g_spart[(((size_t)b * NGRP + g) << 12) + f] = acc[it];
    }
}

// Parallel reduction over NGRP channel-group partials.
__global__ void reduce_kernel()
{
    const int f = blockIdx.x * 512 + threadIdx.x;
    const int b = blockIdx.y;
    const float2* sp = g_spart + (((size_t)b * NGRP) << 12) + f;
    float2 s = make_float2(0.f, 0.f);
#pragma unroll 8
    for (int gp = 0; gp < NGRP; ++gp) {
        float2 v = sp[(size_t)gp << 12];
        s.x += v.x; s.y += v.y;
    }
    g_sred[((size_t)b << 12) + f] = s;
}

// Inverse FFT of reduced spectrum -> mean_corr.
__global__ void ifft_kernel()
{
    extern __shared__ float2 sm[];
    float2* buf = sm;
    float2* tw  = sm + 4096;

    const int tid = threadIdx.x;
    const int b = blockIdx.x;

    {
        float s, c;
        sincosf(6.283185307179586f * (float)tid / 4096.0f, &s, &c);
        tw[tid] = make_float2(c, s);
    }
    __syncthreads();

#pragma unroll
    for (int it = 0; it < 4; ++it) {
        int f = tid + it * 1024;
        buf[rev4_12((unsigned)f)] = g_sred[((size_t)b << 12) + f];
    }
    __syncthreads();

    fft4096_r4<true>(buf, tw, tid);

    const float scale = 1.0f / (4096.0f * 512.0f);
#pragma unroll
    for (int it = 0; it < 4; ++it) {
        int tau = tid + it * 1024;
        g_mcorr[b * LSEQ + tau] = buf[tau].x * scale;
    }
}

// ====================== top-k + softmax ======================
__global__ void topk_kernel()
{
    __shared__ float sval[LSEQ];
    __shared__ float rv[256];
    __shared__ int   ri[256];
    __shared__ float wv[TOPK];
    __shared__ int   wi[TOPK];

    const int tid = threadIdx.x;
    const int b = blockIdx.x;

    for (int i = tid; i < LSEQ; i += 256) sval[i] = g_mcorr[b * LSEQ + i];
    __syncthreads();

    for (int r = 0; r < TOPK; ++r) {
        float best = -FLT_MAX;
        int bi = 0x7fffffff;
        for (int i = tid; i < LSEQ; i += 256) {
            float v = sval[i];
            if (v > best) { best = v; bi = i; }
        }
        rv[tid] = best; ri[tid] = bi;
        __syncthreads();
        for (int s = 128; s > 0; s >>= 1) {
            if (tid < s) {
                if (rv[tid + s] > rv[tid] ||
                    (rv[tid + s] == rv[tid] && ri[tid + s] < ri[tid])) {
                    rv[tid] = rv[tid + s]; ri[tid] = ri[tid + s];
                }
            }
            __syncthreads();
        }
        if (tid == 0) { wv[r] = rv[0]; wi[r] = ri[0]; sval[ri[0]] = -FLT_MAX; }
        __syncthreads();
    }

    if (tid == 0) {
        float mx = wv[0];
        float e[TOPK], sum = 0.f;
#pragma unroll
        for (int i = 0; i < TOPK; ++i) { e[i] = expf(wv[i] - mx); sum += e[i]; }
        float inv = 1.0f / sum;
#pragma unroll
        for (int i = 0; i < TOPK; ++i) {
            g_weights[b * TOPK + i] = e[i] * inv;
            g_delays [b * TOPK + i] = wi[i];
        }
    }
}

// ====================== gather + transpose + bf16 split ======================
__global__ void gather_kernel()
{
    __shared__ float ws[TOPK];
    __shared__ int   ds[TOPK];
    __shared__ float tile[32][33];

    const int tx = threadIdx.x;
    const int ty = threadIdx.y;
    const int tid = ty * 32 + tx;
    const int b  = blockIdx.z;
    const int c0 = blockIdx.y * 32;
    const int l0 = blockIdx.x * 32;

    if (tid < TOPK) {
        ws[tid] = g_weights[b * TOPK + tid];
        ds[tid] = g_delays [b * TOPK + tid];
    }
    __syncthreads();

    const int l = l0 + tx;
#pragma unroll
    for (int i = 0; i < 4; ++i) {
        int c = c0 + ty + i * 8;
        const float* vp = g_v + (((size_t)b * DMODEL + c) << 12);
        float acc = 0.f;
#pragma unroll
        for (int j = 0; j < TOPK; ++j)
            acc += ws[j] * vp[(l + ds[j]) & (LSEQ - 1)];
        tile[ty + i * 8][tx] = acc;
    }
    __syncthreads();

#pragma unroll
    for (int i = 0; i < 4; ++i) {
        int lr = ty + i * 8;
        float v = tile[tx][lr];
        __nv_bfloat16 h = __float2bfloat16(v);
        __nv_bfloat16 lo = __float2bfloat16(v - __bfloat162float(h));
        size_t addr = (((size_t)b * LSEQ + l0 + lr) << 9) + c0 + tx;
        g_athi[addr] = h;
        g_atlo[addr] = lo;
    }
}

// =====================================================================
extern "C" void kernel_launch(void* const* d_in, const int* in_sizes, int n_in,
                              void* d_out, int out_size)
{
    const float* hs = (const float*)d_in[0];
    const float* Wq = (const float*)d_in[1];
    const float* bq = (const float*)d_in[2];
    const float* Wk = (const float*)d_in[3];
    const float* bk = (const float*)d_in[4];
    const float* Wv = (const float*)d_in[5];
    const float* bv = (const float*)d_in[6];
    const float* Wo = (const float*)d_in[7];
    const float* bo = (const float*)d_in[8];
    float* out = (float*)d_out;

    void *pq, *pk, *pv, *pxhi, *pxlo, *pwhi, *pwlo, *pathi, *patlo;
    cudaGetSymbolAddress(&pq,   g_q);
    cudaGetSymbolAddress(&pk,   g_k);
    cudaGetSymbolAddress(&pv,   g_v);
    cudaGetSymbolAddress(&pxhi, g_xhi);
    cudaGetSymbolAddress(&pxlo, g_xlo);
    cudaGetSymbolAddress(&pwhi, g_whi);
    cudaGetSymbolAddress(&pwlo, g_wlo);
    cudaGetSymbolAddress(&pathi, g_athi);
    cudaGetSymbolAddress(&patlo, g_atlo);

    cudaFuncSetAttribute(gemm_qkv_kernel,
                         cudaFuncAttributeMaxDynamicSharedMemorySize, GEMM_DSMEM);
    cudaFuncSetAttribute(gemm_o_kernel,
                         cudaFuncAttributeMaxDynamicSharedMemorySize, GEMM_DSMEM);

    const __nv_bfloat16* whi = (const __nv_bfloat16*)pwhi;
    const __nv_bfloat16* wlo = (const __nv_bfloat16*)pwlo;

    // 1. fp32 -> bf16 hi/lo
    convert_x_kernel<<<(BATCH * LSEQ * DMODEL / 4) / 256, 256>>>(hs);
    convert_w_kernel<<<dim3(WSZ / 4 / 256, 4), 256>>>(Wq, Wk, Wv, Wo);

    // 2. fused Q/K/V projections -> [B, D, L] fp32
    QKVPtrs p;
    p.whi[0] = whi + 0 * WSZ; p.wlo[0] = wlo + 0 * WSZ; p.bias[0] = bq; p.out[0] = (float*)pq;
    p.whi[1] = whi + 1 * WSZ; p.wlo[1] = wlo + 1 * WSZ; p.bias[1] = bk; p.out[1] = (float*)pk;
    p.whi[2] = whi + 2 * WSZ; p.wlo[2] = wlo + 2 * WSZ; p.bias[2] = bv; p.out[2] = (float*)pv;
    dim3 ggq(LSEQ / BN, DMODEL / BM, 3 * BATCH);
    gemm_qkv_kernel<<<ggq, 256, GEMM_DSMEM>>>(p,
        (const __nv_bfloat16*)pxhi, (const __nv_bfloat16*)pxlo);

    // 3. correlation spectrum + reduce + inverse FFT + topk
    fftcorr_kernel<<<dim3(NGRP, BATCH), 1024, FFT_DSMEM>>>();
    reduce_kernel<<<dim3(LSEQ / 512, BATCH), 512>>>();
    ifft_kernel<<<BATCH, 1024, FFT_DSMEM>>>();
    topk_kernel<<<BATCH, 256>>>();

    // 4. gather -> aggT hi/lo [B, L, D]
    gather_kernel<<<dim3(LSEQ / 32, DMODEL / 32, BATCH), dim3(32, 8)>>>();

    // 5. output projection, transposed store -> out [B, L, D]
    dim3 ggo(LSEQ / BN, DMODEL / BM, BATCH);
    gemm_o_kernel<<<ggo, 256, GEMM_DSMEM>>>(whi + 3 * WSZ, wlo + 3 * WSZ,
        (const __nv_bfloat16*)pathi, (const __nv_bfloat16*)patlo, bo, out);
}

// round 8
// speedup vs baseline: 2.6861x; 1.2016x over previous
#include <cuda_runtime.h>
#include <cuda_bf16.h>
#include <math.h>
#include <float.h>
#include <stdint.h>

#define BATCH  8
#define LSEQ   4096
#define DMODEL 512
#define TOPK   8
#define NGRP   64
#define WSZ    (DMODEL * DMODEL)

// ---------------- scratch (static device globals; no allocations) ----------------
__device__ float  g_q  [BATCH * DMODEL * LSEQ];
__device__ float  g_k  [BATCH * DMODEL * LSEQ];
__device__ float  g_v  [BATCH * DMODEL * LSEQ];
__device__ float2 g_spart[BATCH * NGRP * LSEQ];
__device__ float2 g_sred [BATCH * LSEQ];
__device__ float  g_mcorr[BATCH * LSEQ];
__device__ float  g_weights[BATCH * TOPK];
__device__ int    g_delays [BATCH * TOPK];
// bf16 hi/lo operands
__device__ __nv_bfloat16 g_xhi [BATCH * LSEQ * DMODEL];
__device__ __nv_bfloat16 g_xlo [BATCH * LSEQ * DMODEL];
__device__ __nv_bfloat16 g_whi [4 * WSZ];
__device__ __nv_bfloat16 g_wlo [4 * WSZ];
__device__ __nv_bfloat16 g_athi[BATCH * LSEQ * DMODEL];   // aggT [B, L, D]
__device__ __nv_bfloat16 g_atlo[BATCH * LSEQ * DMODEL];

// ====================== helpers ======================
__device__ __forceinline__ uint32_t smem_u32(const void* p) {
    uint32_t a;
    asm("{ .reg .u64 t; cvta.to.shared.u64 t, %1; cvt.u32.u64 %0, t; }" : "=r"(a) : "l"(p));
    return a;
}
#define SWZ(off) ((off) ^ (((off) >> 3) & 0x70))

__device__ __forceinline__ void cpa16(uint32_t dst, const void* src) {
    asm volatile("cp.async.ca.shared.global [%0], [%1], 16;" :: "r"(dst), "l"(src));
}
#define CPA_COMMIT() asm volatile("cp.async.commit_group;" ::: "memory")
#define CPA_WAIT(N)  asm volatile("cp.async.wait_group %0;" :: "n"(N) : "memory")

__device__ __forceinline__ void ldmA(uint32_t* a, uint32_t addr) {
    asm volatile("ldmatrix.sync.aligned.m8n8.x4.shared.b16 {%0,%1,%2,%3}, [%4];"
        : "=r"(a[0]), "=r"(a[1]), "=r"(a[2]), "=r"(a[3]) : "r"(addr));
}
__device__ __forceinline__ void ldmB(uint32_t* b, uint32_t addr) {
    asm volatile("ldmatrix.sync.aligned.m8n8.x2.shared.b16 {%0,%1}, [%2];"
        : "=r"(b[0]), "=r"(b[1]) : "r"(addr));
}
__device__ __forceinline__ void mma16816(float* c, const uint32_t* a, const uint32_t* b) {
    asm volatile("mma.sync.aligned.m16n8k16.row.col.f32.bf16.bf16.f32 "
        "{%0,%1,%2,%3}, {%4,%5,%6,%7}, {%8,%9}, {%0,%1,%2,%3};"
        : "+f"(c[0]), "+f"(c[1]), "+f"(c[2]), "+f"(c[3])
        : "r"(a[0]), "r"(a[1]), "r"(a[2]), "r"(a[3]), "r"(b[0]), "r"(b[1]));
}

// ====================== bf16x3 mma.sync GEMM core ======================
#define BM 128
#define BN 128
#define BK 64
#define NCHUNK (DMODEL / BK)       // 8
#define TSZ     16384
#define OFF_AHI 0
#define OFF_ALO (TSZ)
#define OFF_BHI (2 * TSZ)
#define OFF_BLO (3 * TSZ)
#define STAGE_BYTES (4 * TSZ)              // 65536
#define NSTAGE 3
#define GEMM_DSMEM  (NSTAGE * STAGE_BYTES + 1024)

template<bool TRANS_OUT>
__device__ __forceinline__
void gemm_body(const __nv_bfloat16* __restrict__ Ahi,
               const __nv_bfloat16* __restrict__ Alo,
               const __nv_bfloat16* __restrict__ Bhi,
               const __nv_bfloat16* __restrict__ Blo,
               const float* __restrict__ bias,
               float* __restrict__ out,
               char* dsm, int b, int m0, int n0)
{
    const int tid  = threadIdx.x;
    const int wid  = tid >> 5;
    const int lane = tid & 31;
    const int wm   = wid >> 2;
    const int wn   = wid & 3;

    uint32_t sbase = (smem_u32(dsm) + 1023u) & ~1023u;

    const __nv_bfloat16* aHi = Ahi + (size_t)m0 * DMODEL;
    const __nv_bfloat16* aLo = Alo + (size_t)m0 * DMODEL;
    const __nv_bfloat16* bHi = Bhi + ((size_t)b * LSEQ + n0) * DMODEL;
    const __nv_bfloat16* bLo = Blo + ((size_t)b * LSEQ + n0) * DMODEL;

    auto load_chunk = [&](int st, int k0) {
        uint32_t sb = sbase + st * STAGE_BYTES;
#pragma unroll
        for (int it = 0; it < 4; ++it) {
            int idx = tid + it * 256;
            int row = idx >> 3, q = idx & 7;
            uint32_t sw = SWZ((uint32_t)(row * 128 + q * 16));
            size_t go = (size_t)row * DMODEL + k0 + q * 8;
            cpa16(sb + OFF_AHI + sw, aHi + go);
            cpa16(sb + OFF_ALO + sw, aLo + go);
            cpa16(sb + OFF_BHI + sw, bHi + go);
            cpa16(sb + OFF_BLO + sw, bLo + go);
        }
        CPA_COMMIT();
    };

    float c[4][4][4];
#pragma unroll
    for (int i = 0; i < 4; ++i)
#pragma unroll
        for (int j = 0; j < 4; ++j)
#pragma unroll
            for (int r = 0; r < 4; ++r) c[i][j][r] = 0.f;

    load_chunk(0, 0);
    load_chunk(1, BK);

    for (int ch = 0; ch < NCHUNK; ++ch) {
        int st = ch % NSTAGE;
        if (ch + 2 < NCHUNK) { load_chunk((ch + 2) % NSTAGE, (ch + 2) * BK); CPA_WAIT(2); }
        else if (ch + 1 < NCHUNK) { CPA_WAIT(1); }
        else { CPA_WAIT(0); }
        __syncthreads();

        uint32_t sb = sbase + st * STAGE_BYTES;
        uint32_t aHiB = sb + OFF_AHI, aLoB = sb + OFF_ALO;
        uint32_t bHiB = sb + OFF_BHI, bLoB = sb + OFF_BLO;

#pragma unroll
        for (int ks = 0; ks < 4; ++ks) {
            uint32_t bh[4][2], bl[4][2];
#pragma unroll
            for (int ni = 0; ni < 4; ++ni) {
                uint32_t rowb = wn * 32 + ni * 8 + (lane & 7);
                uint32_t cb   = ks * 32 + (((lane >> 3) & 1) << 4);
                uint32_t off  = SWZ(rowb * 128 + cb);
                ldmB(bh[ni], bHiB + off);
                ldmB(bl[ni], bLoB + off);
            }
#pragma unroll
            for (int mi = 0; mi < 4; ++mi) {
                uint32_t rowa = wm * 64 + mi * 16 + (lane & 15);
                uint32_t ca   = ks * 32 + ((lane >> 4) << 4);
                uint32_t off  = SWZ(rowa * 128 + ca);
                uint32_t ah[4], al[4];
                ldmA(ah, aHiB + off);
                ldmA(al, aLoB + off);
#pragma unroll
                for (int ni = 0; ni < 4; ++ni) {
                    mma16816(c[mi][ni], ah, bh[ni]);
                    mma16816(c[mi][ni], ah, bl[ni]);
                    mma16816(c[mi][ni], al, bh[ni]);
                }
            }
        }
        __syncthreads();
    }

    const int r  = lane >> 2;
    const int q2 = (lane & 3) << 1;
    if (!TRANS_OUT) {
#pragma unroll
        for (int mi = 0; mi < 4; ++mi) {
            int m = m0 + wm * 64 + mi * 16 + r;
            float b0v = bias[m];
            float b1v = bias[m + 8];
#pragma unroll
            for (int ni = 0; ni < 4; ++ni) {
                int n = n0 + wn * 32 + ni * 8 + q2;
                float* p = out + ((size_t)(b * DMODEL + m) << 12) + n;
                *(float2*)p = make_float2(c[mi][ni][0] + b0v, c[mi][ni][1] + b0v);
                float* p2 = p + (8 << 12);
                *(float2*)p2 = make_float2(c[mi][ni][2] + b1v, c[mi][ni][3] + b1v);
            }
        }
    } else {
        // smem transpose: stage accumulators, then coalesced float4 writes along m
        float* tileT = (float*)dsm;   // 128 n-rows x 132 floats
#pragma unroll
        for (int mi = 0; mi < 4; ++mi) {
            int ml = wm * 64 + mi * 16 + r;
#pragma unroll
            for (int ni = 0; ni < 4; ++ni) {
                int nl = wn * 32 + ni * 8 + q2;
                tileT[nl * 132 + ml]           = c[mi][ni][0];
                tileT[(nl + 1) * 132 + ml]     = c[mi][ni][1];
                tileT[nl * 132 + ml + 8]       = c[mi][ni][2];
                tileT[(nl + 1) * 132 + ml + 8] = c[mi][ni][3];
            }
        }
        __syncthreads();
#pragma unroll
        for (int it = 0; it < 16; ++it) {
            int idx = tid + it * 256;
            int nl = idx >> 5;
            int c4 = (idx & 31) << 2;
            float4 v = *(float4*)&tileT[nl * 132 + c4];
            v.x += bias[m0 + c4];
            v.y += bias[m0 + c4 + 1];
            v.z += bias[m0 + c4 + 2];
            v.w += bias[m0 + c4 + 3];
            *(float4*)(out + (((size_t)b * LSEQ + n0 + nl) << 9) + m0 + c4) = v;
        }
    }
}

struct QKVPtrs {
    const __nv_bfloat16* whi[3];
    const __nv_bfloat16* wlo[3];
    const float* bias[3];
    float* out[3];
};

__global__ __launch_bounds__(256, 1)
void gemm_qkv_kernel(QKVPtrs p, const __nv_bfloat16* __restrict__ Bhi,
                     const __nv_bfloat16* __restrict__ Blo)
{
    extern __shared__ char dsm[];
    int z = blockIdx.z;
    int w = z >> 3;
    int b = z & 7;
    gemm_body<false>(p.whi[w], p.wlo[w], Bhi, Blo, p.bias[w], p.out[w],
                     dsm, b, blockIdx.y * BM, blockIdx.x * BN);
}

__global__ __launch_bounds__(256, 1)
void gemm_o_kernel(const __nv_bfloat16* __restrict__ Ahi, const __nv_bfloat16* __restrict__ Alo,
                   const __nv_bfloat16* __restrict__ Bhi, const __nv_bfloat16* __restrict__ Blo,
                   const float* __restrict__ bias, float* __restrict__ out)
{
    extern __shared__ char dsm[];
    gemm_body<true>(Ahi, Alo, Bhi, Blo, bias, out,
                    dsm, blockIdx.z, blockIdx.y * BM, blockIdx.x * BN);
}

// ====================== fp32 -> bf16 hi/lo converts ======================
__global__ void convert_x_kernel(const float* __restrict__ x)
{
    int i = blockIdx.x * blockDim.x + threadIdx.x;
    float4 v = ((const float4*)x)[i];
    float f[4] = {v.x, v.y, v.z, v.w};
    __nv_bfloat16 h[4], l[4];
#pragma unroll
    for (int j = 0; j < 4; ++j) {
        h[j] = __float2bfloat16(f[j]);
        l[j] = __float2bfloat16(f[j] - __bfloat162float(h[j]));
    }
    __nv_bfloat162 h01, h23, l01, l23;
    h01.x = h[0]; h01.y = h[1]; h23.x = h[2]; h23.y = h[3];
    l01.x = l[0]; l01.y = l[1]; l23.x = l[2]; l23.y = l[3];
    ((__nv_bfloat162*)g_xhi)[2 * i]     = h01;
    ((__nv_bfloat162*)g_xhi)[2 * i + 1] = h23;
    ((__nv_bfloat162*)g_xlo)[2 * i]     = l01;
    ((__nv_bfloat162*)g_xlo)[2 * i + 1] = l23;
}

__global__ void convert_w_kernel(const float* __restrict__ w0, const float* __restrict__ w1,
                                 const float* __restrict__ w2, const float* __restrict__ w3)
{
    int wi = blockIdx.y;
    const float* w = (wi == 0) ? w0 : (wi == 1) ? w1 : (wi == 2) ? w2 : w3;
    int i = blockIdx.x * blockDim.x + threadIdx.x;
    float4 v = ((const float4*)w)[i];
    float f[4] = {v.x, v.y, v.z, v.w};
#pragma unroll
    for (int j = 0; j < 4; ++j) {
        __nv_bfloat16 h = __float2bfloat16(f[j]);
        __nv_bfloat16 l = __float2bfloat16(f[j] - __bfloat162float(h));
        g_whi[(size_t)wi * WSZ + i * 4 + j] = h;
        g_wlo[(size_t)wi * WSZ + i * 4 + j] = l;
    }
}

// ====================== radix-16 FFT machinery ======================
// pad: every access pattern (stride 1 / 16 / 256) lands at <=2-way conflicts
#define FPAD(i) ((i) + ((i) >> 4) + ((i) >> 8))
#define FFT_BUF 4368        // >= FPAD(4095)+1

__device__ __forceinline__ float2 cmul(float2 a, float2 b) {
    return make_float2(a.x * b.x - a.y * b.y, a.x * b.y + a.y * b.x);
}
__device__ __forceinline__ int rev16_12(int i) {   // 3-digit base-16 reversal
    return ((i & 15) << 8) | (i & 0xF0) | ((i >> 8) & 15);
}

template<bool INV>
__device__ __forceinline__ void dft4(float2 a, float2 b, float2 c, float2 d,
                                     float2& o0, float2& o1, float2& o2, float2& o3)
{
    float2 e0 = make_float2(a.x + c.x, a.y + c.y);
    float2 e1 = make_float2(a.x - c.x, a.y - c.y);
    float2 e2 = make_float2(b.x + d.x, b.y + d.y);
    float2 e3 = make_float2(b.x - d.x, b.y - d.y);
    o0 = make_float2(e0.x + e2.x, e0.y + e2.y);
    o2 = make_float2(e0.x - e2.x, e0.y - e2.y);
    if (!INV) {
        o1 = make_float2(e1.x + e3.y, e1.y - e3.x);
        o3 = make_float2(e1.x - e3.y, e1.y + e3.x);
    } else {
        o1 = make_float2(e1.x - e3.y, e1.y + e3.x);
        o3 = make_float2(e1.x + e3.y, e1.y - e3.x);
    }
}

template<bool INV>
__device__ __forceinline__ void dft16(float2* x)
{
    const float c1 = 0.92387953251128674f;
    const float s1 = 0.38268343236508978f;
    const float r2 = 0.70710678118654752f;
    const float si = INV ? 1.f : -1.f;
    auto tm = [](float2 v, float wr, float wi) {
        return make_float2(v.x * wr - v.y * wi, v.x * wi + v.y * wr);
    };
    float2 A[16];   // A[u0*4 + t0]
#pragma unroll
    for (int t0 = 0; t0 < 4; ++t0)
        dft4<INV>(x[t0], x[t0 + 4], x[t0 + 8], x[t0 + 12],
                  A[0 + t0], A[4 + t0], A[8 + t0], A[12 + t0]);
    // W16^{u0*t0}
    A[4 + 1]  = tm(A[4 + 1],  c1,  si * s1);
    A[4 + 2]  = tm(A[4 + 2],  r2,  si * r2);
    A[4 + 3]  = tm(A[4 + 3],  s1,  si * c1);
    A[8 + 1]  = tm(A[8 + 1],  r2,  si * r2);
    A[8 + 2]  = tm(A[8 + 2],  0.f, si);
    A[8 + 3]  = tm(A[8 + 3], -r2,  si * r2);
    A[12 + 1] = tm(A[12 + 1], s1,  si * c1);
    A[12 + 2] = tm(A[12 + 2], -r2, si * r2);
    A[12 + 3] = tm(A[12 + 3], -c1, -si * s1);
#pragma unroll
    for (int u0 = 0; u0 < 4; ++u0)
        dft4<INV>(A[u0 * 4], A[u0 * 4 + 1], A[u0 * 4 + 2], A[u0 * 4 + 3],
                  x[u0], x[u0 + 4], x[u0 + 8], x[u0 + 12]);
}

// 4096-pt in-place FFT: input base-16 digit-reversed, natural output. 256 threads.
// tw[j] = exp(-+2*pi*i*j/4096), j < 256.
template<bool INV>
__device__ __forceinline__ void fft4096_r16(float2* buf, const float2* tw, int tid)
{
#pragma unroll
    for (int s = 0; s < 3; ++s) {
        const int Q = 1 << (4 * s);
        int q  = tid & (Q - 1);
        int i0 = ((tid >> (4 * s)) << (4 * s + 4)) + q;
        float2 w1 = tw[q << (8 - 4 * s)];
        float2 x[16];
        x[0] = buf[FPAD(i0)];
        float2 wt = w1;
#pragma unroll
        for (int t = 1; t < 16; ++t) {
            x[t] = cmul(buf[FPAD(i0 + t * Q)], wt);
            wt = cmul(wt, w1);
        }
        dft16<INV>(x);
#pragma unroll
        for (int u = 0; u < 16; ++u) buf[FPAD(i0 + u * Q)] = x[u];
        __syncthreads();
    }
}

// Forward FFT of z = q + i*k per channel, accumulate Qf*conj(Kf) over 8 channels.
__global__ void fftcorr_kernel()
{
    __shared__ float2 buf[FFT_BUF];
    __shared__ float2 tw[256];

    const int tid = threadIdx.x;
    const int g = blockIdx.x, b = blockIdx.y;

    if (tid < 256) {
        float s, c;
        sincosf(6.283185307179586f * (float)tid / 4096.0f, &s, &c);
        tw[tid] = make_float2(c, -s);
    }

    float2 acc[16];
#pragma unroll
    for (int j = 0; j < 16; ++j) acc[j] = make_float2(0.f, 0.f);

    for (int cc = 0; cc < 8; ++cc) {
        int ch = g * 8 + cc;
        const float* qp = g_q + (((size_t)b * DMODEL + ch) << 12);
        const float* kp = g_k + (((size_t)b * DMODEL + ch) << 12);

        __syncthreads();
#pragma unroll
        for (int j = 0; j < 16; ++j) {
            int n = tid + 256 * j;
            buf[FPAD(rev16_12(n))] = make_float2(qp[n], kp[n]);
        }
        __syncthreads();

        fft4096_r16<false>(buf, tw, tid);

#pragma unroll
        for (int j = 0; j < 16; ++j) {
            int f = tid + 256 * j;
            float2 Zf = buf[FPAD(f)];
            float2 Zm = buf[FPAD((4096 - f) & 4095)];
            float2 Q  = make_float2(0.5f * (Zf.x + Zm.x), 0.5f * (Zf.y - Zm.y));
            float dx = Zf.x - Zm.x, dy = Zf.y + Zm.y;
            float2 Kc = make_float2(0.5f * dy, -0.5f * dx);
            acc[j].x += Q.x * Kc.x + Q.y * Kc.y;
            acc[j].y += Q.y * Kc.x - Q.x * Kc.y;
        }
    }
#pragma unroll
    for (int j = 0; j < 16; ++j)
        g_spart[(((size_t)b * NGRP + g) << 12) + tid + 256 * j] = acc[j];
}

// Parallel reduction over NGRP channel-group partials.
__global__ void reduce_kernel()
{
    const int f = blockIdx.x * 512 + threadIdx.x;
    const int b = blockIdx.y;
    const float2* sp = g_spart + (((size_t)b * NGRP) << 12) + f;
    float2 s = make_float2(0.f, 0.f);
#pragma unroll 8
    for (int gp = 0; gp < NGRP; ++gp) {
        float2 v = sp[(size_t)gp << 12];
        s.x += v.x; s.y += v.y;
    }
    g_sred[((size_t)b << 12) + f] = s;
}

// Inverse FFT of reduced spectrum -> mean_corr.
__global__ void ifft_kernel()
{
    __shared__ float2 buf[FFT_BUF];
    __shared__ float2 tw[256];

    const int tid = threadIdx.x;
    const int b = blockIdx.x;

    if (tid < 256) {
        float s, c;
        sincosf(6.283185307179586f * (float)tid / 4096.0f, &s, &c);
        tw[tid] = make_float2(c, s);
    }
    __syncthreads();

#pragma unroll
    for (int j = 0; j < 16; ++j) {
        int f = tid + 256 * j;
        buf[FPAD(rev16_12(f))] = g_sred[((size_t)b << 12) + f];
    }
    __syncthreads();

    fft4096_r16<true>(buf, tw, tid);

    const float scale = 1.0f / (4096.0f * 512.0f);
#pragma unroll
    for (int j = 0; j < 16; ++j) {
        int tau = tid + 256 * j;
        g_mcorr[b * LSEQ + tau] = buf[FPAD(tau)].x * scale;
    }
}

// ====================== top-k + softmax ======================
__global__ void topk_kernel()
{
    __shared__ float sval[LSEQ];
    __shared__ float rv[256];
    __shared__ int   ri[256];
    __shared__ float wv[TOPK];
    __shared__ int   wi[TOPK];

    const int tid = threadIdx.x;
    const int b = blockIdx.x;

    for (int i = tid; i < LSEQ; i += 256) sval[i] = g_mcorr[b * LSEQ + i];
    __syncthreads();

    for (int r = 0; r < TOPK; ++r) {
        float best = -FLT_MAX;
        int bi = 0x7fffffff;
        for (int i = tid; i < LSEQ; i += 256) {
            float v = sval[i];
            if (v > best) { best = v; bi = i; }
        }
        rv[tid] = best; ri[tid] = bi;
        __syncthreads();
        for (int s = 128; s > 0; s >>= 1) {
            if (tid < s) {
                if (rv[tid + s] > rv[tid] ||
                    (rv[tid + s] == rv[tid] && ri[tid + s] < ri[tid])) {
                    rv[tid] = rv[tid + s]; ri[tid] = ri[tid + s];
                }
            }
            __syncthreads();
        }
        if (tid == 0) { wv[r] = rv[0]; wi[r] = ri[0]; sval[ri[0]] = -FLT_MAX; }
        __syncthreads();
    }

    if (tid == 0) {
        float mx = wv[0];
        float e[TOPK], sum = 0.f;
#pragma unroll
        for (int i = 0; i < TOPK; ++i) { e[i] = expf(wv[i] - mx); sum += e[i]; }
        float inv = 1.0f / sum;
#pragma unroll
        for (int i = 0; i < TOPK; ++i) {
            g_weights[b * TOPK + i] = e[i] * inv;
            g_delays [b * TOPK + i] = wi[i];
        }
    }
}

// ====================== gather + transpose + bf16 split ======================
__global__ void gather_kernel()
{
    __shared__ float ws[TOPK];
    __shared__ int   ds[TOPK];
    __shared__ float tile[32][33];

    const int tx = threadIdx.x;
    const int ty = threadIdx.y;
    const int tid = ty * 32 + tx;
    const int b  = blockIdx.z;
    const int c0 = blockIdx.y * 32;
    const int l0 = blockIdx.x * 32;

    if (tid < TOPK) {
        ws[tid] = g_weights[b * TOPK + tid];
        ds[tid] = g_delays [b * TOPK + tid];
    }
    __syncthreads();

    const int l = l0 + tx;
#pragma unroll
    for (int i = 0; i < 4; ++i) {
        int c = c0 + ty + i * 8;
        const float* vp = g_v + (((size_t)b * DMODEL + c) << 12);
        float acc = 0.f;
#pragma unroll
        for (int j = 0; j < TOPK; ++j)
            acc += ws[j] * vp[(l + ds[j]) & (LSEQ - 1)];
        tile[ty + i * 8][tx] = acc;
    }
    __syncthreads();

#pragma unroll
    for (int i = 0; i < 4; ++i) {
        int lr = ty + i * 8;
        float v = tile[tx][lr];
        __nv_bfloat16 h = __float2bfloat16(v);
        __nv_bfloat16 lo = __float2bfloat16(v - __bfloat162float(h));
        size_t addr = (((size_t)b * LSEQ + l0 + lr) << 9) + c0 + tx;
        g_athi[addr] = h;
        g_atlo[addr] = lo;
    }
}

// =====================================================================
extern "C" void kernel_launch(void* const* d_in, const int* in_sizes, int n_in,
                              void* d_out, int out_size)
{
    const float* hs = (const float*)d_in[0];
    const float* Wq = (const float*)d_in[1];
    const float* bq = (const float*)d_in[2];
    const float* Wk = (const float*)d_in[3];
    const float* bk = (const float*)d_in[4];
    const float* Wv = (const float*)d_in[5];
    const float* bv = (const float*)d_in[6];
    const float* Wo = (const float*)d_in[7];
    const float* bo = (const float*)d_in[8];
    float* out = (float*)d_out;

    void *pq, *pk, *pv, *pxhi, *pxlo, *pwhi, *pwlo, *pathi, *patlo;
    cudaGetSymbolAddress(&pq,   g_q);
    cudaGetSymbolAddress(&pk,   g_k);
    cudaGetSymbolAddress(&pv,   g_v);
    cudaGetSymbolAddress(&pxhi, g_xhi);
    cudaGetSymbolAddress(&pxlo, g_xlo);
    cudaGetSymbolAddress(&pwhi, g_whi);
    cudaGetSymbolAddress(&pwlo, g_wlo);
    cudaGetSymbolAddress(&pathi, g_athi);
    cudaGetSymbolAddress(&patlo, g_atlo);

    cudaFuncSetAttribute(gemm_qkv_kernel,
                         cudaFuncAttributeMaxDynamicSharedMemorySize, GEMM_DSMEM);
    cudaFuncSetAttribute(gemm_o_kernel,
                         cudaFuncAttributeMaxDynamicSharedMemorySize, GEMM_DSMEM);

    const __nv_bfloat16* whi = (const __nv_bfloat16*)pwhi;
    const __nv_bfloat16* wlo = (const __nv_bfloat16*)pwlo;

    // 1. fp32 -> bf16 hi/lo
    convert_x_kernel<<<(BATCH * LSEQ * DMODEL / 4) / 256, 256>>>(hs);
    convert_w_kernel<<<dim3(WSZ / 4 / 256, 4), 256>>>(Wq, Wk, Wv, Wo);

    // 2. fused Q/K/V projections -> [B, D, L] fp32
    QKVPtrs p;
    p.whi[0] = whi + 0 * WSZ; p.wlo[0] = wlo + 0 * WSZ; p.bias[0] = bq; p.out[0] = (float*)pq;
    p.whi[1] = whi + 1 * WSZ; p.wlo[1] = wlo + 1 * WSZ; p.bias[1] = bk; p.out[1] = (float*)pk;
    p.whi[2] = whi + 2 * WSZ; p.wlo[2] = wlo + 2 * WSZ; p.bias[2] = bv; p.out[2] = (float*)pv;
    dim3 ggq(LSEQ / BN, DMODEL / BM, 3 * BATCH);
    gemm_qkv_kernel<<<ggq, 256, GEMM_DSMEM>>>(p,
        (const __nv_bfloat16*)pxhi, (const __nv_bfloat16*)pxlo);

    // 3. correlation spectrum (radix-16) + reduce + inverse FFT + topk
    fftcorr_kernel<<<dim3(NGRP, BATCH), 256>>>();
    reduce_kernel<<<dim3(LSEQ / 512, BATCH), 512>>>();
    ifft_kernel<<<BATCH, 256>>>();
    topk_kernel<<<BATCH, 256>>>();

    // 4. gather -> aggT hi/lo [B, L, D]
    gather_kernel<<<dim3(LSEQ / 32, DMODEL / 32, BATCH), dim3(32, 8)>>>();

    // 5. output projection, transposed store -> out [B, L, D]
    dim3 ggo(LSEQ / BN, DMODEL / BM, BATCH);
    gemm_o_kernel<<<ggo, 256, GEMM_DSMEM>>>(whi + 3 * WSZ, wlo + 3 * WSZ,
        (const __nv_bfloat16*)pathi, (const __nv_bfloat16*)patlo, bo, out);
}

// round 11
// speedup vs baseline: 3.2786x; 1.2206x over previous
#include <cuda_runtime.h>
#include <cuda_bf16.h>
#include <math.h>
#include <float.h>
#include <stdint.h>

#define BATCH  8
#define LSEQ   4096
#define DMODEL 512
#define TOPK   8
#define NGRP   64
#define WSZ    (DMODEL * DMODEL)

// ---------------- scratch (static device globals; no allocations) ----------------
__device__ float  g_q  [BATCH * DMODEL * LSEQ];
__device__ float  g_k  [BATCH * DMODEL * LSEQ];
__device__ float2 g_spart[BATCH * NGRP * LSEQ];
__device__ float2 g_sred [BATCH * LSEQ];
__device__ float  g_mcorr[BATCH * LSEQ];
__device__ float  g_weights[BATCH * TOPK];
__device__ int    g_delays [BATCH * TOPK];
__device__ float  g_bov[DMODEL];
// bf16 hi/lo operands (weight slot 2 = Wov)
__device__ __nv_bfloat16 g_xhi [BATCH * LSEQ * DMODEL];
__device__ __nv_bfloat16 g_xlo [BATCH * LSEQ * DMODEL];
__device__ __nv_bfloat16 g_whi [3 * WSZ];
__device__ __nv_bfloat16 g_wlo [3 * WSZ];
__device__ __nv_bfloat16 g_athi[BATCH * LSEQ * DMODEL];   // xagg [B, L, D]
__device__ __nv_bfloat16 g_atlo[BATCH * LSEQ * DMODEL];

// ====================== helpers ======================
__device__ __forceinline__ uint32_t smem_u32(const void* p) {
    uint32_t a;
    asm("{ .reg .u64 t; cvta.to.shared.u64 t, %1; cvt.u32.u64 %0, t; }" : "=r"(a) : "l"(p));
    return a;
}
#define SWZ(off) ((off) ^ (((off) >> 3) & 0x70))

__device__ __forceinline__ void cpa16(uint32_t dst, const void* src) {
    asm volatile("cp.async.ca.shared.global [%0], [%1], 16;" :: "r"(dst), "l"(src));
}
#define CPA_COMMIT() asm volatile("cp.async.commit_group;" ::: "memory")
#define CPA_WAIT(N)  asm volatile("cp.async.wait_group %0;" :: "n"(N) : "memory")

__device__ __forceinline__ void ldmA(uint32_t* a, uint32_t addr) {
    asm volatile("ldmatrix.sync.aligned.m8n8.x4.shared.b16 {%0,%1,%2,%3}, [%4];"
        : "=r"(a[0]), "=r"(a[1]), "=r"(a[2]), "=r"(a[3]) : "r"(addr));
}
__device__ __forceinline__ void ldmB(uint32_t* b, uint32_t addr) {
    asm volatile("ldmatrix.sync.aligned.m8n8.x2.shared.b16 {%0,%1}, [%2];"
        : "=r"(b[0]), "=r"(b[1]) : "r"(addr));
}
__device__ __forceinline__ void mma16816(float* c, const uint32_t* a, const uint32_t* b) {
    asm volatile("mma.sync.aligned.m16n8k16.row.col.f32.bf16.bf16.f32 "
        "{%0,%1,%2,%3}, {%4,%5,%6,%7}, {%8,%9}, {%0,%1,%2,%3};"
        : "+f"(c[0]), "+f"(c[1]), "+f"(c[2]), "+f"(c[3])
        : "r"(a[0]), "r"(a[1]), "r"(a[2]), "r"(a[3]), "r"(b[0]), "r"(b[1]));
}

// ====================== bf16x3 mma.sync GEMM core ======================
#define BM 128
#define BN 128
#define BK 64
#define NCHUNK (DMODEL / BK)       // 8
#define TSZ     16384
#define OFF_AHI 0
#define OFF_ALO (TSZ)
#define OFF_BHI (2 * TSZ)
#define OFF_BLO (3 * TSZ)
#define STAGE_BYTES (4 * TSZ)              // 65536
#define NSTAGE 3
#define GEMM_DSMEM  (NSTAGE * STAGE_BYTES + 1024)

template<bool TRANS_OUT>
__device__ __forceinline__
void gemm_body(const __nv_bfloat16* __restrict__ Ahi,
               const __nv_bfloat16* __restrict__ Alo,
               const __nv_bfloat16* __restrict__ Bhi,
               const __nv_bfloat16* __restrict__ Blo,
               const float* __restrict__ bias,
               float* __restrict__ out,
               char* dsm, int b, int m0, int n0)
{
    const int tid  = threadIdx.x;
    const int wid  = tid >> 5;
    const int lane = tid & 31;
    const int wm   = wid >> 2;
    const int wn   = wid & 3;

    uint32_t sbase = (smem_u32(dsm) + 1023u) & ~1023u;

    const __nv_bfloat16* aHi = Ahi + (size_t)m0 * DMODEL;
    const __nv_bfloat16* aLo = Alo + (size_t)m0 * DMODEL;
    const __nv_bfloat16* bHi = Bhi + ((size_t)b * LSEQ + n0) * DMODEL;
    const __nv_bfloat16* bLo = Blo + ((size_t)b * LSEQ + n0) * DMODEL;

    auto load_chunk = [&](int st, int k0) {
        uint32_t sb = sbase + st * STAGE_BYTES;
#pragma unroll
        for (int it = 0; it < 4; ++it) {
            int idx = tid + it * 256;
            int row = idx >> 3, q = idx & 7;
            uint32_t sw = SWZ((uint32_t)(row * 128 + q * 16));
            size_t go = (size_t)row * DMODEL + k0 + q * 8;
            cpa16(sb + OFF_AHI + sw, aHi + go);
            cpa16(sb + OFF_ALO + sw, aLo + go);
            cpa16(sb + OFF_BHI + sw, bHi + go);
            cpa16(sb + OFF_BLO + sw, bLo + go);
        }
        CPA_COMMIT();
    };

    float c[4][4][4];
#pragma unroll
    for (int i = 0; i < 4; ++i)
#pragma unroll
        for (int j = 0; j < 4; ++j)
#pragma unroll
            for (int r = 0; r < 4; ++r) c[i][j][r] = 0.f;

    load_chunk(0, 0);
    load_chunk(1, BK);

    for (int ch = 0; ch < NCHUNK; ++ch) {
        int st = ch % NSTAGE;
        if (ch + 2 < NCHUNK) { load_chunk((ch + 2) % NSTAGE, (ch + 2) * BK); CPA_WAIT(2); }
        else if (ch + 1 < NCHUNK) { CPA_WAIT(1); }
        else { CPA_WAIT(0); }
        __syncthreads();

        uint32_t sb = sbase + st * STAGE_BYTES;
        uint32_t aHiB = sb + OFF_AHI, aLoB = sb + OFF_ALO;
        uint32_t bHiB = sb + OFF_BHI, bLoB = sb + OFF_BLO;

#pragma unroll
        for (int ks = 0; ks < 4; ++ks) {
            uint32_t bh[4][2], bl[4][2];
#pragma unroll
            for (int ni = 0; ni < 4; ++ni) {
                uint32_t rowb = wn * 32 + ni * 8 + (lane & 7);
                uint32_t cb   = ks * 32 + (((lane >> 3) & 1) << 4);
                uint32_t off  = SWZ(rowb * 128 + cb);
                ldmB(bh[ni], bHiB + off);
                ldmB(bl[ni], bLoB + off);
            }
#pragma unroll
            for (int mi = 0; mi < 4; ++mi) {
                uint32_t rowa = wm * 64 + mi * 16 + (lane & 15);
                uint32_t ca   = ks * 32 + ((lane >> 4) << 4);
                uint32_t off  = SWZ(rowa * 128 + ca);
                uint32_t ah[4], al[4];
                ldmA(ah, aHiB + off);
                ldmA(al, aLoB + off);
#pragma unroll
                for (int ni = 0; ni < 4; ++ni) {
                    mma16816(c[mi][ni], ah, bh[ni]);
                    mma16816(c[mi][ni], ah, bl[ni]);
                    mma16816(c[mi][ni], al, bh[ni]);
                }
            }
        }
        __syncthreads();
    }

    const int r  = lane >> 2;
    const int q2 = (lane & 3) << 1;
    if (!TRANS_OUT) {
#pragma unroll
        for (int mi = 0; mi < 4; ++mi) {
            int m = m0 + wm * 64 + mi * 16 + r;
            float b0v = bias[m];
            float b1v = bias[m + 8];
#pragma unroll
            for (int ni = 0; ni < 4; ++ni) {
                int n = n0 + wn * 32 + ni * 8 + q2;
                float* p = out + ((size_t)(b * DMODEL + m) << 12) + n;
                *(float2*)p = make_float2(c[mi][ni][0] + b0v, c[mi][ni][1] + b0v);
                float* p2 = p + (8 << 12);
                *(float2*)p2 = make_float2(c[mi][ni][2] + b1v, c[mi][ni][3] + b1v);
            }
        }
    } else {
        // smem transpose: stage accumulators, then coalesced float4 writes along m
        float* tileT = (float*)dsm;   // 128 n-rows x 132 floats
#pragma unroll
        for (int mi = 0; mi < 4; ++mi) {
            int ml = wm * 64 + mi * 16 + r;
#pragma unroll
            for (int ni = 0; ni < 4; ++ni) {
                int nl = wn * 32 + ni * 8 + q2;
                tileT[nl * 132 + ml]           = c[mi][ni][0];
                tileT[(nl + 1) * 132 + ml]     = c[mi][ni][1];
                tileT[nl * 132 + ml + 8]       = c[mi][ni][2];
                tileT[(nl + 1) * 132 + ml + 8] = c[mi][ni][3];
            }
        }
        __syncthreads();
#pragma unroll
        for (int it = 0; it < 16; ++it) {
            int idx = tid + it * 256;
            int nl = idx >> 5;
            int c4 = (idx & 31) << 2;
            float4 v = *(float4*)&tileT[nl * 132 + c4];
            v.x += bias[m0 + c4];
            v.y += bias[m0 + c4 + 1];
            v.z += bias[m0 + c4 + 2];
            v.w += bias[m0 + c4 + 3];
            *(float4*)(out + (((size_t)b * LSEQ + n0 + nl) << 9) + m0 + c4) = v;
        }
    }
}

struct QKPtrs {
    const __nv_bfloat16* whi[2];
    const __nv_bfloat16* wlo[2];
    const float* bias[2];
    float* out[2];
};

__global__ __launch_bounds__(256, 1)
void gemm_qk_kernel(QKPtrs p, const __nv_bfloat16* __restrict__ Bhi,
                    const __nv_bfloat16* __restrict__ Blo)
{
    extern __shared__ char dsm[];
    int z = blockIdx.z;
    int w = z >> 3;
    int b = z & 7;
    gemm_body<false>(p.whi[w], p.wlo[w], Bhi, Blo, p.bias[w], p.out[w],
                     dsm, b, blockIdx.y * BM, blockIdx.x * BN);
}

__global__ __launch_bounds__(256, 1)
void gemm_o_kernel(const __nv_bfloat16* __restrict__ Ahi, const __nv_bfloat16* __restrict__ Alo,
                   const __nv_bfloat16* __restrict__ Bhi, const __nv_bfloat16* __restrict__ Blo,
                   const float* __restrict__ bias, float* __restrict__ out)
{
    extern __shared__ char dsm[];
    gemm_body<true>(Ahi, Alo, Bhi, Blo, bias, out,
                    dsm, blockIdx.z, blockIdx.y * BM, blockIdx.x * BN);
}

// ====================== fp32 -> bf16 hi/lo converts ======================
__global__ void convert_x_kernel(const float* __restrict__ x)
{
    int i = blockIdx.x * blockDim.x + threadIdx.x;
    float4 v = ((const float4*)x)[i];
    float f[4] = {v.x, v.y, v.z, v.w};
    __nv_bfloat16 h[4], l[4];
#pragma unroll
    for (int j = 0; j < 4; ++j) {
        h[j] = __float2bfloat16(f[j]);
        l[j] = __float2bfloat16(f[j] - __bfloat162float(h[j]));
    }
    __nv_bfloat162 h01, h23, l01, l23;
    h01.x = h[0]; h01.y = h[1]; h23.x = h[2]; h23.y = h[3];
    l01.x = l[0]; l01.y = l[1]; l23.x = l[2]; l23.y = l[3];
    ((__nv_bfloat162*)g_xhi)[2 * i]     = h01;
    ((__nv_bfloat162*)g_xhi)[2 * i + 1] = h23;
    ((__nv_bfloat162*)g_xlo)[2 * i]     = l01;
    ((__nv_bfloat162*)g_xlo)[2 * i + 1] = l23;
}

__global__ void convert_w_kernel(const float* __restrict__ w0, const float* __restrict__ w1)
{
    int wi = blockIdx.y;
    const float* w = (wi == 0) ? w0 : w1;
    int i = blockIdx.x * blockDim.x + threadIdx.x;
    float4 v = ((const float4*)w)[i];
    float f[4] = {v.x, v.y, v.z, v.w};
#pragma unroll
    for (int j = 0; j < 4; ++j) {
        __nv_bfloat16 h = __float2bfloat16(f[j]);
        __nv_bfloat16 l = __float2bfloat16(f[j] - __bfloat162float(h));
        g_whi[(size_t)wi * WSZ + i * 4 + j] = h;
        g_wlo[(size_t)wi * WSZ + i * 4 + j] = l;
    }
}

// ====================== Wov = Wo @ Wv (fp32) -> bf16 hi/lo slot 2 ======================
__global__ __launch_bounds__(256)
void wov_kernel(const float* __restrict__ Wo, const float* __restrict__ Wv)
{
    __shared__ float As[32][68];   // [c][m]
    __shared__ float Bs[32][68];   // [c][n]
    const int tid = threadIdx.x;
    const int tx = tid & 15, ty = tid >> 4;
    const int m0 = blockIdx.y * 64, n0 = blockIdx.x * 64;

    float c[4][4];
#pragma unroll
    for (int i = 0; i < 4; ++i)
#pragma unroll
        for (int j = 0; j < 4; ++j) c[i][j] = 0.f;

    for (int cc = 0; cc < DMODEL; cc += 32) {
#pragma unroll
        for (int it = 0; it < 2; ++it) {
            int idx = tid + it * 256;           // 0..511
            int m = idx >> 3; int cq = (idx & 7) << 2;
            float4 v = *(const float4*)&Wo[(size_t)(m0 + m) * DMODEL + cc + cq];
            As[cq + 0][m] = v.x; As[cq + 1][m] = v.y;
            As[cq + 2][m] = v.z; As[cq + 3][m] = v.w;
        }
#pragma unroll
        for (int it = 0; it < 2; ++it) {
            int idx = tid + it * 256;
            int c2 = idx >> 4; int nq = (idx & 15) << 2;
            *(float4*)&Bs[c2][nq] = *(const float4*)&Wv[(size_t)(cc + c2) * DMODEL + n0 + nq];
        }
        __syncthreads();
#pragma unroll
        for (int k = 0; k < 32; ++k) {
            float a[4], bb[4];
#pragma unroll
            for (int i = 0; i < 4; ++i) a[i] = As[k][ty * 4 + i];
#pragma unroll
            for (int j = 0; j < 4; ++j) bb[j] = Bs[k][tx * 4 + j];
#pragma unroll
            for (int i = 0; i < 4; ++i)
#pragma unroll
                for (int j = 0; j < 4; ++j) c[i][j] += a[i] * bb[j];
        }
        __syncthreads();
    }

#pragma unroll
    for (int i = 0; i < 4; ++i) {
        int m = m0 + ty * 4 + i;
#pragma unroll
        for (int j = 0; j < 4; ++j) {
            int n = n0 + tx * 4 + j;
            float v = c[i][j];
            __nv_bfloat16 h  = __float2bfloat16(v);
            __nv_bfloat16 lo = __float2bfloat16(v - __bfloat162float(h));
            g_whi[2 * (size_t)WSZ + (size_t)m * DMODEL + n] = h;
            g_wlo[2 * (size_t)WSZ + (size_t)m * DMODEL + n] = lo;
        }
    }
}

// bov[m] = Wo[m,:]·bv + bo[m]
__global__ void bov_kernel(const float* __restrict__ Wo, const float* __restrict__ bv,
                           const float* __restrict__ bo)
{
    int m = blockIdx.x * 8 + (threadIdx.x >> 5);
    int lane = threadIdx.x & 31;
    const float* row = Wo + (size_t)m * DMODEL;
    float s = 0.f;
    for (int c = lane; c < DMODEL; c += 32) s += row[c] * bv[c];
#pragma unroll
    for (int o = 16; o; o >>= 1) s += __shfl_xor_sync(0xffffffffu, s, o);
    if (lane == 0) g_bov[m] = s + bo[m];
}

// ====================== radix-16 FFT machinery ======================
#define FPAD(i) ((i) + ((i) >> 4) + ((i) >> 8))
#define FFT_BUF 4368

__device__ __forceinline__ float2 cmul(float2 a, float2 b) {
    return make_float2(a.x * b.x - a.y * b.y, a.x * b.y + a.y * b.x);
}
__device__ __forceinline__ int rev16_12(int i) {
    return ((i & 15) << 8) | (i & 0xF0) | ((i >> 8) & 15);
}

template<bool INV>
__device__ __forceinline__ void dft4(float2 a, float2 b, float2 c, float2 d,
                                     float2& o0, float2& o1, float2& o2, float2& o3)
{
    float2 e0 = make_float2(a.x + c.x, a.y + c.y);
    float2 e1 = make_float2(a.x - c.x, a.y - c.y);
    float2 e2 = make_float2(b.x + d.x, b.y + d.y);
    float2 e3 = make_float2(b.x - d.x, b.y - d.y);
    o0 = make_float2(e0.x + e2.x, e0.y + e2.y);
    o2 = make_float2(e0.x - e2.x, e0.y - e2.y);
    if (!INV) {
        o1 = make_float2(e1.x + e3.y, e1.y - e3.x);
        o3 = make_float2(e1.x - e3.y, e1.y + e3.x);
    } else {
        o1 = make_float2(e1.x - e3.y, e1.y + e3.x);
        o3 = make_float2(e1.x + e3.y, e1.y - e3.x);
    }
}

template<bool INV>
__device__ __forceinline__ void dft16(float2* x)
{
    const float c1 = 0.92387953251128674f;
    const float s1 = 0.38268343236508978f;
    const float r2 = 0.70710678118654752f;
    const float si = INV ? 1.f : -1.f;
    auto tm = [](float2 v, float wr, float wi) {
        return make_float2(v.x * wr - v.y * wi, v.x * wi + v.y * wr);
    };
    float2 A[16];
#pragma unroll
    for (int t0 = 0; t0 < 4; ++t0)
        dft4<INV>(x[t0], x[t0 + 4], x[t0 + 8], x[t0 + 12],
                  A[0 + t0], A[4 + t0], A[8 + t0], A[12 + t0]);
    A[4 + 1]  = tm(A[4 + 1],  c1,  si * s1);
    A[4 + 2]  = tm(A[4 + 2],  r2,  si * r2);
    A[4 + 3]  = tm(A[4 + 3],  s1,  si * c1);
    A[8 + 1]  = tm(A[8 + 1],  r2,  si * r2);
    A[8 + 2]  = tm(A[8 + 2],  0.f, si);
    A[8 + 3]  = tm(A[8 + 3], -r2,  si * r2);
    A[12 + 1] = tm(A[12 + 1], s1,  si * c1);
    A[12 + 2] = tm(A[12 + 2], -r2, si * r2);
    A[12 + 3] = tm(A[12 + 3], -c1, -si * s1);
#pragma unroll
    for (int u0 = 0; u0 < 4; ++u0)
        dft4<INV>(A[u0 * 4], A[u0 * 4 + 1], A[u0 * 4 + 2], A[u0 * 4 + 3],
                  x[u0], x[u0 + 4], x[u0 + 8], x[u0 + 12]);
}

template<bool INV>
__device__ __forceinline__ void fft4096_r16(float2* buf, const float2* tw, int tid)
{
#pragma unroll
    for (int s = 0; s < 3; ++s) {
        const int Q = 1 << (4 * s);
        int q  = tid & (Q - 1);
        int i0 = ((tid >> (4 * s)) << (4 * s + 4)) + q;
        float2 w1 = tw[q << (8 - 4 * s)];
        float2 x[16];
        x[0] = buf[FPAD(i0)];
        float2 wt = w1;
#pragma unroll
        for (int t = 1; t < 16; ++t) {
            x[t] = cmul(buf[FPAD(i0 + t * Q)], wt);
            wt = cmul(wt, w1);
        }
        dft16<INV>(x);
#pragma unroll
        for (int u = 0; u < 16; ++u) buf[FPAD(i0 + u * Q)] = x[u];
        __syncthreads();
    }
}

__global__ void fftcorr_kernel()
{
    __shared__ float2 buf[FFT_BUF];
    __shared__ float2 tw[256];

    const int tid = threadIdx.x;
    const int g = blockIdx.x, b = blockIdx.y;

    if (tid < 256) {
        float s, c;
        sincosf(6.283185307179586f * (float)tid / 4096.0f, &s, &c);
        tw[tid] = make_float2(c, -s);
    }

    float2 acc[16];
#pragma unroll
    for (int j = 0; j < 16; ++j) acc[j] = make_float2(0.f, 0.f);

    for (int cc = 0; cc < 8; ++cc) {
        int ch = g * 8 + cc;
        const float* qp = g_q + (((size_t)b * DMODEL + ch) << 12);
        const float* kp = g_k + (((size_t)b * DMODEL + ch) << 12);

        __syncthreads();
#pragma unroll
        for (int j = 0; j < 16; ++j) {
            int n = tid + 256 * j;
            buf[FPAD(rev16_12(n))] = make_float2(qp[n], kp[n]);
        }
        __syncthreads();

        fft4096_r16<false>(buf, tw, tid);

#pragma unroll
        for (int j = 0; j < 16; ++j) {
            int f = tid + 256 * j;
            float2 Zf = buf[FPAD(f)];
            float2 Zm = buf[FPAD((4096 - f) & 4095)];
            float2 Q  = make_float2(0.5f * (Zf.x + Zm.x), 0.5f * (Zf.y - Zm.y));
            float dx = Zf.x - Zm.x, dy = Zf.y + Zm.y;
            float2 Kc = make_float2(0.5f * dy, -0.5f * dx);
            acc[j].x += Q.x * Kc.x + Q.y * Kc.y;
            acc[j].y += Q.y * Kc.x - Q.x * Kc.y;
        }
    }
#pragma unroll
    for (int j = 0; j < 16; ++j)
        g_spart[(((size_t)b * NGRP + g) << 12) + tid + 256 * j] = acc[j];
}

__global__ void reduce_kernel()
{
    const int f = blockIdx.x * 512 + threadIdx.x;
    const int b = blockIdx.y;
    const float2* sp = g_spart + (((size_t)b * NGRP) << 12) + f;
    float2 s = make_float2(0.f, 0.f);
#pragma unroll 8
    for (int gp = 0; gp < NGRP; ++gp) {
        float2 v = sp[(size_t)gp << 12];
        s.x += v.x; s.y += v.y;
    }
    g_sred[((size_t)b << 12) + f] = s;
}

__global__ void ifft_kernel()
{
    __shared__ float2 buf[FFT_BUF];
    __shared__ float2 tw[256];

    const int tid = threadIdx.x;
    const int b = blockIdx.x;

    if (tid < 256) {
        float s, c;
        sincosf(6.283185307179586f * (float)tid / 4096.0f, &s, &c);
        tw[tid] = make_float2(c, s);
    }
    __syncthreads();

#pragma unroll
    for (int j = 0; j < 16; ++j) {
        int f = tid + 256 * j;
        buf[FPAD(rev16_12(f))] = g_sred[((size_t)b << 12) + f];
    }
    __syncthreads();

    fft4096_r16<true>(buf, tw, tid);

    const float scale = 1.0f / (4096.0f * 512.0f);
#pragma unroll
    for (int j = 0; j < 16; ++j) {
        int tau = tid + 256 * j;
        g_mcorr[b * LSEQ + tau] = buf[FPAD(tau)].x * scale;
    }
}

// ====================== top-k + softmax ======================
__global__ void topk_kernel()
{
    __shared__ float sval[LSEQ];
    __shared__ float rv[256];
    __shared__ int   ri[256];
    __shared__ float wv[TOPK];
    __shared__ int   wi[TOPK];

    const int tid = threadIdx.x;
    const int b = blockIdx.x;

    for (int i = tid; i < LSEQ; i += 256) sval[i] = g_mcorr[b * LSEQ + i];
    __syncthreads();

    for (int r = 0; r < TOPK; ++r) {
        float best = -FLT_MAX;
        int bi = 0x7fffffff;
        for (int i = tid; i < LSEQ; i += 256) {
            float v = sval[i];
            if (v > best) { best = v; bi = i; }
        }
        rv[tid] = best; ri[tid] = bi;
        __syncthreads();
        for (int s = 128; s > 0; s >>= 1) {
            if (tid < s) {
                if (rv[tid + s] > rv[tid] ||
                    (rv[tid + s] == rv[tid] && ri[tid + s] < ri[tid])) {
                    rv[tid] = rv[tid + s]; ri[tid] = ri[tid + s];
                }
            }
            __syncthreads();
        }
        if (tid == 0) { wv[r] = rv[0]; wi[r] = ri[0]; sval[ri[0]] = -FLT_MAX; }
        __syncthreads();
    }

    if (tid == 0) {
        float mx = wv[0];
        float e[TOPK], sum = 0.f;
#pragma unroll
        for (int i = 0; i < TOPK; ++i) { e[i] = expf(wv[i] - mx); sum += e[i]; }
        float inv = 1.0f / sum;
#pragma unroll
        for (int i = 0; i < TOPK; ++i) {
            g_weights[b * TOPK + i] = e[i] * inv;
            g_delays [b * TOPK + i] = wi[i];
        }
    }
}

// ====================== gather on hidden_states (natural [B,L,D]) ======================
// xagg[b,l,:] = sum_i w[b,i] * hs[b, (l+delay[b,i]) % L, :]  -> bf16 hi/lo
__global__ __launch_bounds__(128)
void gatherx_kernel(const float* __restrict__ hs)
{
    __shared__ float ws[TOPK];
    __shared__ int   ds[TOPK];
    const int tid = threadIdx.x;   // 128 = one float4 per thread over D
    const int l = blockIdx.x, b = blockIdx.y;

    if (tid < TOPK) {
        ws[tid] = g_weights[b * TOPK + tid];
        ds[tid] = g_delays [b * TOPK + tid];
    }
    __syncthreads();

    const float4* xb = (const float4*)(hs + (((size_t)b * LSEQ) << 9));
    float4 acc = make_float4(0.f, 0.f, 0.f, 0.f);
#pragma unroll
    for (int i = 0; i < TOPK; ++i) {
        int t = (l + ds[i]) & (LSEQ - 1);
        float4 v = xb[t * 128 + tid];
        float w = ws[i];
        acc.x += w * v.x; acc.y += w * v.y; acc.z += w * v.z; acc.w += w * v.w;
    }

    float f[4] = {acc.x, acc.y, acc.z, acc.w};
    __nv_bfloat16 h[4], lo[4];
#pragma unroll
    for (int j = 0; j < 4; ++j) {
        h[j]  = __float2bfloat16(f[j]);
        lo[j] = __float2bfloat16(f[j] - __bfloat162float(h[j]));
    }
    size_t base = (((size_t)b * LSEQ + l) << 9) + tid * 4;
    __nv_bfloat162 h01, h23, l01, l23;
    h01.x = h[0];  h01.y = h[1];  h23.x = h[2];  h23.y = h[3];
    l01.x = lo[0]; l01.y = lo[1]; l23.x = lo[2]; l23.y = lo[3];
    *(__nv_bfloat162*)(g_athi + base)     = h01;
    *(__nv_bfloat162*)(g_athi + base + 2) = h23;
    *(__nv_bfloat162*)(g_atlo + base)     = l01;
    *(__nv_bfloat162*)(g_atlo + base + 2) = l23;
}

// =====================================================================
extern "C" void kernel_launch(void* const* d_in, const int* in_sizes, int n_in,
                              void* d_out, int out_size)
{
    const float* hs = (const float*)d_in[0];
    const float* Wq = (const float*)d_in[1];
    const float* bq = (const float*)d_in[2];
    const float* Wk = (const float*)d_in[3];
    const float* bk = (const float*)d_in[4];
    const float* Wv = (const float*)d_in[5];
    const float* bv = (const float*)d_in[6];
    const float* Wo = (const float*)d_in[7];
    const float* bo = (const float*)d_in[8];
    float* out = (float*)d_out;

    void *pq, *pk, *pxhi, *pxlo, *pwhi, *pwlo, *pathi, *patlo, *pbov;
    cudaGetSymbolAddress(&pq,   g_q);
    cudaGetSymbolAddress(&pk,   g_k);
    cudaGetSymbolAddress(&pxhi, g_xhi);
    cudaGetSymbolAddress(&pxlo, g_xlo);
    cudaGetSymbolAddress(&pwhi, g_whi);
    cudaGetSymbolAddress(&pwlo, g_wlo);
    cudaGetSymbolAddress(&pathi, g_athi);
    cudaGetSymbolAddress(&patlo, g_atlo);
    cudaGetSymbolAddress(&pbov, g_bov);

    cudaFuncSetAttribute(gemm_qk_kernel,
                         cudaFuncAttributeMaxDynamicSharedMemorySize, GEMM_DSMEM);
    cudaFuncSetAttribute(gemm_o_kernel,
                         cudaFuncAttributeMaxDynamicSharedMemorySize, GEMM_DSMEM);

    const __nv_bfloat16* whi = (const __nv_bfloat16*)pwhi;
    const __nv_bfloat16* wlo = (const __nv_bfloat16*)pwlo;

    // 1. fp32 -> bf16 hi/lo; fold Wo@Wv and Wo·bv+bo
    convert_x_kernel<<<(BATCH * LSEQ * DMODEL / 4) / 256, 256>>>(hs);
    convert_w_kernel<<<dim3(WSZ / 4 / 256, 2), 256>>>(Wq, Wk);
    wov_kernel<<<dim3(8, 8), 256>>>(Wo, Wv);
    bov_kernel<<<64, 256>>>(Wo, bv, bo);

    // 2. fused Q/K projections -> [B, D, L] fp32
    QKPtrs p;
    p.whi[0] = whi + 0 * WSZ; p.wlo[0] = wlo + 0 * WSZ; p.bias[0] = bq; p.out[0] = (float*)pq;
    p.whi[1] = whi + 1 * WSZ; p.wlo[1] = wlo + 1 * WSZ; p.bias[1] = bk; p.out[1] = (float*)pk;
    dim3 ggq(LSEQ / BN, DMODEL / BM, 2 * BATCH);
    gemm_qk_kernel<<<ggq, 256, GEMM_DSMEM>>>(p,
        (const __nv_bfloat16*)pxhi, (const __nv_bfloat16*)pxlo);

    // 3. correlation spectrum (radix-16) + reduce + inverse FFT + topk
    fftcorr_kernel<<<dim3(NGRP, BATCH), 256>>>();
    reduce_kernel<<<dim3(LSEQ / 512, BATCH), 512>>>();
    ifft_kernel<<<BATCH, 256>>>();
    topk_kernel<<<BATCH, 256>>>();

    // 4. gather directly on hidden_states -> xagg bf16 hi/lo [B, L, D]
    gatherx_kernel<<<dim3(LSEQ, BATCH), 128>>>(hs);

    // 5. fused output projection: out = xagg @ Wov^T + bov  (transposed store)
    dim3 ggo(LSEQ / BN, DMODEL / BM, BATCH);
    gemm_o_kernel<<<ggo, 256, GEMM_DSMEM>>>(whi + 2 * WSZ, wlo + 2 * WSZ,
        (const __nv_bfloat16*)pathi, (const __nv_bfloat16*)patlo,
        (const float*)pbov, out);
}

// round 13
// speedup vs baseline: 3.3566x; 1.0238x over previous
#include <cuda_runtime.h>
#include <cuda_bf16.h>
#include <math.h>
#include <float.h>
#include <stdint.h>

#define BATCH  8
#define LSEQ   4096
#define DMODEL 512
#define TOPK   8
#define NGRP   64
#define WSZ    (DMODEL * DMODEL)

// ---------------- scratch (static device globals; no allocations) ----------------
__device__ float  g_q  [BATCH * DMODEL * LSEQ];
__device__ float  g_k  [BATCH * DMODEL * LSEQ];
__device__ float2 g_spart[BATCH * NGRP * LSEQ];
__device__ float2 g_sred [BATCH * LSEQ];
__device__ float  g_weights[BATCH * TOPK];
__device__ int    g_delays [BATCH * TOPK];
__device__ float  g_bov[DMODEL];
// bf16 hi/lo operands (weight slot 2 = Wov)
__device__ __nv_bfloat16 g_xhi [BATCH * LSEQ * DMODEL];
__device__ __nv_bfloat16 g_xlo [BATCH * LSEQ * DMODEL];
__device__ __nv_bfloat16 g_whi [3 * WSZ];
__device__ __nv_bfloat16 g_wlo [3 * WSZ];
__device__ __nv_bfloat16 g_athi[BATCH * LSEQ * DMODEL];   // xagg [B, L, D]
__device__ __nv_bfloat16 g_atlo[BATCH * LSEQ * DMODEL];

// ====================== helpers ======================
__device__ __forceinline__ uint32_t smem_u32(const void* p) {
    uint32_t a;
    asm("{ .reg .u64 t; cvta.to.shared.u64 t, %1; cvt.u32.u64 %0, t; }" : "=r"(a) : "l"(p));
    return a;
}
#define SWZ(off) ((off) ^ (((off) >> 3) & 0x70))

__device__ __forceinline__ void cpa16(uint32_t dst, const void* src) {
    asm volatile("cp.async.ca.shared.global [%0], [%1], 16;" :: "r"(dst), "l"(src));
}
#define CPA_COMMIT() asm volatile("cp.async.commit_group;" ::: "memory")
#define CPA_WAIT(N)  asm volatile("cp.async.wait_group %0;" :: "n"(N) : "memory")

__device__ __forceinline__ void ldmA(uint32_t* a, uint32_t addr) {
    asm volatile("ldmatrix.sync.aligned.m8n8.x4.shared.b16 {%0,%1,%2,%3}, [%4];"
        : "=r"(a[0]), "=r"(a[1]), "=r"(a[2]), "=r"(a[3]) : "r"(addr));
}
__device__ __forceinline__ void ldmB(uint32_t* b, uint32_t addr) {
    asm volatile("ldmatrix.sync.aligned.m8n8.x2.shared.b16 {%0,%1}, [%2];"
        : "=r"(b[0]), "=r"(b[1]) : "r"(addr));
}
__device__ __forceinline__ void mma16816(float* c, const uint32_t* a, const uint32_t* b) {
    asm volatile("mma.sync.aligned.m16n8k16.row.col.f32.bf16.bf16.f32 "
        "{%0,%1,%2,%3}, {%4,%5,%6,%7}, {%8,%9}, {%0,%1,%2,%3};"
        : "+f"(c[0]), "+f"(c[1]), "+f"(c[2]), "+f"(c[3])
        : "r"(a[0]), "r"(a[1]), "r"(a[2]), "r"(a[3]), "r"(b[0]), "r"(b[1]));
}

// ====================== bf16x3 mma.sync GEMM core ======================
#define BM 128
#define BN 128
#define BK 64
#define NCHUNK (DMODEL / BK)       // 8
#define TSZ     16384
#define OFF_AHI 0
#define OFF_ALO (TSZ)
#define OFF_BHI (2 * TSZ)
#define OFF_BLO (3 * TSZ)
#define STAGE_BYTES (4 * TSZ)              // 65536
#define NSTAGE 3
#define GEMM_DSMEM  (NSTAGE * STAGE_BYTES + 1024)

template<bool TRANS_OUT>
__device__ __forceinline__
void gemm_body(const __nv_bfloat16* __restrict__ Ahi,
               const __nv_bfloat16* __restrict__ Alo,
               const __nv_bfloat16* __restrict__ Bhi,
               const __nv_bfloat16* __restrict__ Blo,
               const float* __restrict__ bias,
               float* __restrict__ out,
               char* dsm, int b, int m0, int n0)
{
    const int tid  = threadIdx.x;
    const int wid  = tid >> 5;
    const int lane = tid & 31;
    const int wm   = wid >> 2;
    const int wn   = wid & 3;

    uint32_t sbase = (smem_u32(dsm) + 1023u) & ~1023u;

    const __nv_bfloat16* aHi = Ahi + (size_t)m0 * DMODEL;
    const __nv_bfloat16* aLo = Alo + (size_t)m0 * DMODEL;
    const __nv_bfloat16* bHi = Bhi + ((size_t)b * LSEQ + n0) * DMODEL;
    const __nv_bfloat16* bLo = Blo + ((size_t)b * LSEQ + n0) * DMODEL;

    auto load_chunk = [&](int st, int k0) {
        uint32_t sb = sbase + st * STAGE_BYTES;
#pragma unroll
        for (int it = 0; it < 4; ++it) {
            int idx = tid + it * 256;
            int row = idx >> 3, q = idx & 7;
            uint32_t sw = SWZ((uint32_t)(row * 128 + q * 16));
            size_t go = (size_t)row * DMODEL + k0 + q * 8;
            cpa16(sb + OFF_AHI + sw, aHi + go);
            cpa16(sb + OFF_ALO + sw, aLo + go);
            cpa16(sb + OFF_BHI + sw, bHi + go);
            cpa16(sb + OFF_BLO + sw, bLo + go);
        }
        CPA_COMMIT();
    };

    float c[4][4][4];
#pragma unroll
    for (int i = 0; i < 4; ++i)
#pragma unroll
        for (int j = 0; j < 4; ++j)
#pragma unroll
            for (int r = 0; r < 4; ++r) c[i][j][r] = 0.f;

    load_chunk(0, 0);
    load_chunk(1, BK);

    // single-barrier pipeline: loads for ch+2 are issued AFTER the top sync of
    // iter ch, at which point every warp has finished reading stage
    // (ch-1)%3 == (ch+2)%3 — so no trailing barrier is needed.
    for (int ch = 0; ch < NCHUNK; ++ch) {
        int st = ch % NSTAGE;
        if (ch < NCHUNK - 1) { CPA_WAIT(1); }
        else                 { CPA_WAIT(0); }
        __syncthreads();
        if (ch + 2 < NCHUNK) load_chunk((ch + 2) % NSTAGE, (ch + 2) * BK);

        uint32_t sb = sbase + st * STAGE_BYTES;
        uint32_t aHiB = sb + OFF_AHI, aLoB = sb + OFF_ALO;
        uint32_t bHiB = sb + OFF_BHI, bLoB = sb + OFF_BLO;

#pragma unroll
        for (int ks = 0; ks < 4; ++ks) {
            uint32_t bh[4][2], bl[4][2];
#pragma unroll
            for (int ni = 0; ni < 4; ++ni) {
                uint32_t rowb = wn * 32 + ni * 8 + (lane & 7);
                uint32_t cb   = ks * 32 + (((lane >> 3) & 1) << 4);
                uint32_t off  = SWZ(rowb * 128 + cb);
                ldmB(bh[ni], bHiB + off);
                ldmB(bl[ni], bLoB + off);
            }
#pragma unroll
            for (int mi = 0; mi < 4; ++mi) {
                uint32_t rowa = wm * 64 + mi * 16 + (lane & 15);
                uint32_t ca   = ks * 32 + ((lane >> 4) << 4);
                uint32_t off  = SWZ(rowa * 128 + ca);
                uint32_t ah[4], al[4];
                ldmA(ah, aHiB + off);
                ldmA(al, aLoB + off);
#pragma unroll
                for (int ni = 0; ni < 4; ++ni) {
                    mma16816(c[mi][ni], ah, bh[ni]);
                    mma16816(c[mi][ni], ah, bl[ni]);
                    mma16816(c[mi][ni], al, bh[ni]);
                }
            }
        }
    }

    const int r  = lane >> 2;
    const int q2 = (lane & 3) << 1;
    if (!TRANS_OUT) {
#pragma unroll
        for (int mi = 0; mi < 4; ++mi) {
            int m = m0 + wm * 64 + mi * 16 + r;
            float b0v = bias[m];
            float b1v = bias[m + 8];
#pragma unroll
            for (int ni = 0; ni < 4; ++ni) {
                int n = n0 + wn * 32 + ni * 8 + q2;
                float* p = out + ((size_t)(b * DMODEL + m) << 12) + n;
                *(float2*)p = make_float2(c[mi][ni][0] + b0v, c[mi][ni][1] + b0v);
                float* p2 = p + (8 << 12);
                *(float2*)p2 = make_float2(c[mi][ni][2] + b1v, c[mi][ni][3] + b1v);
            }
        }
    } else {
        // smem transpose: stage accumulators, then coalesced float4 writes along m
        float* tileT = (float*)dsm;   // 128 n-rows x 132 floats
        __syncthreads();              // mainloop has no trailing barrier
#pragma unroll
        for (int mi = 0; mi < 4; ++mi) {
            int ml = wm * 64 + mi * 16 + r;
#pragma unroll
            for (int ni = 0; ni < 4; ++ni) {
                int nl = wn * 32 + ni * 8 + q2;
                tileT[nl * 132 + ml]           = c[mi][ni][0];
                tileT[(nl + 1) * 132 + ml]     = c[mi][ni][1];
                tileT[nl * 132 + ml + 8]       = c[mi][ni][2];
                tileT[(nl + 1) * 132 + ml + 8] = c[mi][ni][3];
            }
        }
        __syncthreads();
#pragma unroll
        for (int it = 0; it < 16; ++it) {
            int idx = tid + it * 256;
            int nl = idx >> 5;
            int c4 = (idx & 31) << 2;
            float4 v = *(float4*)&tileT[nl * 132 + c4];
            v.x += bias[m0 + c4];
            v.y += bias[m0 + c4 + 1];
            v.z += bias[m0 + c4 + 2];
            v.w += bias[m0 + c4 + 3];
            *(float4*)(out + (((size_t)b * LSEQ + n0 + nl) << 9) + m0 + c4) = v;
        }
    }
}

struct QKPtrs {
    const __nv_bfloat16* whi[2];
    const __nv_bfloat16* wlo[2];
    const float* bias[2];
    float* out[2];
};

__global__ __launch_bounds__(256, 1)
void gemm_qk_kernel(QKPtrs p, const __nv_bfloat16* __restrict__ Bhi,
                    const __nv_bfloat16* __restrict__ Blo)
{
    extern __shared__ char dsm[];
    int z = blockIdx.z;
    int w = z >> 3;
    int b = z & 7;
    gemm_body<false>(p.whi[w], p.wlo[w], Bhi, Blo, p.bias[w], p.out[w],
                     dsm, b, blockIdx.y * BM, blockIdx.x * BN);
}

__global__ __launch_bounds__(256, 1)
void gemm_o_kernel(const __nv_bfloat16* __restrict__ Ahi, const __nv_bfloat16* __restrict__ Alo,
                   const __nv_bfloat16* __restrict__ Bhi, const __nv_bfloat16* __restrict__ Blo,
                   const float* __restrict__ bias, float* __restrict__ out)
{
    extern __shared__ char dsm[];
    gemm_body<true>(Ahi, Alo, Bhi, Blo, bias, out,
                    dsm, blockIdx.z, blockIdx.y * BM, blockIdx.x * BN);
}

// ====================== fp32 -> bf16 hi/lo converts ======================
__global__ void convert_x_kernel(const float* __restrict__ x)
{
    int i = blockIdx.x * blockDim.x + threadIdx.x;
    float4 v = ((const float4*)x)[i];
    float f[4] = {v.x, v.y, v.z, v.w};
    __nv_bfloat16 h[4], l[4];
#pragma unroll
    for (int j = 0; j < 4; ++j) {
        h[j] = __float2bfloat16(f[j]);
        l[j] = __float2bfloat16(f[j] - __bfloat162float(h[j]));
    }
    __nv_bfloat162 h01, h23, l01, l23;
    h01.x = h[0]; h01.y = h[1]; h23.x = h[2]; h23.y = h[3];
    l01.x = l[0]; l01.y = l[1]; l23.x = l[2]; l23.y = l[3];
    ((__nv_bfloat162*)g_xhi)[2 * i]     = h01;
    ((__nv_bfloat162*)g_xhi)[2 * i + 1] = h23;
    ((__nv_bfloat162*)g_xlo)[2 * i]     = l01;
    ((__nv_bfloat162*)g_xlo)[2 * i + 1] = l23;
}

__global__ void convert_w_kernel(const float* __restrict__ w0, const float* __restrict__ w1)
{
    int wi = blockIdx.y;
    const float* w = (wi == 0) ? w0 : w1;
    int i = blockIdx.x * blockDim.x + threadIdx.x;
    float4 v = ((const float4*)w)[i];
    float f[4] = {v.x, v.y, v.z, v.w};
#pragma unroll
    for (int j = 0; j < 4; ++j) {
        __nv_bfloat16 h = __float2bfloat16(f[j]);
        __nv_bfloat16 l = __float2bfloat16(f[j] - __bfloat162float(h));
        g_whi[(size_t)wi * WSZ + i * 4 + j] = h;
        g_wlo[(size_t)wi * WSZ + i * 4 + j] = l;
    }
}

// ====================== Wov = Wo @ Wv (fp32) -> bf16 hi/lo slot 2; +bov column ======================
__global__ __launch_bounds__(256)
void wov_kernel(const float* __restrict__ Wo, const float* __restrict__ Wv,
                const float* __restrict__ bv, const float* __restrict__ bo)
{
    // grid (9, 8): x<8 -> Wov tile; x==8 -> bov rows [by*64, by*64+64)
    if (blockIdx.x == 8) {
        int w = threadIdx.x >> 5, lane = threadIdx.x & 31;
#pragma unroll
        for (int rr = 0; rr < 8; ++rr) {
            int m = blockIdx.y * 64 + w * 8 + rr;
            const float* row = Wo + (size_t)m * DMODEL;
            float s = 0.f;
            for (int c = lane; c < DMODEL; c += 32) s += row[c] * bv[c];
#pragma unroll
            for (int o = 16; o; o >>= 1) s += __shfl_xor_sync(0xffffffffu, s, o);
            if (lane == 0) g_bov[m] = s + bo[m];
        }
        return;
    }

    __shared__ float As[32][68];   // [c][m]
    __shared__ float Bs[32][68];   // [c][n]
    const int tid = threadIdx.x;
    const int tx = tid & 15, ty = tid >> 4;
    const int m0 = blockIdx.y * 64, n0 = blockIdx.x * 64;

    float c[4][4];
#pragma unroll
    for (int i = 0; i < 4; ++i)
#pragma unroll
        for (int j = 0; j < 4; ++j) c[i][j] = 0.f;

    for (int cc = 0; cc < DMODEL; cc += 32) {
#pragma unroll
        for (int it = 0; it < 2; ++it) {
            int idx = tid + it * 256;
            int m = idx >> 3; int cq = (idx & 7) << 2;
            float4 v = *(const float4*)&Wo[(size_t)(m0 + m) * DMODEL + cc + cq];
            As[cq + 0][m] = v.x; As[cq + 1][m] = v.y;
            As[cq + 2][m] = v.z; As[cq + 3][m] = v.w;
        }
#pragma unroll
        for (int it = 0; it < 2; ++it) {
            int idx = tid + it * 256;
            int c2 = idx >> 4; int nq = (idx & 15) << 2;
            *(float4*)&Bs[c2][nq] = *(const float4*)&Wv[(size_t)(cc + c2) * DMODEL + n0 + nq];
        }
        __syncthreads();
#pragma unroll
        for (int k = 0; k < 32; ++k) {
            float a[4], bb[4];
#pragma unroll
            for (int i = 0; i < 4; ++i) a[i] = As[k][ty * 4 + i];
#pragma unroll
            for (int j = 0; j < 4; ++j) bb[j] = Bs[k][tx * 4 + j];
#pragma unroll
            for (int i = 0; i < 4; ++i)
#pragma unroll
                for (int j = 0; j < 4; ++j) c[i][j] += a[i] * bb[j];
        }
        __syncthreads();
    }

#pragma unroll
    for (int i = 0; i < 4; ++i) {
        int m = m0 + ty * 4 + i;
#pragma unroll
        for (int j = 0; j < 4; ++j) {
            int n = n0 + tx * 4 + j;
            float v = c[i][j];
            __nv_bfloat16 h  = __float2bfloat16(v);
            __nv_bfloat16 lo = __float2bfloat16(v - __bfloat162float(h));
            g_whi[2 * (size_t)WSZ + (size_t)m * DMODEL + n] = h;
            g_wlo[2 * (size_t)WSZ + (size_t)m * DMODEL + n] = lo;
        }
    }
}

// ====================== radix-16 FFT machinery ======================
#define FPAD(i) ((i) + ((i) >> 4) + ((i) >> 8))
#define FFT_BUF 4368

__device__ __forceinline__ float2 cmul(float2 a, float2 b) {
    return make_float2(a.x * b.x - a.y * b.y, a.x * b.y + a.y * b.x);
}
__device__ __forceinline__ int rev16_12(int i) {
    return ((i & 15) << 8) | (i & 0xF0) | ((i >> 8) & 15);
}

template<bool INV>
__device__ __forceinline__ void dft4(float2 a, float2 b, float2 c, float2 d,
                                     float2& o0, float2& o1, float2& o2, float2& o3)
{
    float2 e0 = make_float2(a.x + c.x, a.y + c.y);
    float2 e1 = make_float2(a.x - c.x, a.y - c.y);
    float2 e2 = make_float2(b.x + d.x, b.y + d.y);
    float2 e3 = make_float2(b.x - d.x, b.y - d.y);
    o0 = make_float2(e0.x + e2.x, e0.y + e2.y);
    o2 = make_float2(e0.x - e2.x, e0.y - e2.y);
    if (!INV) {
        o1 = make_float2(e1.x + e3.y, e1.y - e3.x);
        o3 = make_float2(e1.x - e3.y, e1.y + e3.x);
    } else {
        o1 = make_float2(e1.x - e3.y, e1.y + e3.x);
        o3 = make_float2(e1.x + e3.y, e1.y - e3.x);
    }
}

template<bool INV>
__device__ __forceinline__ void dft16(float2* x)
{
    const float c1 = 0.92387953251128674f;
    const float s1 = 0.38268343236508978f;
    const float r2 = 0.70710678118654752f;
    const float si = INV ? 1.f : -1.f;
    auto tm = [](float2 v, float wr, float wi) {
        return make_float2(v.x * wr - v.y * wi, v.x * wi + v.y * wr);
    };
    float2 A[16];
#pragma unroll
    for (int t0 = 0; t0 < 4; ++t0)
        dft4<INV>(x[t0], x[t0 + 4], x[t0 + 8], x[t0 + 12],
                  A[0 + t0], A[4 + t0], A[8 + t0], A[12 + t0]);
    A[4 + 1]  = tm(A[4 + 1],  c1,  si * s1);
    A[4 + 2]  = tm(A[4 + 2],  r2,  si * r2);
    A[4 + 3]  = tm(A[4 + 3],  s1,  si * c1);
    A[8 + 1]  = tm(A[8 + 1],  r2,  si * r2);
    A[8 + 2]  = tm(A[8 + 2],  0.f, si);
    A[8 + 3]  = tm(A[8 + 3], -r2,  si * r2);
    A[12 + 1] = tm(A[12 + 1], s1,  si * c1);
    A[12 + 2] = tm(A[12 + 2], -r2, si * r2);
    A[12 + 3] = tm(A[12 + 3], -c1, -si * s1);
#pragma unroll
    for (int u0 = 0; u0 < 4; ++u0)
        dft4<INV>(A[u0 * 4], A[u0 * 4 + 1], A[u0 * 4 + 2], A[u0 * 4 + 3],
                  x[u0], x[u0 + 4], x[u0 + 8], x[u0 + 12]);
}

template<bool INV>
__device__ __forceinline__ void fft4096_r16(float2* buf, const float2* tw, int tid)
{
#pragma unroll
    for (int s = 0; s < 3; ++s) {
        const int Q = 1 << (4 * s);
        int q  = tid & (Q - 1);
        int i0 = ((tid >> (4 * s)) << (4 * s + 4)) + q;
        float2 w1 = tw[q << (8 - 4 * s)];
        float2 x[16];
        x[0] = buf[FPAD(i0)];
        float2 wt = w1;
#pragma unroll
        for (int t = 1; t < 16; ++t) {
            x[t] = cmul(buf[FPAD(i0 + t * Q)], wt);
            wt = cmul(wt, w1);
        }
        dft16<INV>(x);
#pragma unroll
        for (int u = 0; u < 16; ++u) buf[FPAD(i0 + u * Q)] = x[u];
        __syncthreads();
    }
}

__global__ void fftcorr_kernel()
{
    __shared__ float2 buf[FFT_BUF];
    __shared__ float2 tw[256];

    const int tid = threadIdx.x;
    const int g = blockIdx.x, b = blockIdx.y;

    if (tid < 256) {
        float s, c;
        sincosf(6.283185307179586f * (float)tid / 4096.0f, &s, &c);
        tw[tid] = make_float2(c, -s);
    }

    float2 acc[16];
#pragma unroll
    for (int j = 0; j < 16; ++j) acc[j] = make_float2(0.f, 0.f);

    for (int cc = 0; cc < 8; ++cc) {
        int ch = g * 8 + cc;
        const float* qp = g_q + (((size_t)b * DMODEL + ch) << 12);
        const float* kp = g_k + (((size_t)b * DMODEL + ch) << 12);

        __syncthreads();
#pragma unroll
        for (int j = 0; j < 16; ++j) {
            int n = tid + 256 * j;
            buf[FPAD(rev16_12(n))] = make_float2(qp[n], kp[n]);
        }
        __syncthreads();

        fft4096_r16<false>(buf, tw, tid);

#pragma unroll
        for (int j = 0; j < 16; ++j) {
            int f = tid + 256 * j;
            float2 Zf = buf[FPAD(f)];
            float2 Zm = buf[FPAD((4096 - f) & 4095)];
            float2 Q  = make_float2(0.5f * (Zf.x + Zm.x), 0.5f * (Zf.y - Zm.y));
            float dx = Zf.x - Zm.x, dy = Zf.y + Zm.y;
            float2 Kc = make_float2(0.5f * dy, -0.5f * dx);
            acc[j].x += Q.x * Kc.x + Q.y * Kc.y;
            acc[j].y += Q.y * Kc.x - Q.x * Kc.y;
        }
    }
#pragma unroll
    for (int j = 0; j < 16; ++j)
        g_spart[(((size_t)b * NGRP + g) << 12) + tid + 256 * j] = acc[j];
}

__global__ void reduce_kernel()
{
    const int f = blockIdx.x * 256 + threadIdx.x;
    const int b = blockIdx.y;
    const float2* sp = g_spart + (((size_t)b * NGRP) << 12) + f;
    float2 s = make_float2(0.f, 0.f);
#pragma unroll 8
    for (int gp = 0; gp < NGRP; ++gp) {
        float2 v = sp[(size_t)gp << 12];
        s.x += v.x; s.y += v.y;
    }
    g_sred[((size_t)b << 12) + f] = s;
}

// Inverse FFT of reduced spectrum + fused top-k + softmax (corr stays in smem).
__global__ void ifft_topk_kernel()
{
    __shared__ float2 buf[FFT_BUF];
    __shared__ float2 tw[256];
    __shared__ float rv[256];
    __shared__ int   ri[256];
    __shared__ float wv[TOPK];
    __shared__ int   wi[TOPK];

    const int tid = threadIdx.x;
    const int b = blockIdx.x;

    {
        float s, c;
        sincosf(6.283185307179586f * (float)tid / 4096.0f, &s, &c);
        tw[tid] = make_float2(c, s);
    }
    __syncthreads();

#pragma unroll
    for (int j = 0; j < 16; ++j) {
        int f = tid + 256 * j;
        buf[FPAD(rev16_12(f))] = g_sred[((size_t)b << 12) + f];
    }
    __syncthreads();

    fft4096_r16<true>(buf, tw, tid);
    // buf[FPAD(tau)].x * scale = mean_corr(tau); select top-8 in smem.

    for (int r = 0; r < TOPK; ++r) {
        float best = -FLT_MAX;
        int bi = 0x7fffffff;
#pragma unroll
        for (int j = 0; j < 16; ++j) {
            int i = tid + 256 * j;           // ascending index order per thread
            float v = buf[FPAD(i)].x;
            if (v > best) { best = v; bi = i; }
        }
        rv[tid] = best; ri[tid] = bi;
        __syncthreads();
        for (int s = 128; s > 0; s >>= 1) {
            if (tid < s) {
                if (rv[tid + s] > rv[tid] ||
                    (rv[tid + s] == rv[tid] && ri[tid + s] < ri[tid])) {
                    rv[tid] = rv[tid + s]; ri[tid] = ri[tid + s];
                }
            }
            __syncthreads();
        }
        if (tid == 0) { wv[r] = rv[0]; wi[r] = ri[0]; buf[FPAD(ri[0])].x = -FLT_MAX; }
        __syncthreads();
    }

    if (tid == 0) {
        const float scale = 1.0f / (4096.0f * 512.0f);
        float mx = wv[0] * scale;
        float e[TOPK], sum = 0.f;
#pragma unroll
        for (int i = 0; i < TOPK; ++i) { e[i] = expf(wv[i] * scale - mx); sum += e[i]; }
        float inv = 1.0f / sum;
#pragma unroll
        for (int i = 0; i < TOPK; ++i) {
            g_weights[b * TOPK + i] = e[i] * inv;
            g_delays [b * TOPK + i] = wi[i];
        }
    }
}

// ====================== gather on hidden_states (natural [B,L,D]) ======================
__global__ __launch_bounds__(128)
void gatherx_kernel(const float* __restrict__ hs)
{
    __shared__ float ws[TOPK];
    __shared__ int   ds[TOPK];
    const int tid = threadIdx.x;
    const int l = blockIdx.x, b = blockIdx.y;

    if (tid < TOPK) {
        ws[tid] = g_weights[b * TOPK + tid];
        ds[tid] = g_delays [b * TOPK + tid];
    }
    __syncthreads();

    const float4* xb = (const float4*)(hs + (((size_t)b * LSEQ) << 9));
    float4 acc = make_float4(0.f, 0.f, 0.f, 0.f);
#pragma unroll
    for (int i = 0; i < TOPK; ++i) {
        int t = (l + ds[i]) & (LSEQ - 1);
        float4 v = xb[t * 128 + tid];
        float w = ws[i];
        acc.x += w * v.x; acc.y += w * v.y; acc.z += w * v.z; acc.w += w * v.w;
    }

    float f[4] = {acc.x, acc.y, acc.z, acc.w};
    __nv_bfloat16 h[4], lo[4];
#pragma unroll
    for (int j = 0; j < 4; ++j) {
        h[j]  = __float2bfloat16(f[j]);
        lo[j] = __float2bfloat16(f[j] - __bfloat162float(h[j]));
    }
    size_t base = (((size_t)b * LSEQ + l) << 9) + tid * 4;
    __nv_bfloat162 h01, h23, l01, l23;
    h01.x = h[0];  h01.y = h[1];  h23.x = h[2];  h23.y = h[3];
    l01.x = lo[0]; l01.y = lo[1]; l23.x = lo[2]; l23.y = lo[3];
    *(__nv_bfloat162*)(g_athi + base)     = h01;
    *(__nv_bfloat162*)(g_athi + base + 2) = h23;
    *(__nv_bfloat162*)(g_atlo + base)     = l01;
    *(__nv_bfloat162*)(g_atlo + base + 2) = l23;
}

// =====================================================================
extern "C" void kernel_launch(void* const* d_in, const int* in_sizes, int n_in,
                              void* d_out, int out_size)
{
    const float* hs = (const float*)d_in[0];
    const float* Wq = (const float*)d_in[1];
    const float* bq = (const float*)d_in[2];
    const float* Wk = (const float*)d_in[3];
    const float* bk = (const float*)d_in[4];
    const float* Wv = (const float*)d_in[5];
    const float* bv = (const float*)d_in[6];
    const float* Wo = (const float*)d_in[7];
    const float* bo = (const float*)d_in[8];
    float* out = (float*)d_out;

    void *pq, *pk, *pxhi, *pxlo, *pwhi, *pwlo, *pathi, *patlo, *pbov;
    cudaGetSymbolAddress(&pq,   g_q);
    cudaGetSymbolAddress(&pk,   g_k);
    cudaGetSymbolAddress(&pxhi, g_xhi);
    cudaGetSymbolAddress(&pxlo, g_xlo);
    cudaGetSymbolAddress(&pwhi, g_whi);
    cudaGetSymbolAddress(&pwlo, g_wlo);
    cudaGetSymbolAddress(&pathi, g_athi);
    cudaGetSymbolAddress(&patlo, g_atlo);
    cudaGetSymbolAddress(&pbov, g_bov);

    cudaFuncSetAttribute(gemm_qk_kernel,
                         cudaFuncAttributeMaxDynamicSharedMemorySize, GEMM_DSMEM);
    cudaFuncSetAttribute(gemm_o_kernel,
                         cudaFuncAttributeMaxDynamicSharedMemorySize, GEMM_DSMEM);

    const __nv_bfloat16* whi = (const __nv_bfloat16*)pwhi;
    const __nv_bfloat16* wlo = (const __nv_bfloat16*)pwlo;

    // 1. fp32 -> bf16 hi/lo; fold Wo@Wv and Wo·bv+bo (bov fused into wov grid)
    convert_x_kernel<<<(BATCH * LSEQ * DMODEL / 4) / 256, 256>>>(hs);
    convert_w_kernel<<<dim3(WSZ / 4 / 256, 2), 256>>>(Wq, Wk);
    wov_kernel<<<dim3(9, 8), 256>>>(Wo, Wv, bv, bo);

    // 2. fused Q/K projections -> [B, D, L] fp32
    QKPtrs p;
    p.whi[0] = whi + 0 * WSZ; p.wlo[0] = wlo + 0 * WSZ; p.bias[0] = bq; p.out[0] = (float*)pq;
    p.whi[1] = whi + 1 * WSZ; p.wlo[1] = wlo + 1 * WSZ; p.bias[1] = bk; p.out[1] = (float*)pk;
    dim3 ggq(LSEQ / BN, DMODEL / BM, 2 * BATCH);
    gemm_qk_kernel<<<ggq, 256, GEMM_DSMEM>>>(p,
        (const __nv_bfloat16*)pxhi, (const __nv_bfloat16*)pxlo);

    // 3. correlation spectrum + reduce + fused iFFT/top-k
    fftcorr_kernel<<<dim3(NGRP, BATCH), 256>>>();
    reduce_kernel<<<dim3(LSEQ / 256, BATCH), 256>>>();
    ifft_topk_kernel<<<BATCH, 256>>>();

    // 4. gather directly on hidden_states -> xagg bf16 hi/lo [B, L, D]
    gatherx_kernel<<<dim3(LSEQ, BATCH), 128>>>(hs);

    // 5. fused output projection: out = xagg @ Wov^T + bov  (transposed store)
    dim3 ggo(LSEQ / BN, DMODEL / BM, BATCH);
    gemm_o_kernel<<<ggo, 256, GEMM_DSMEM>>>(whi + 2 * WSZ, wlo + 2 * WSZ,
        (const __nv_bfloat16*)pathi, (const __nv_bfloat16*)patlo,
        (const float*)pbov, out);
}

// round 14
// speedup vs baseline: 4.0738x; 1.2137x over previous
#include <cuda_runtime.h>
#include <cuda_bf16.h>
#include <math.h>
#include <float.h>
#include <stdint.h>

#define BATCH  8
#define LSEQ   4096
#define DMODEL 512
#define TOPK   8
#define NGRP   64
#define WSZ    (DMODEL * DMODEL)

// ---------------- scratch (static device globals; no allocations) ----------------
__device__ float  g_u  [BATCH * DMODEL * LSEQ];   // u = H x, channel-major
__device__ float  g_xt [BATCH * DMODEL * LSEQ];   // x transposed, channel-major
__device__ float2 g_spart[BATCH * NGRP * LSEQ];
__device__ float2 g_sred [BATCH * LSEQ];
__device__ float  g_weights[BATCH * TOPK];
__device__ int    g_delays [BATCH * TOPK];
__device__ float  g_bov[DMODEL];
__device__ float  g_zero[DMODEL];                 // never written: stays 0
// bf16 hi/lo operands: slot 0 = H (=Wk^T Wq), slot 2 = Wov (=Wo Wv)
__device__ __nv_bfloat16 g_xhi [BATCH * LSEQ * DMODEL];
__device__ __nv_bfloat16 g_xlo [BATCH * LSEQ * DMODEL];
__device__ __nv_bfloat16 g_whi [3 * WSZ];
__device__ __nv_bfloat16 g_wlo [3 * WSZ];
__device__ __nv_bfloat16 g_athi[BATCH * LSEQ * DMODEL];   // xagg [B, L, D]
__device__ __nv_bfloat16 g_atlo[BATCH * LSEQ * DMODEL];

// ====================== helpers ======================
__device__ __forceinline__ uint32_t smem_u32(const void* p) {
    uint32_t a;
    asm("{ .reg .u64 t; cvta.to.shared.u64 t, %1; cvt.u32.u64 %0, t; }" : "=r"(a) : "l"(p));
    return a;
}
#define SWZ(off) ((off) ^ (((off) >> 3) & 0x70))

__device__ __forceinline__ void cpa16(uint32_t dst, const void* src) {
    asm volatile("cp.async.ca.shared.global [%0], [%1], 16;" :: "r"(dst), "l"(src));
}
#define CPA_COMMIT() asm volatile("cp.async.commit_group;" ::: "memory")
#define CPA_WAIT(N)  asm volatile("cp.async.wait_group %0;" :: "n"(N) : "memory")

__device__ __forceinline__ void ldmA(uint32_t* a, uint32_t addr) {
    asm volatile("ldmatrix.sync.aligned.m8n8.x4.shared.b16 {%0,%1,%2,%3}, [%4];"
        : "=r"(a[0]), "=r"(a[1]), "=r"(a[2]), "=r"(a[3]) : "r"(addr));
}
__device__ __forceinline__ void ldmB(uint32_t* b, uint32_t addr) {
    asm volatile("ldmatrix.sync.aligned.m8n8.x2.shared.b16 {%0,%1}, [%2];"
        : "=r"(b[0]), "=r"(b[1]) : "r"(addr));
}
__device__ __forceinline__ void mma16816(float* c, const uint32_t* a, const uint32_t* b) {
    asm volatile("mma.sync.aligned.m16n8k16.row.col.f32.bf16.bf16.f32 "
        "{%0,%1,%2,%3}, {%4,%5,%6,%7}, {%8,%9}, {%0,%1,%2,%3};"
        : "+f"(c[0]), "+f"(c[1]), "+f"(c[2]), "+f"(c[3])
        : "r"(a[0]), "r"(a[1]), "r"(a[2]), "r"(a[3]), "r"(b[0]), "r"(b[1]));
}

// ====================== bf16x3 mma.sync GEMM core ======================
#define BM 128
#define BN 128
#define BK 64
#define NCHUNK (DMODEL / BK)       // 8
#define TSZ     16384
#define OFF_AHI 0
#define OFF_ALO (TSZ)
#define OFF_BHI (2 * TSZ)
#define OFF_BLO (3 * TSZ)
#define STAGE_BYTES (4 * TSZ)              // 65536
#define NSTAGE 3
#define GEMM_DSMEM  (NSTAGE * STAGE_BYTES + 1024)

template<bool TRANS_OUT>
__device__ __forceinline__
void gemm_body(const __nv_bfloat16* __restrict__ Ahi,
               const __nv_bfloat16* __restrict__ Alo,
               const __nv_bfloat16* __restrict__ Bhi,
               const __nv_bfloat16* __restrict__ Blo,
               const float* __restrict__ bias,
               float* __restrict__ out,
               char* dsm, int b, int m0, int n0)
{
    const int tid  = threadIdx.x;
    const int wid  = tid >> 5;
    const int lane = tid & 31;
    const int wm   = wid >> 2;
    const int wn   = wid & 3;

    uint32_t sbase = (smem_u32(dsm) + 1023u) & ~1023u;

    const __nv_bfloat16* aHi = Ahi + (size_t)m0 * DMODEL;
    const __nv_bfloat16* aLo = Alo + (size_t)m0 * DMODEL;
    const __nv_bfloat16* bHi = Bhi + ((size_t)b * LSEQ + n0) * DMODEL;
    const __nv_bfloat16* bLo = Blo + ((size_t)b * LSEQ + n0) * DMODEL;

    auto load_chunk = [&](int st, int k0) {
        uint32_t sb = sbase + st * STAGE_BYTES;
#pragma unroll
        for (int it = 0; it < 4; ++it) {
            int idx = tid + it * 256;
            int row = idx >> 3, q = idx & 7;
            uint32_t sw = SWZ((uint32_t)(row * 128 + q * 16));
            size_t go = (size_t)row * DMODEL + k0 + q * 8;
            cpa16(sb + OFF_AHI + sw, aHi + go);
            cpa16(sb + OFF_ALO + sw, aLo + go);
            cpa16(sb + OFF_BHI + sw, bHi + go);
            cpa16(sb + OFF_BLO + sw, bLo + go);
        }
        CPA_COMMIT();
    };

    float c[4][4][4];
#pragma unroll
    for (int i = 0; i < 4; ++i)
#pragma unroll
        for (int j = 0; j < 4; ++j)
#pragma unroll
            for (int r = 0; r < 4; ++r) c[i][j][r] = 0.f;

    load_chunk(0, 0);
    load_chunk(1, BK);

    // single-barrier pipeline (stage ch+2 written only after top sync of ch)
    for (int ch = 0; ch < NCHUNK; ++ch) {
        int st = ch % NSTAGE;
        if (ch < NCHUNK - 1) { CPA_WAIT(1); }
        else                 { CPA_WAIT(0); }
        __syncthreads();
        if (ch + 2 < NCHUNK) load_chunk((ch + 2) % NSTAGE, (ch + 2) * BK);

        uint32_t sb = sbase + st * STAGE_BYTES;
        uint32_t aHiB = sb + OFF_AHI, aLoB = sb + OFF_ALO;
        uint32_t bHiB = sb + OFF_BHI, bLoB = sb + OFF_BLO;

#pragma unroll
        for (int ks = 0; ks < 4; ++ks) {
            uint32_t bh[4][2], bl[4][2];
#pragma unroll
            for (int ni = 0; ni < 4; ++ni) {
                uint32_t rowb = wn * 32 + ni * 8 + (lane & 7);
                uint32_t cb   = ks * 32 + (((lane >> 3) & 1) << 4);
                uint32_t off  = SWZ(rowb * 128 + cb);
                ldmB(bh[ni], bHiB + off);
                ldmB(bl[ni], bLoB + off);
            }
#pragma unroll
            for (int mi = 0; mi < 4; ++mi) {
                uint32_t rowa = wm * 64 + mi * 16 + (lane & 15);
                uint32_t ca   = ks * 32 + ((lane >> 4) << 4);
                uint32_t off  = SWZ(rowa * 128 + ca);
                uint32_t ah[4], al[4];
                ldmA(ah, aHiB + off);
                ldmA(al, aLoB + off);
#pragma unroll
                for (int ni = 0; ni < 4; ++ni) {
                    mma16816(c[mi][ni], ah, bh[ni]);
                    mma16816(c[mi][ni], ah, bl[ni]);
                    mma16816(c[mi][ni], al, bh[ni]);
                }
            }
        }
    }

    const int r  = lane >> 2;
    const int q2 = (lane & 3) << 1;
    if (!TRANS_OUT) {
#pragma unroll
        for (int mi = 0; mi < 4; ++mi) {
            int m = m0 + wm * 64 + mi * 16 + r;
            float b0v = bias[m];
            float b1v = bias[m + 8];
#pragma unroll
            for (int ni = 0; ni < 4; ++ni) {
                int n = n0 + wn * 32 + ni * 8 + q2;
                float* p = out + ((size_t)(b * DMODEL + m) << 12) + n;
                *(float2*)p = make_float2(c[mi][ni][0] + b0v, c[mi][ni][1] + b0v);
                float* p2 = p + (8 << 12);
                *(float2*)p2 = make_float2(c[mi][ni][2] + b1v, c[mi][ni][3] + b1v);
            }
        }
    } else {
        float* tileT = (float*)dsm;   // 128 n-rows x 132 floats
        __syncthreads();
#pragma unroll
        for (int mi = 0; mi < 4; ++mi) {
            int ml = wm * 64 + mi * 16 + r;
#pragma unroll
            for (int ni = 0; ni < 4; ++ni) {
                int nl = wn * 32 + ni * 8 + q2;
                tileT[nl * 132 + ml]           = c[mi][ni][0];
                tileT[(nl + 1) * 132 + ml]     = c[mi][ni][1];
                tileT[nl * 132 + ml + 8]       = c[mi][ni][2];
                tileT[(nl + 1) * 132 + ml + 8] = c[mi][ni][3];
            }
        }
        __syncthreads();
#pragma unroll
        for (int it = 0; it < 16; ++it) {
            int idx = tid + it * 256;
            int nl = idx >> 5;
            int c4 = (idx & 31) << 2;
            float4 v = *(float4*)&tileT[nl * 132 + c4];
            v.x += bias[m0 + c4];
            v.y += bias[m0 + c4 + 1];
            v.z += bias[m0 + c4 + 2];
            v.w += bias[m0 + c4 + 3];
            *(float4*)(out + (((size_t)b * LSEQ + n0 + nl) << 9) + m0 + c4) = v;
        }
    }
}

template<bool TRANS_OUT>
__global__ __launch_bounds__(256, 1)
void gemm_kernel(const __nv_bfloat16* __restrict__ Ahi, const __nv_bfloat16* __restrict__ Alo,
                 const __nv_bfloat16* __restrict__ Bhi, const __nv_bfloat16* __restrict__ Blo,
                 const float* __restrict__ bias, float* __restrict__ out)
{
    extern __shared__ char dsm[];
    gemm_body<TRANS_OUT>(Ahi, Alo, Bhi, Blo, bias, out,
                         dsm, blockIdx.z, blockIdx.y * BM, blockIdx.x * BN);
}

// ====================== convert x: bf16 hi/lo + fp32 transpose ======================
// reads hs [B,L,D]; writes g_xhi/g_xlo [B,L,D] and g_xt [B,D,L]
__global__ __launch_bounds__(256)
void convert_x_kernel(const float* __restrict__ hs)
{
    __shared__ float tile[32][33];
    const int tx = threadIdx.x;        // 0..31
    const int ty = threadIdx.y;        // 0..7
    const int b  = blockIdx.z;
    const int d0 = blockIdx.y * 32;
    const int l0 = blockIdx.x * 32;

#pragma unroll
    for (int i = 0; i < 4; ++i) {
        int l = l0 + ty + i * 8;
        size_t gi = (((size_t)b * LSEQ + l) << 9) + d0 + tx;
        float v = hs[gi];
        tile[ty + i * 8][tx] = v;
        __nv_bfloat16 h  = __float2bfloat16(v);
        __nv_bfloat16 lo = __float2bfloat16(v - __bfloat162float(h));
        g_xhi[gi] = h;
        g_xlo[gi] = lo;
    }
    __syncthreads();

#pragma unroll
    for (int i = 0; i < 4; ++i) {
        int d = d0 + ty + i * 8;
        g_xt[(((size_t)b * DMODEL + d) << 12) + l0 + tx] = tile[tx][ty + i * 8];
    }
}

// ====================== H = Wk^T @ Wq (fp32) -> bf16 hi/lo slot 0 ======================
__global__ __launch_bounds__(256)
void h_kernel(const float* __restrict__ Wk, const float* __restrict__ Wq)
{
    __shared__ float As[32][68];   // [d][m]  (Wk rows)
    __shared__ float Bs[32][68];   // [d][k]  (Wq rows)
    const int tid = threadIdx.x;
    const int tx = tid & 15, ty = tid >> 4;
    const int m0 = blockIdx.y * 64, n0 = blockIdx.x * 64;

    float c[4][4];
#pragma unroll
    for (int i = 0; i < 4; ++i)
#pragma unroll
        for (int j = 0; j < 4; ++j) c[i][j] = 0.f;

    for (int cc = 0; cc < DMODEL; cc += 32) {
#pragma unroll
        for (int it = 0; it < 2; ++it) {
            int idx = tid + it * 256;            // 0..511
            int d2 = idx >> 4; int q4 = (idx & 15) << 2;
            *(float4*)&As[d2][q4] = *(const float4*)&Wk[(size_t)(cc + d2) * DMODEL + m0 + q4];
            *(float4*)&Bs[d2][q4] = *(const float4*)&Wq[(size_t)(cc + d2) * DMODEL + n0 + q4];
        }
        __syncthreads();
#pragma unroll
        for (int k = 0; k < 32; ++k) {
            float a[4], bb[4];
#pragma unroll
            for (int i = 0; i < 4; ++i) a[i] = As[k][ty * 4 + i];
#pragma unroll
            for (int j = 0; j < 4; ++j) bb[j] = Bs[k][tx * 4 + j];
#pragma unroll
            for (int i = 0; i < 4; ++i)
#pragma unroll
                for (int j = 0; j < 4; ++j) c[i][j] += a[i] * bb[j];
        }
        __syncthreads();
    }

#pragma unroll
    for (int i = 0; i < 4; ++i) {
        int m = m0 + ty * 4 + i;
#pragma unroll
        for (int j = 0; j < 4; ++j) {
            int n = n0 + tx * 4 + j;
            float v = c[i][j];
            __nv_bfloat16 h  = __float2bfloat16(v);
            __nv_bfloat16 lo = __float2bfloat16(v - __bfloat162float(h));
            g_whi[(size_t)m * DMODEL + n] = h;
            g_wlo[(size_t)m * DMODEL + n] = lo;
        }
    }
}

// ====================== Wov = Wo @ Wv -> bf16 hi/lo slot 2; +bov column ======================
__global__ __launch_bounds__(256)
void wov_kernel(const float* __restrict__ Wo, const float* __restrict__ Wv,
                const float* __restrict__ bv, const float* __restrict__ bo)
{
    if (blockIdx.x == 8) {
        int w = threadIdx.x >> 5, lane = threadIdx.x & 31;
#pragma unroll
        for (int rr = 0; rr < 8; ++rr) {
            int m = blockIdx.y * 64 + w * 8 + rr;
            const float* row = Wo + (size_t)m * DMODEL;
            float s = 0.f;
            for (int c = lane; c < DMODEL; c += 32) s += row[c] * bv[c];
#pragma unroll
            for (int o = 16; o; o >>= 1) s += __shfl_xor_sync(0xffffffffu, s, o);
            if (lane == 0) g_bov[m] = s + bo[m];
        }
        return;
    }

    __shared__ float As[32][68];
    __shared__ float Bs[32][68];
    const int tid = threadIdx.x;
    const int tx = tid & 15, ty = tid >> 4;
    const int m0 = blockIdx.y * 64, n0 = blockIdx.x * 64;

    float c[4][4];
#pragma unroll
    for (int i = 0; i < 4; ++i)
#pragma unroll
        for (int j = 0; j < 4; ++j) c[i][j] = 0.f;

    for (int cc = 0; cc < DMODEL; cc += 32) {
#pragma unroll
        for (int it = 0; it < 2; ++it) {
            int idx = tid + it * 256;
            int m = idx >> 3; int cq = (idx & 7) << 2;
            float4 v = *(const float4*)&Wo[(size_t)(m0 + m) * DMODEL + cc + cq];
            As[cq + 0][m] = v.x; As[cq + 1][m] = v.y;
            As[cq + 2][m] = v.z; As[cq + 3][m] = v.w;
        }
#pragma unroll
        for (int it = 0; it < 2; ++it) {
            int idx = tid + it * 256;
            int c2 = idx >> 4; int nq = (idx & 15) << 2;
            *(float4*)&Bs[c2][nq] = *(const float4*)&Wv[(size_t)(cc + c2) * DMODEL + n0 + nq];
        }
        __syncthreads();
#pragma unroll
        for (int k = 0; k < 32; ++k) {
            float a[4], bb[4];
#pragma unroll
            for (int i = 0; i < 4; ++i) a[i] = As[k][ty * 4 + i];
#pragma unroll
            for (int j = 0; j < 4; ++j) bb[j] = Bs[k][tx * 4 + j];
#pragma unroll
            for (int i = 0; i < 4; ++i)
#pragma unroll
                for (int j = 0; j < 4; ++j) c[i][j] += a[i] * bb[j];
        }
        __syncthreads();
    }

#pragma unroll
    for (int i = 0; i < 4; ++i) {
        int m = m0 + ty * 4 + i;
#pragma unroll
        for (int j = 0; j < 4; ++j) {
            int n = n0 + tx * 4 + j;
            float v = c[i][j];
            __nv_bfloat16 h  = __float2bfloat16(v);
            __nv_bfloat16 lo = __float2bfloat16(v - __bfloat162float(h));
            g_whi[2 * (size_t)WSZ + (size_t)m * DMODEL + n] = h;
            g_wlo[2 * (size_t)WSZ + (size_t)m * DMODEL + n] = lo;
        }
    }
}

// ====================== radix-16 FFT machinery ======================
#define FPAD(i) ((i) + ((i) >> 4) + ((i) >> 8))
#define FFT_BUF 4368

__device__ __forceinline__ float2 cmul(float2 a, float2 b) {
    return make_float2(a.x * b.x - a.y * b.y, a.x * b.y + a.y * b.x);
}
__device__ __forceinline__ int rev16_12(int i) {
    return ((i & 15) << 8) | (i & 0xF0) | ((i >> 8) & 15);
}

template<bool INV>
__device__ __forceinline__ void dft4(float2 a, float2 b, float2 c, float2 d,
                                     float2& o0, float2& o1, float2& o2, float2& o3)
{
    float2 e0 = make_float2(a.x + c.x, a.y + c.y);
    float2 e1 = make_float2(a.x - c.x, a.y - c.y);
    float2 e2 = make_float2(b.x + d.x, b.y + d.y);
    float2 e3 = make_float2(b.x - d.x, b.y - d.y);
    o0 = make_float2(e0.x + e2.x, e0.y + e2.y);
    o2 = make_float2(e0.x - e2.x, e0.y - e2.y);
    if (!INV) {
        o1 = make_float2(e1.x + e3.y, e1.y - e3.x);
        o3 = make_float2(e1.x - e3.y, e1.y + e3.x);
    } else {
        o1 = make_float2(e1.x - e3.y, e1.y + e3.x);
        o3 = make_float2(e1.x + e3.y, e1.y - e3.x);
    }
}

template<bool INV>
__device__ __forceinline__ void dft16(float2* x)
{
    const float c1 = 0.92387953251128674f;
    const float s1 = 0.38268343236508978f;
    const float r2 = 0.70710678118654752f;
    const float si = INV ? 1.f : -1.f;
    auto tm = [](float2 v, float wr, float wi) {
        return make_float2(v.x * wr - v.y * wi, v.x * wi + v.y * wr);
    };
    float2 A[16];
#pragma unroll
    for (int t0 = 0; t0 < 4; ++t0)
        dft4<INV>(x[t0], x[t0 + 4], x[t0 + 8], x[t0 + 12],
                  A[0 + t0], A[4 + t0], A[8 + t0], A[12 + t0]);
    A[4 + 1]  = tm(A[4 + 1],  c1,  si * s1);
    A[4 + 2]  = tm(A[4 + 2],  r2,  si * r2);
    A[4 + 3]  = tm(A[4 + 3],  s1,  si * c1);
    A[8 + 1]  = tm(A[8 + 1],  r2,  si * r2);
    A[8 + 2]  = tm(A[8 + 2],  0.f, si);
    A[8 + 3]  = tm(A[8 + 3], -r2,  si * r2);
    A[12 + 1] = tm(A[12 + 1], s1,  si * c1);
    A[12 + 2] = tm(A[12 + 2], -r2, si * r2);
    A[12 + 3] = tm(A[12 + 3], -c1, -si * s1);
#pragma unroll
    for (int u0 = 0; u0 < 4; ++u0)
        dft4<INV>(A[u0 * 4], A[u0 * 4 + 1], A[u0 * 4 + 2], A[u0 * 4 + 3],
                  x[u0], x[u0 + 4], x[u0 + 8], x[u0 + 12]);
}

template<bool INV>
__device__ __forceinline__ void fft4096_r16(float2* buf, const float2* tw, int tid)
{
#pragma unroll
    for (int s = 0; s < 3; ++s) {
        const int Q = 1 << (4 * s);
        int q  = tid & (Q - 1);
        int i0 = ((tid >> (4 * s)) << (4 * s + 4)) + q;
        float2 w1 = tw[q << (8 - 4 * s)];
        float2 x[16];
        x[0] = buf[FPAD(i0)];
        float2 wt = w1;
#pragma unroll
        for (int t = 1; t < 16; ++t) {
            x[t] = cmul(buf[FPAD(i0 + t * Q)], wt);
            wt = cmul(wt, w1);
        }
        dft16<INV>(x);
#pragma unroll
        for (int u = 0; u < 16; ++u) buf[FPAD(i0 + u * Q)] = x[u];
        __syncthreads();
    }
}

// Forward FFT of z = u + i*x per channel, accumulate Uf*conj(Xf) over 8 channels.
__global__ void fftcorr_kernel()
{
    __shared__ float2 buf[FFT_BUF];
    __shared__ float2 tw[256];

    const int tid = threadIdx.x;
    const int g = blockIdx.x, b = blockIdx.y;

    if (tid < 256) {
        float s, c;
        sincosf(6.283185307179586f * (float)tid / 4096.0f, &s, &c);
        tw[tid] = make_float2(c, -s);
    }

    float2 acc[16];
#pragma unroll
    for (int j = 0; j < 16; ++j) acc[j] = make_float2(0.f, 0.f);

    for (int cc = 0; cc < 8; ++cc) {
        int ch = g * 8 + cc;
        const float* up = g_u  + (((size_t)b * DMODEL + ch) << 12);
        const float* xp = g_xt + (((size_t)b * DMODEL + ch) << 12);

        __syncthreads();
#pragma unroll
        for (int j = 0; j < 16; ++j) {
            int n = tid + 256 * j;
            buf[FPAD(rev16_12(n))] = make_float2(up[n], xp[n]);
        }
        __syncthreads();

        fft4096_r16<false>(buf, tw, tid);

#pragma unroll
        for (int j = 0; j < 16; ++j) {
            int f = tid + 256 * j;
            float2 Zf = buf[FPAD(f)];
            float2 Zm = buf[FPAD((4096 - f) & 4095)];
            float2 U  = make_float2(0.5f * (Zf.x + Zm.x), 0.5f * (Zf.y - Zm.y));
            float dx = Zf.x - Zm.x, dy = Zf.y + Zm.y;
            float2 Xc = make_float2(0.5f * dy, -0.5f * dx);
            acc[j].x += U.x * Xc.x + U.y * Xc.y;
            acc[j].y += U.y * Xc.x - U.x * Xc.y;
        }
    }
#pragma unroll
    for (int j = 0; j < 16; ++j)
        g_spart[(((size_t)b * NGRP + g) << 12) + tid + 256 * j] = acc[j];
}

__global__ void reduce_kernel()
{
    const int f = blockIdx.x * 256 + threadIdx.x;
    const int b = blockIdx.y;
    const float2* sp = g_spart + (((size_t)b * NGRP) << 12) + f;
    float2 s = make_float2(0.f, 0.f);
#pragma unroll 8
    for (int gp = 0; gp < NGRP; ++gp) {
        float2 v = sp[(size_t)gp << 12];
        s.x += v.x; s.y += v.y;
    }
    g_sred[((size_t)b << 12) + f] = s;
}

// Inverse FFT of reduced spectrum + fused top-k + softmax.
__global__ void ifft_topk_kernel()
{
    __shared__ float2 buf[FFT_BUF];
    __shared__ float2 tw[256];
    __shared__ float rv[256];
    __shared__ int   ri[256];
    __shared__ float wv[TOPK];
    __shared__ int   wi[TOPK];

    const int tid = threadIdx.x;
    const int b = blockIdx.x;

    {
        float s, c;
        sincosf(6.283185307179586f * (float)tid / 4096.0f, &s, &c);
        tw[tid] = make_float2(c, s);
    }
    __syncthreads();

#pragma unroll
    for (int j = 0; j < 16; ++j) {
        int f = tid + 256 * j;
        buf[FPAD(rev16_12(f))] = g_sred[((size_t)b << 12) + f];
    }
    __syncthreads();

    fft4096_r16<true>(buf, tw, tid);

    for (int r = 0; r < TOPK; ++r) {
        float best = -FLT_MAX;
        int bi = 0x7fffffff;
#pragma unroll
        for (int j = 0; j < 16; ++j) {
            int i = tid + 256 * j;
            float v = buf[FPAD(i)].x;
            if (v > best) { best = v; bi = i; }
        }
        rv[tid] = best; ri[tid] = bi;
        __syncthreads();
        for (int s = 128; s > 0; s >>= 1) {
            if (tid < s) {
                if (rv[tid + s] > rv[tid] ||
                    (rv[tid + s] == rv[tid] && ri[tid + s] < ri[tid])) {
                    rv[tid] = rv[tid + s]; ri[tid] = ri[tid + s];
                }
            }
            __syncthreads();
        }
        if (tid == 0) { wv[r] = rv[0]; wi[r] = ri[0]; buf[FPAD(ri[0])].x = -FLT_MAX; }
        __syncthreads();
    }

    if (tid == 0) {
        const float scale = 1.0f / (4096.0f * 512.0f);
        float mx = wv[0] * scale;
        float e[TOPK], sum = 0.f;
#pragma unroll
        for (int i = 0; i < TOPK; ++i) { e[i] = expf(wv[i] * scale - mx); sum += e[i]; }
        float inv = 1.0f / sum;
#pragma unroll
        for (int i = 0; i < TOPK; ++i) {
            g_weights[b * TOPK + i] = e[i] * inv;
            g_delays [b * TOPK + i] = wi[i];
        }
    }
}

// ====================== gather on hidden_states (natural [B,L,D]) ======================
__global__ __launch_bounds__(128)
void gatherx_kernel(const float* __restrict__ hs)
{
    __shared__ float ws[TOPK];
    __shared__ int   ds[TOPK];
    const int tid = threadIdx.x;
    const int l = blockIdx.x, b = blockIdx.y;

    if (tid < TOPK) {
        ws[tid] = g_weights[b * TOPK + tid];
        ds[tid] = g_delays [b * TOPK + tid];
    }
    __syncthreads();

    const float4* xb = (const float4*)(hs + (((size_t)b * LSEQ) << 9));
    float4 acc = make_float4(0.f, 0.f, 0.f, 0.f);
#pragma unroll
    for (int i = 0; i < TOPK; ++i) {
        int t = (l + ds[i]) & (LSEQ - 1);
        float4 v = xb[t * 128 + tid];
        float w = ws[i];
        acc.x += w * v.x; acc.y += w * v.y; acc.z += w * v.z; acc.w += w * v.w;
    }

    float f[4] = {acc.x, acc.y, acc.z, acc.w};
    __nv_bfloat16 h[4], lo[4];
#pragma unroll
    for (int j = 0; j < 4; ++j) {
        h[j]  = __float2bfloat16(f[j]);
        lo[j] = __float2bfloat16(f[j] - __bfloat162float(h[j]));
    }
    size_t base = (((size_t)b * LSEQ + l) << 9) + tid * 4;
    __nv_bfloat162 h01, h23, l01, l23;
    h01.x = h[0];  h01.y = h[1];  h23.x = h[2];  h23.y = h[3];
    l01.x = lo[0]; l01.y = lo[1]; l23.x = lo[2]; l23.y = lo[3];
    *(__nv_bfloat162*)(g_athi + base)     = h01;
    *(__nv_bfloat162*)(g_athi + base + 2) = h23;
    *(__nv_bfloat162*)(g_atlo + base)     = l01;
    *(__nv_bfloat162*)(g_atlo + base + 2) = l23;
}

// =====================================================================
extern "C" void kernel_launch(void* const* d_in, const int* in_sizes, int n_in,
                              void* d_out, int out_size)
{
    const float* hs = (const float*)d_in[0];
    const float* Wq = (const float*)d_in[1];
    const float* Wk = (const float*)d_in[3];
    const float* Wv = (const float*)d_in[5];
    const float* bv = (const float*)d_in[6];
    const float* Wo = (const float*)d_in[7];
    const float* bo = (const float*)d_in[8];
    float* out = (float*)d_out;

    void *pu, *pxhi, *pxlo, *pwhi, *pwlo, *pathi, *patlo, *pbov, *pzero;
    cudaGetSymbolAddress(&pu,   g_u);
    cudaGetSymbolAddress(&pxhi, g_xhi);
    cudaGetSymbolAddress(&pxlo, g_xlo);
    cudaGetSymbolAddress(&pwhi, g_whi);
    cudaGetSymbolAddress(&pwlo, g_wlo);
    cudaGetSymbolAddress(&pathi, g_athi);
    cudaGetSymbolAddress(&patlo, g_atlo);
    cudaGetSymbolAddress(&pbov, g_bov);
    cudaGetSymbolAddress(&pzero, g_zero);

    cudaFuncSetAttribute(gemm_kernel<false>,
                         cudaFuncAttributeMaxDynamicSharedMemorySize, GEMM_DSMEM);
    cudaFuncSetAttribute(gemm_kernel<true>,
                         cudaFuncAttributeMaxDynamicSharedMemorySize, GEMM_DSMEM);

    const __nv_bfloat16* whi = (const __nv_bfloat16*)pwhi;
    const __nv_bfloat16* wlo = (const __nv_bfloat16*)pwlo;

    // 1. x: bf16 hi/lo + fp32 transpose; H = Wk^T Wq; Wov = Wo Wv (+bov)
    convert_x_kernel<<<dim3(LSEQ / 32, DMODEL / 32, BATCH), dim3(32, 8)>>>(hs);
    h_kernel<<<dim3(8, 8), 256>>>(Wk, Wq);
    wov_kernel<<<dim3(9, 8), 256>>>(Wo, Wv, bv, bo);

    // 2. single projection u = H x  -> [B, D, L] fp32 (bias = 0)
    dim3 ggu(LSEQ / BN, DMODEL / BM, BATCH);
    gemm_kernel<false><<<ggu, 256, GEMM_DSMEM>>>(whi, wlo,
        (const __nv_bfloat16*)pxhi, (const __nv_bfloat16*)pxlo,
        (const float*)pzero, (float*)pu);

    // 3. cross-correlation spectrum of (u, x) + reduce + fused iFFT/top-k
    fftcorr_kernel<<<dim3(NGRP, BATCH), 256>>>();
    reduce_kernel<<<dim3(LSEQ / 256, BATCH), 256>>>();
    ifft_topk_kernel<<<BATCH, 256>>>();

    // 4. gather directly on hidden_states -> xagg bf16 hi/lo [B, L, D]
    gatherx_kernel<<<dim3(LSEQ, BATCH), 128>>>(hs);

    // 5. fused output projection: out = xagg @ Wov^T + bov (transposed store)
    gemm_kernel<true><<<ggu, 256, GEMM_DSMEM>>>(whi + 2 * WSZ, wlo + 2 * WSZ,
        (const __nv_bfloat16*)pathi, (const __nv_bfloat16*)patlo,
        (const float*)pbov, out);
}

// round 15
// speedup vs baseline: 4.3439x; 1.0663x over previous
#include <cuda_runtime.h>
#include <cuda_bf16.h>
#include <math.h>
#include <float.h>
#include <stdint.h>

#define BATCH  8
#define LSEQ   4096
#define DMODEL 512
#define TOPK   8
#define NGRP   64
#define WSZ    (DMODEL * DMODEL)

// ---------------- scratch (static device globals; no allocations) ----------------
__device__ float  g_u  [BATCH * DMODEL * LSEQ];   // u = H x, channel-major [B,D,L]
__device__ float  g_y  [BATCH * LSEQ * DMODEL];   // y = Wov x, [B,L,D]
__device__ float  g_xt [BATCH * DMODEL * LSEQ];   // x transposed, channel-major
__device__ float2 g_spart[BATCH * NGRP * LSEQ];
__device__ float2 g_sred [BATCH * LSEQ];
__device__ float  g_weights[BATCH * TOPK];
__device__ int    g_delays [BATCH * TOPK];
__device__ float  g_bov[DMODEL];
// bf16 hi/lo operands: slot 0 = H (=Wk^T Wq), slot 2 = Wov (=Wo Wv)
__device__ __nv_bfloat16 g_xhi [BATCH * LSEQ * DMODEL];
__device__ __nv_bfloat16 g_xlo [BATCH * LSEQ * DMODEL];
__device__ __nv_bfloat16 g_whi [3 * WSZ];
__device__ __nv_bfloat16 g_wlo [3 * WSZ];

// ====================== helpers ======================
__device__ __forceinline__ uint32_t smem_u32(const void* p) {
    uint32_t a;
    asm("{ .reg .u64 t; cvta.to.shared.u64 t, %1; cvt.u32.u64 %0, t; }" : "=r"(a) : "l"(p));
    return a;
}
#define SWZ(off) ((off) ^ (((off) >> 3) & 0x70))

__device__ __forceinline__ void cpa16(uint32_t dst, const void* src) {
    asm volatile("cp.async.ca.shared.global [%0], [%1], 16;" :: "r"(dst), "l"(src));
}
#define CPA_COMMIT() asm volatile("cp.async.commit_group;" ::: "memory")
#define CPA_WAIT(N)  asm volatile("cp.async.wait_group %0;" :: "n"(N) : "memory")

__device__ __forceinline__ void ldmA(uint32_t* a, uint32_t addr) {
    asm volatile("ldmatrix.sync.aligned.m8n8.x4.shared.b16 {%0,%1,%2,%3}, [%4];"
        : "=r"(a[0]), "=r"(a[1]), "=r"(a[2]), "=r"(a[3]) : "r"(addr));
}
__device__ __forceinline__ void ldmB(uint32_t* b, uint32_t addr) {
    asm volatile("ldmatrix.sync.aligned.m8n8.x2.shared.b16 {%0,%1}, [%2];"
        : "=r"(b[0]), "=r"(b[1]) : "r"(addr));
}
__device__ __forceinline__ void mma16816(float* c, const uint32_t* a, const uint32_t* b) {
    asm volatile("mma.sync.aligned.m16n8k16.row.col.f32.bf16.bf16.f32 "
        "{%0,%1,%2,%3}, {%4,%5,%6,%7}, {%8,%9}, {%0,%1,%2,%3};"
        : "+f"(c[0]), "+f"(c[1]), "+f"(c[2]), "+f"(c[3])
        : "r"(a[0]), "r"(a[1]), "r"(a[2]), "r"(a[3]), "r"(b[0]), "r"(b[1]));
}

// ====================== bf16x3 mma.sync fused GEMM ======================
// Computes BOTH u = H x  (rows 0..511 of stacked weight, out [B,D,L])
//      AND y = Wov x     (rows 512..1023,            out [B,L,D])
// in a single launch; B operand (xhi/xlo) shared.
#define BM 128
#define BN 128
#define BK 64
#define NCHUNK (DMODEL / BK)       // 8
#define TSZ     16384
#define OFF_AHI 0
#define OFF_ALO (TSZ)
#define OFF_BHI (2 * TSZ)
#define OFF_BLO (3 * TSZ)
#define STAGE_BYTES (4 * TSZ)              // 65536
#define NSTAGE 3
#define GEMM_DSMEM  (NSTAGE * STAGE_BYTES + 1024)

__global__ __launch_bounds__(256, 1)
void gemm_uy_kernel(const __nv_bfloat16* __restrict__ Whi,
                    const __nv_bfloat16* __restrict__ Wlo,
                    const __nv_bfloat16* __restrict__ Bhi,
                    const __nv_bfloat16* __restrict__ Blo,
                    float* __restrict__ uout, float* __restrict__ yout)
{
    extern __shared__ char dsm[];
    const int tid  = threadIdx.x;
    const int wid  = tid >> 5;
    const int lane = tid & 31;
    const int wm   = wid >> 2;
    const int wn   = wid & 3;
    const int b  = blockIdx.z;
    const int mb = blockIdx.y;                 // 0..7
    const bool isY = (mb >= 4);
    const int m0 = (isY ? (mb - 4) : mb) * BM;
    const int n0 = blockIdx.x * BN;

    uint32_t sbase = (smem_u32(dsm) + 1023u) & ~1023u;

    const __nv_bfloat16* aHi = Whi + (isY ? 2 * (size_t)WSZ : 0) + (size_t)m0 * DMODEL;
    const __nv_bfloat16* aLo = Wlo + (isY ? 2 * (size_t)WSZ : 0) + (size_t)m0 * DMODEL;
    const __nv_bfloat16* bHi = Bhi + ((size_t)b * LSEQ + n0) * DMODEL;
    const __nv_bfloat16* bLo = Blo + ((size_t)b * LSEQ + n0) * DMODEL;

    auto load_chunk = [&](int st, int k0) {
        uint32_t sb = sbase + st * STAGE_BYTES;
#pragma unroll
        for (int it = 0; it < 4; ++it) {
            int idx = tid + it * 256;
            int row = idx >> 3, q = idx & 7;
            uint32_t sw = SWZ((uint32_t)(row * 128 + q * 16));
            size_t go = (size_t)row * DMODEL + k0 + q * 8;
            cpa16(sb + OFF_AHI + sw, aHi + go);
            cpa16(sb + OFF_ALO + sw, aLo + go);
            cpa16(sb + OFF_BHI + sw, bHi + go);
            cpa16(sb + OFF_BLO + sw, bLo + go);
        }
        CPA_COMMIT();
    };

    float c[4][4][4];
#pragma unroll
    for (int i = 0; i < 4; ++i)
#pragma unroll
        for (int j = 0; j < 4; ++j)
#pragma unroll
            for (int r = 0; r < 4; ++r) c[i][j][r] = 0.f;

    load_chunk(0, 0);
    load_chunk(1, BK);

    // single-barrier pipeline (stage ch+2 written only after top sync of ch)
    for (int ch = 0; ch < NCHUNK; ++ch) {
        int st = ch % NSTAGE;
        if (ch < NCHUNK - 1) { CPA_WAIT(1); }
        else                 { CPA_WAIT(0); }
        __syncthreads();
        if (ch + 2 < NCHUNK) load_chunk((ch + 2) % NSTAGE, (ch + 2) * BK);

        uint32_t sb = sbase + st * STAGE_BYTES;
        uint32_t aHiB = sb + OFF_AHI, aLoB = sb + OFF_ALO;
        uint32_t bHiB = sb + OFF_BHI, bLoB = sb + OFF_BLO;

#pragma unroll
        for (int ks = 0; ks < 4; ++ks) {
            uint32_t bh[4][2], bl[4][2];
#pragma unroll
            for (int ni = 0; ni < 4; ++ni) {
                uint32_t rowb = wn * 32 + ni * 8 + (lane & 7);
                uint32_t cb   = ks * 32 + (((lane >> 3) & 1) << 4);
                uint32_t off  = SWZ(rowb * 128 + cb);
                ldmB(bh[ni], bHiB + off);
                ldmB(bl[ni], bLoB + off);
            }
#pragma unroll
            for (int mi = 0; mi < 4; ++mi) {
                uint32_t rowa = wm * 64 + mi * 16 + (lane & 15);
                uint32_t ca   = ks * 32 + ((lane >> 4) << 4);
                uint32_t off  = SWZ(rowa * 128 + ca);
                uint32_t ah[4], al[4];
                ldmA(ah, aHiB + off);
                ldmA(al, aLoB + off);
#pragma unroll
                for (int ni = 0; ni < 4; ++ni) {
                    mma16816(c[mi][ni], ah, bh[ni]);
                    mma16816(c[mi][ni], ah, bl[ni]);
                    mma16816(c[mi][ni], al, bh[ni]);
                }
            }
        }
    }

    const int r  = lane >> 2;
    const int q2 = (lane & 3) << 1;
    if (!isY) {
        // u: [B, D, L]
#pragma unroll
        for (int mi = 0; mi < 4; ++mi) {
            int m = m0 + wm * 64 + mi * 16 + r;
#pragma unroll
            for (int ni = 0; ni < 4; ++ni) {
                int n = n0 + wn * 32 + ni * 8 + q2;
                float* p = uout + ((size_t)(b * DMODEL + m) << 12) + n;
                *(float2*)p = make_float2(c[mi][ni][0], c[mi][ni][1]);
                float* p2 = p + (8 << 12);
                *(float2*)p2 = make_float2(c[mi][ni][2], c[mi][ni][3]);
            }
        }
    } else {
        // y: [B, L, D] via smem transpose (bov added later in gather)
        float* tileT = (float*)dsm;   // 128 n-rows x 132 floats
        __syncthreads();
#pragma unroll
        for (int mi = 0; mi < 4; ++mi) {
            int ml = wm * 64 + mi * 16 + r;
#pragma unroll
            for (int ni = 0; ni < 4; ++ni) {
                int nl = wn * 32 + ni * 8 + q2;
                tileT[nl * 132 + ml]           = c[mi][ni][0];
                tileT[(nl + 1) * 132 + ml]     = c[mi][ni][1];
                tileT[nl * 132 + ml + 8]       = c[mi][ni][2];
                tileT[(nl + 1) * 132 + ml + 8] = c[mi][ni][3];
            }
        }
        __syncthreads();
#pragma unroll
        for (int it = 0; it < 16; ++it) {
            int idx = tid + it * 256;
            int nl = idx >> 5;
            int c4 = (idx & 31) << 2;
            float4 v = *(float4*)&tileT[nl * 132 + c4];
            *(float4*)(yout + (((size_t)b * LSEQ + n0 + nl) << 9) + m0 + c4) = v;
        }
    }
}

// ====================== convert x: bf16 hi/lo + fp32 transpose ======================
__global__ __launch_bounds__(256)
void convert_x_kernel(const float* __restrict__ hs)
{
    __shared__ float tile[32][33];
    const int tx = threadIdx.x;
    const int ty = threadIdx.y;
    const int b  = blockIdx.z;
    const int d0 = blockIdx.y * 32;
    const int l0 = blockIdx.x * 32;

#pragma unroll
    for (int i = 0; i < 4; ++i) {
        int l = l0 + ty + i * 8;
        size_t gi = (((size_t)b * LSEQ + l) << 9) + d0 + tx;
        float v = hs[gi];
        tile[ty + i * 8][tx] = v;
        __nv_bfloat16 h  = __float2bfloat16(v);
        __nv_bfloat16 lo = __float2bfloat16(v - __bfloat162float(h));
        g_xhi[gi] = h;
        g_xlo[gi] = lo;
    }
    __syncthreads();

#pragma unroll
    for (int i = 0; i < 4; ++i) {
        int d = d0 + ty + i * 8;
        g_xt[(((size_t)b * DMODEL + d) << 12) + l0 + tx] = tile[tx][ty + i * 8];
    }
}

// ====================== weight prep: H = Wk^T Wq (z=0) / Wov = Wo Wv + bov (z=1) ======================
__global__ __launch_bounds__(256)
void wprep_kernel(const float* __restrict__ Wk, const float* __restrict__ Wq,
                  const float* __restrict__ Wo, const float* __restrict__ Wv,
                  const float* __restrict__ bv, const float* __restrict__ bo)
{
    const int z = blockIdx.z;
    if (blockIdx.x == 8) {
        if (z == 1) {
            int w = threadIdx.x >> 5, lane = threadIdx.x & 31;
#pragma unroll
            for (int rr = 0; rr < 8; ++rr) {
                int m = blockIdx.y * 64 + w * 8 + rr;
                const float* row = Wo + (size_t)m * DMODEL;
                float s = 0.f;
                for (int c = lane; c < DMODEL; c += 32) s += row[c] * bv[c];
#pragma unroll
                for (int o = 16; o; o >>= 1) s += __shfl_xor_sync(0xffffffffu, s, o);
                if (lane == 0) g_bov[m] = s + bo[m];
            }
        }
        return;
    }

    __shared__ float As[32][68];
    __shared__ float Bs[32][68];
    const int tid = threadIdx.x;
    const int tx = tid & 15, ty = tid >> 4;
    const int m0 = blockIdx.y * 64, n0 = blockIdx.x * 64;

    float c[4][4];
#pragma unroll
    for (int i = 0; i < 4; ++i)
#pragma unroll
        for (int j = 0; j < 4; ++j) c[i][j] = 0.f;

    for (int cc = 0; cc < DMODEL; cc += 32) {
        if (z == 0) {
            // H = Wk^T Wq : As[d][m] = Wk[cc+d][m0+..], Bs[d][n] = Wq[cc+d][n0+..]
#pragma unroll
            for (int it = 0; it < 2; ++it) {
                int idx = tid + it * 256;
                int d2 = idx >> 4; int q4 = (idx & 15) << 2;
                *(float4*)&As[d2][q4] = *(const float4*)&Wk[(size_t)(cc + d2) * DMODEL + m0 + q4];
                *(float4*)&Bs[d2][q4] = *(const float4*)&Wq[(size_t)(cc + d2) * DMODEL + n0 + q4];
            }
        } else {
            // Wov = Wo Wv : As[c][m] = Wo[m0+m][cc+c] (transposed load), Bs[c][n] = Wv[cc+c][n0+..]
#pragma unroll
            for (int it = 0; it < 2; ++it) {
                int idx = tid + it * 256;
                int m = idx >> 3; int cq = (idx & 7) << 2;
                float4 v = *(const float4*)&Wo[(size_t)(m0 + m) * DMODEL + cc + cq];
                As[cq + 0][m] = v.x; As[cq + 1][m] = v.y;
                As[cq + 2][m] = v.z; As[cq + 3][m] = v.w;
            }
#pragma unroll
            for (int it = 0; it < 2; ++it) {
                int idx = tid + it * 256;
                int c2 = idx >> 4; int nq = (idx & 15) << 2;
                *(float4*)&Bs[c2][nq] = *(const float4*)&Wv[(size_t)(cc + c2) * DMODEL + n0 + nq];
            }
        }
        __syncthreads();
#pragma unroll
        for (int k = 0; k < 32; ++k) {
            float a[4], bb[4];
#pragma unroll
            for (int i = 0; i < 4; ++i) a[i] = As[k][ty * 4 + i];
#pragma unroll
            for (int j = 0; j < 4; ++j) bb[j] = Bs[k][tx * 4 + j];
#pragma unroll
            for (int i = 0; i < 4; ++i)
#pragma unroll
                for (int j = 0; j < 4; ++j) c[i][j] += a[i] * bb[j];
        }
        __syncthreads();
    }

    size_t slot = (z == 0) ? 0 : 2 * (size_t)WSZ;
#pragma unroll
    for (int i = 0; i < 4; ++i) {
        int m = m0 + ty * 4 + i;
#pragma unroll
        for (int j = 0; j < 4; ++j) {
            int n = n0 + tx * 4 + j;
            float v = c[i][j];
            __nv_bfloat16 h  = __float2bfloat16(v);
            __nv_bfloat16 lo = __float2bfloat16(v - __bfloat162float(h));
            g_whi[slot + (size_t)m * DMODEL + n] = h;
            g_wlo[slot + (size_t)m * DMODEL + n] = lo;
        }
    }
}

// ====================== radix-16 FFT machinery ======================
#define FPAD(i) ((i) + ((i) >> 4) + ((i) >> 8))
#define FFT_BUF 4368

__device__ __forceinline__ float2 cmul(float2 a, float2 b) {
    return make_float2(a.x * b.x - a.y * b.y, a.x * b.y + a.y * b.x);
}
__device__ __forceinline__ int rev16_12(int i) {
    return ((i & 15) << 8) | (i & 0xF0) | ((i >> 8) & 15);
}

template<bool INV>
__device__ __forceinline__ void dft4(float2 a, float2 b, float2 c, float2 d,
                                     float2& o0, float2& o1, float2& o2, float2& o3)
{
    float2 e0 = make_float2(a.x + c.x, a.y + c.y);
    float2 e1 = make_float2(a.x - c.x, a.y - c.y);
    float2 e2 = make_float2(b.x + d.x, b.y + d.y);
    float2 e3 = make_float2(b.x - d.x, b.y - d.y);
    o0 = make_float2(e0.x + e2.x, e0.y + e2.y);
    o2 = make_float2(e0.x - e2.x, e0.y - e2.y);
    if (!INV) {
        o1 = make_float2(e1.x + e3.y, e1.y - e3.x);
        o3 = make_float2(e1.x - e3.y, e1.y + e3.x);
    } else {
        o1 = make_float2(e1.x - e3.y, e1.y + e3.x);
        o3 = make_float2(e1.x + e3.y, e1.y - e3.x);
    }
}

template<bool INV>
__device__ __forceinline__ void dft16(float2* x)
{
    const float c1 = 0.92387953251128674f;
    const float s1 = 0.38268343236508978f;
    const float r2 = 0.70710678118654752f;
    const float si = INV ? 1.f : -1.f;
    auto tm = [](float2 v, float wr, float wi) {
        return make_float2(v.x * wr - v.y * wi, v.x * wi + v.y * wr);
    };
    float2 A[16];
#pragma unroll
    for (int t0 = 0; t0 < 4; ++t0)
        dft4<INV>(x[t0], x[t0 + 4], x[t0 + 8], x[t0 + 12],
                  A[0 + t0], A[4 + t0], A[8 + t0], A[12 + t0]);
    A[4 + 1]  = tm(A[4 + 1],  c1,  si * s1);
    A[4 + 2]  = tm(A[4 + 2],  r2,  si * r2);
    A[4 + 3]  = tm(A[4 + 3],  s1,  si * c1);
    A[8 + 1]  = tm(A[8 + 1],  r2,  si * r2);
    A[8 + 2]  = tm(A[8 + 2],  0.f, si);
    A[8 + 3]  = tm(A[8 + 3], -r2,  si * r2);
    A[12 + 1] = tm(A[12 + 1], s1,  si * c1);
    A[12 + 2] = tm(A[12 + 2], -r2, si * r2);
    A[12 + 3] = tm(A[12 + 3], -c1, -si * s1);
#pragma unroll
    for (int u0 = 0; u0 < 4; ++u0)
        dft4<INV>(A[u0 * 4], A[u0 * 4 + 1], A[u0 * 4 + 2], A[u0 * 4 + 3],
                  x[u0], x[u0 + 4], x[u0 + 8], x[u0 + 12]);
}

template<bool INV>
__device__ __forceinline__ void fft4096_r16(float2* buf, const float2* tw, int tid)
{
#pragma unroll
    for (int s = 0; s < 3; ++s) {
        const int Q = 1 << (4 * s);
        int q  = tid & (Q - 1);
        int i0 = ((tid >> (4 * s)) << (4 * s + 4)) + q;
        float2 w1 = tw[q << (8 - 4 * s)];
        float2 x[16];
        x[0] = buf[FPAD(i0)];
        float2 wt = w1;
#pragma unroll
        for (int t = 1; t < 16; ++t) {
            x[t] = cmul(buf[FPAD(i0 + t * Q)], wt);
            wt = cmul(wt, w1);
        }
        dft16<INV>(x);
#pragma unroll
        for (int u = 0; u < 16; ++u) buf[FPAD(i0 + u * Q)] = x[u];
        __syncthreads();
    }
}

// Forward FFT of z = u + i*x per channel, accumulate Uf*conj(Xf) over 8 channels.
__global__ void fftcorr_kernel()
{
    __shared__ float2 buf[FFT_BUF];
    __shared__ float2 tw[256];

    const int tid = threadIdx.x;
    const int g = blockIdx.x, b = blockIdx.y;

    if (tid < 256) {
        float s, c;
        sincosf(6.283185307179586f * (float)tid / 4096.0f, &s, &c);
        tw[tid] = make_float2(c, -s);
    }

    float2 acc[16];
#pragma unroll
    for (int j = 0; j < 16; ++j) acc[j] = make_float2(0.f, 0.f);

    for (int cc = 0; cc < 8; ++cc) {
        int ch = g * 8 + cc;
        const float* up = g_u  + (((size_t)b * DMODEL + ch) << 12);
        const float* xp = g_xt + (((size_t)b * DMODEL + ch) << 12);

        __syncthreads();
#pragma unroll
        for (int j = 0; j < 16; ++j) {
            int n = tid + 256 * j;
            buf[FPAD(rev16_12(n))] = make_float2(up[n], xp[n]);
        }
        __syncthreads();

        fft4096_r16<false>(buf, tw, tid);

#pragma unroll
        for (int j = 0; j < 16; ++j) {
            int f = tid + 256 * j;
            float2 Zf = buf[FPAD(f)];
            float2 Zm = buf[FPAD((4096 - f) & 4095)];
            float2 U  = make_float2(0.5f * (Zf.x + Zm.x), 0.5f * (Zf.y - Zm.y));
            float dx = Zf.x - Zm.x, dy = Zf.y + Zm.y;
            float2 Xc = make_float2(0.5f * dy, -0.5f * dx);
            acc[j].x += U.x * Xc.x + U.y * Xc.y;
            acc[j].y += U.y * Xc.x - U.x * Xc.y;
        }
    }
#pragma unroll
    for (int j = 0; j < 16; ++j)
        g_spart[(((size_t)b * NGRP + g) << 12) + tid + 256 * j] = acc[j];
}

__global__ void reduce_kernel()
{
    const int f = blockIdx.x * 256 + threadIdx.x;
    const int b = blockIdx.y;
    const float2* sp = g_spart + (((size_t)b * NGRP) << 12) + f;
    float2 s = make_float2(0.f, 0.f);
#pragma unroll 8
    for (int gp = 0; gp < NGRP; ++gp) {
        float2 v = sp[(size_t)gp << 12];
        s.x += v.x; s.y += v.y;
    }
    g_sred[((size_t)b << 12) + f] = s;
}

// Inverse FFT of reduced spectrum + fused top-k + softmax.
__global__ void ifft_topk_kernel()
{
    __shared__ float2 buf[FFT_BUF];
    __shared__ float2 tw[256];
    __shared__ float rv[256];
    __shared__ int   ri[256];
    __shared__ float wv[TOPK];
    __shared__ int   wi[TOPK];

    const int tid = threadIdx.x;
    const int b = blockIdx.x;

    {
        float s, c;
        sincosf(6.283185307179586f * (float)tid / 4096.0f, &s, &c);
        tw[tid] = make_float2(c, s);
    }
    __syncthreads();

#pragma unroll
    for (int j = 0; j < 16; ++j) {
        int f = tid + 256 * j;
        buf[FPAD(rev16_12(f))] = g_sred[((size_t)b << 12) + f];
    }
    __syncthreads();

    fft4096_r16<true>(buf, tw, tid);

    for (int r = 0; r < TOPK; ++r) {
        float best = -FLT_MAX;
        int bi = 0x7fffffff;
#pragma unroll
        for (int j = 0; j < 16; ++j) {
            int i = tid + 256 * j;
            float v = buf[FPAD(i)].x;
            if (v > best) { best = v; bi = i; }
        }
        rv[tid] = best; ri[tid] = bi;
        __syncthreads();
        for (int s = 128; s > 0; s >>= 1) {
            if (tid < s) {
                if (rv[tid + s] > rv[tid] ||
                    (rv[tid + s] == rv[tid] && ri[tid + s] < ri[tid])) {
                    rv[tid] = rv[tid + s]; ri[tid] = ri[tid + s];
                }
            }
            __syncthreads();
        }
        if (tid == 0) { wv[r] = rv[0]; wi[r] = ri[0]; buf[FPAD(ri[0])].x = -FLT_MAX; }
        __syncthreads();
    }

    if (tid == 0) {
        const float scale = 1.0f / (4096.0f * 512.0f);
        float mx = wv[0] * scale;
        float e[TOPK], sum = 0.f;
#pragma unroll
        for (int i = 0; i < TOPK; ++i) { e[i] = expf(wv[i] * scale - mx); sum += e[i]; }
        float inv = 1.0f / sum;
#pragma unroll
        for (int i = 0; i < TOPK; ++i) {
            g_weights[b * TOPK + i] = e[i] * inv;
            g_delays [b * TOPK + i] = wi[i];
        }
    }
}

// ====================== final gather on y: out = sum_i w_i y(l+d_i) + bov ======================
__global__ __launch_bounds__(128)
void gathery_kernel(float* __restrict__ out)
{
    __shared__ float ws[TOPK];
    __shared__ int   ds[TOPK];
    const int tid = threadIdx.x;
    const int l = blockIdx.x, b = blockIdx.y;

    if (tid < TOPK) {
        ws[tid] = g_weights[b * TOPK + tid];
        ds[tid] = g_delays [b * TOPK + tid];
    }
    __syncthreads();

    const float4* yb = (const float4*)(g_y + (((size_t)b * LSEQ) << 9));
    float4 acc = ((const float4*)g_bov)[tid];
#pragma unroll
    for (int i = 0; i < TOPK; ++i) {
        int t = (l + ds[i]) & (LSEQ - 1);
        float4 v = yb[t * 128 + tid];
        float w = ws[i];
        acc.x += w * v.x; acc.y += w * v.y; acc.z += w * v.z; acc.w += w * v.w;
    }
    ((float4*)(out + (((size_t)b * LSEQ + l) << 9)))[tid] = acc;
}

// =====================================================================
extern "C" void kernel_launch(void* const* d_in, const int* in_sizes, int n_in,
                              void* d_out, int out_size)
{
    const float* hs = (const float*)d_in[0];
    const float* Wq = (const float*)d_in[1];
    const float* Wk = (const float*)d_in[3];
    const float* Wv = (const float*)d_in[5];
    const float* bv = (const float*)d_in[6];
    const float* Wo = (const float*)d_in[7];
    const float* bo = (const float*)d_in[8];
    float* out = (float*)d_out;

    void *pu, *py, *pxhi, *pxlo, *pwhi, *pwlo;
    cudaGetSymbolAddress(&pu,   g_u);
    cudaGetSymbolAddress(&py,   g_y);
    cudaGetSymbolAddress(&pxhi, g_xhi);
    cudaGetSymbolAddress(&pxlo, g_xlo);
    cudaGetSymbolAddress(&pwhi, g_whi);
    cudaGetSymbolAddress(&pwlo, g_wlo);

    cudaFuncSetAttribute(gemm_uy_kernel,
                         cudaFuncAttributeMaxDynamicSharedMemorySize, GEMM_DSMEM);

    // 1. x prep + weight folding (H, Wov, bov)
    convert_x_kernel<<<dim3(LSEQ / 32, DMODEL / 32, BATCH), dim3(32, 8)>>>(hs);
    wprep_kernel<<<dim3(9, 8, 2), 256>>>(Wk, Wq, Wo, Wv, bv, bo);

    // 2. fused GEMM: u = H x (-> [B,D,L])  and  y = Wov x (-> [B,L,D])
    dim3 gg(LSEQ / BN, 8, BATCH);
    gemm_uy_kernel<<<gg, 256, GEMM_DSMEM>>>(
        (const __nv_bfloat16*)pwhi, (const __nv_bfloat16*)pwlo,
        (const __nv_bfloat16*)pxhi, (const __nv_bfloat16*)pxlo,
        (float*)pu, (float*)py);

    // 3. cross-correlation spectrum of (u, x) + reduce + fused iFFT/top-k
    fftcorr_kernel<<<dim3(NGRP, BATCH), 256>>>();
    reduce_kernel<<<dim3(LSEQ / 256, BATCH), 256>>>();
    ifft_topk_kernel<<<BATCH, 256>>>();

    // 4. final gather on y -> out (+bov)
    gathery_kernel<<<dim3(LSEQ, BATCH), 128>>>(out);
}